// round 3
// baseline (speedup 1.0000x reference)
#include <cuda_runtime.h>

#define BB   2
#define TT   2048
#define CC   2048
#define HQ   32
#define HKV  8
#define HD   64
#define MM   (BB*TT)        // 4096
#define KVD  (HKV*HD)       // 512

// Scratch (no allocations allowed anywhere)
__device__ float g_Q[MM*CC];   // 32 MB, columns = h*64 + d
__device__ float g_K[MM*KVD];  // 8 MB
__device__ float g_V[MM*KVD];  // 8 MB
__device__ float g_O[MM*CC];   // 32 MB, attention output (head-major columns)

// ---------------------------------------------------------------------------
// SGEMM: C[M,N] = A[M,K] @ W[K,N] + bias[N]
// 128x128 tile, BK=8, 256 threads, 8x8 per-thread microtile (split fragments)
// ---------------------------------------------------------------------------
__global__ __launch_bounds__(256) void sgemm_bias(
    const float* __restrict__ A, const float* __restrict__ W,
    const float* __restrict__ bias, float* __restrict__ Co,
    int Nd, int Kd)
{
    __shared__ float As[8][128];   // [k][m] (transposed)
    __shared__ float Bs[8][128];   // [k][n]

    const int tid  = threadIdx.x;
    const int row0 = blockIdx.y * 128;
    const int col0 = blockIdx.x * 128;

    const int aRow = tid >> 1;            // 0..127
    const int aC4  = (tid & 1) * 4;       // 0 or 4
    const int bRow = tid >> 5;            // 0..7
    const int bC4  = (tid & 31) * 4;      // 0..124

    const int ty = tid >> 4;              // 0..15
    const int tx = tid & 15;              // 0..15

    float acc[8][8];
#pragma unroll
    for (int i = 0; i < 8; i++)
#pragma unroll
        for (int j = 0; j < 8; j++) acc[i][j] = 0.f;

    for (int k0 = 0; k0 < Kd; k0 += 8) {
        float4 a4 = *(const float4*)(A + (size_t)(row0 + aRow) * Kd + k0 + aC4);
        As[aC4 + 0][aRow] = a4.x;
        As[aC4 + 1][aRow] = a4.y;
        As[aC4 + 2][aRow] = a4.z;
        As[aC4 + 3][aRow] = a4.w;
        float4 b4 = *(const float4*)(W + (size_t)(k0 + bRow) * Nd + col0 + bC4);
        *(float4*)(&Bs[bRow][bC4]) = b4;
        __syncthreads();

#pragma unroll
        for (int k = 0; k < 8; k++) {
            float a[8], b[8];
            *(float4*)(a)     = *(const float4*)(&As[k][ty * 4]);
            *(float4*)(a + 4) = *(const float4*)(&As[k][64 + ty * 4]);
            *(float4*)(b)     = *(const float4*)(&Bs[k][tx * 4]);
            *(float4*)(b + 4) = *(const float4*)(&Bs[k][64 + tx * 4]);
#pragma unroll
            for (int i = 0; i < 8; i++)
#pragma unroll
                for (int j = 0; j < 8; j++)
                    acc[i][j] = fmaf(a[i], b[j], acc[i][j]);
        }
        __syncthreads();
    }

#pragma unroll
    for (int i = 0; i < 8; i++) {
        const int r = row0 + ((i >= 4) ? 64 : 0) + ty * 4 + (i & 3);
#pragma unroll
        for (int jh = 0; jh < 2; jh++) {
            const int c = col0 + jh * 64 + tx * 4;
            float4 o;
            o.x = acc[i][jh * 4 + 0] + bias[c + 0];
            o.y = acc[i][jh * 4 + 1] + bias[c + 1];
            o.z = acc[i][jh * 4 + 2] + bias[c + 2];
            o.w = acc[i][jh * 4 + 3] + bias[c + 3];
            *(float4*)(Co + (size_t)r * Nd + c) = o;
        }
    }
}

// ---------------------------------------------------------------------------
// Flash attention (fp32, causal, GQA). One CTA = (b, h, 64-query tile).
// 256 threads; S and PV as 16x16 thread grid of 4x4 microtiles.
// ---------------------------------------------------------------------------
__global__ __launch_bounds__(256) void attn_kernel(
    const float* __restrict__ Qg, const float* __restrict__ Kg,
    const float* __restrict__ Vg, float* __restrict__ Og)
{
    extern __shared__ float sm[];
    float* Qs   = sm;            // [64][64]  (d, r)
    float* KP   = sm + 4096;     // phase 1: K as (d, c); phase 2: P^T as (c, r)
    float* Vs   = sm + 8192;     // [64][64]  (kv, d)
    float* mrow = sm + 12288;    // [64]
    float* lrow = sm + 12352;    // [64]
    float* arow = sm + 12416;    // [64]

    const int tid = threadIdx.x;
    const int q0  = blockIdx.x * 64;
    const int h   = blockIdx.y;
    const int b   = blockIdx.z;
    const int hkv = h >> 2;                 // N_REP = 4
    const int ty  = tid >> 4, tx = tid & 15;

    // Load Q tile transposed: Qs[d][r]
    {
        const int r  = tid >> 2;
        const int c0 = (tid & 3) * 16;
        const float* qp = Qg + (size_t)(b * TT + q0 + r) * CC + h * HD + c0;
#pragma unroll
        for (int i = 0; i < 4; i++) {
            float4 v = *(const float4*)(qp + i * 4);
            const int d = c0 + i * 4;
            Qs[(d + 0) * 64 + r] = v.x;
            Qs[(d + 1) * 64 + r] = v.y;
            Qs[(d + 2) * 64 + r] = v.z;
            Qs[(d + 3) * 64 + r] = v.w;
        }
    }
    if (tid < 64) { mrow[tid] = -1e30f; lrow[tid] = 0.f; }

    float acc[4][4];
#pragma unroll
    for (int i = 0; i < 4; i++)
#pragma unroll
        for (int j = 0; j < 4; j++) acc[i][j] = 0.f;

    const int ntile = (q0 >> 6) + 1;
    for (int jt = 0; jt < ntile; jt++) {
        const int k0 = jt * 64;
        __syncthreads();   // previous PV reads of KP/Vs done
        {
            const int r  = tid >> 2;
            const int c0 = (tid & 3) * 16;
            const float* kp = Kg + (size_t)(b * TT + k0 + r) * KVD + hkv * HD + c0;
            const float* vp = Vg + (size_t)(b * TT + k0 + r) * KVD + hkv * HD + c0;
#pragma unroll
            for (int i = 0; i < 4; i++) {
                const int d = c0 + i * 4;
                float4 kk = *(const float4*)(kp + i * 4);
                KP[(d + 0) * 64 + r] = kk.x;
                KP[(d + 1) * 64 + r] = kk.y;
                KP[(d + 2) * 64 + r] = kk.z;
                KP[(d + 3) * 64 + r] = kk.w;
                float4 vv = *(const float4*)(vp + i * 4);
                *(float4*)(Vs + r * 64 + d) = vv;
            }
        }
        __syncthreads();

        // S = Q @ K^T : thread owns rows ty*4.., cols tx*4..
        float s[4][4];
#pragma unroll
        for (int i = 0; i < 4; i++)
#pragma unroll
            for (int j = 0; j < 4; j++) s[i][j] = 0.f;
#pragma unroll 8
        for (int d = 0; d < 64; d++) {
            float4 aq = *(const float4*)(Qs + d * 64 + ty * 4);
            float4 bk = *(const float4*)(KP + d * 64 + tx * 4);
            const float av[4] = {aq.x, aq.y, aq.z, aq.w};
            const float bv[4] = {bk.x, bk.y, bk.z, bk.w};
#pragma unroll
            for (int i = 0; i < 4; i++)
#pragma unroll
                for (int j = 0; j < 4; j++)
                    s[i][j] = fmaf(av[i], bv[j], s[i][j]);
        }
        __syncthreads();   // everyone done reading KP as K

        // Write S^T (scaled, causal-masked) into KP as (c, r)
        const bool diag = (k0 == q0);
#pragma unroll
        for (int i = 0; i < 4; i++)
#pragma unroll
            for (int j = 0; j < 4; j++) {
                const int r = ty * 4 + i, c = tx * 4 + j;
                float v = s[i][j] * 0.125f;   // 1/sqrt(64)
                if (diag && c > r) v = -1e30f;
                KP[c * 64 + r] = v;
            }
        __syncthreads();

        // Online softmax: thread r (< 64) owns row r
        if (tid < 64) {
            const int r = tid;
            const float m_old = mrow[r];
            float mx = m_old;
#pragma unroll 8
            for (int c = 0; c < 64; c++) mx = fmaxf(mx, KP[c * 64 + r]);
            const float al = __expf(m_old - mx);
            float ls = 0.f;
#pragma unroll 8
            for (int c = 0; c < 64; c++) {
                const float p = __expf(KP[c * 64 + r] - mx);
                KP[c * 64 + r] = p;
                ls += p;
            }
            mrow[r] = mx;
            lrow[r] = lrow[r] * al + ls;
            arow[r] = al;
        }
        __syncthreads();

        // Rescale accumulators, then O += P @ V
        const float al0 = arow[ty * 4 + 0];
        const float al1 = arow[ty * 4 + 1];
        const float al2 = arow[ty * 4 + 2];
        const float al3 = arow[ty * 4 + 3];
#pragma unroll
        for (int j = 0; j < 4; j++) {
            acc[0][j] *= al0; acc[1][j] *= al1;
            acc[2][j] *= al2; acc[3][j] *= al3;
        }
#pragma unroll 8
        for (int kv = 0; kv < 64; kv++) {
            float4 pp = *(const float4*)(KP + kv * 64 + ty * 4);   // P^T (kv, r)
            float4 vv = *(const float4*)(Vs + kv * 64 + tx * 4);   // V  (kv, d)
            const float pa[4] = {pp.x, pp.y, pp.z, pp.w};
            const float va[4] = {vv.x, vv.y, vv.z, vv.w};
#pragma unroll
            for (int i = 0; i < 4; i++)
#pragma unroll
                for (int j = 0; j < 4; j++)
                    acc[i][j] = fmaf(pa[i], va[j], acc[i][j]);
        }
    }

    // Epilogue: O / l  -> g_O (head-major columns)
#pragma unroll
    for (int i = 0; i < 4; i++) {
        const int r = ty * 4 + i;
        const float inv = 1.f / lrow[r];
        float4 o;
        o.x = acc[i][0] * inv;
        o.y = acc[i][1] * inv;
        o.z = acc[i][2] * inv;
        o.w = acc[i][3] * inv;
        *(float4*)(Og + (size_t)(b * TT + q0 + r) * CC + h * HD + tx * 4) = o;
    }
}

// ---------------------------------------------------------------------------
extern "C" void kernel_launch(void* const* d_in, const int* in_sizes, int n_in,
                              void* d_out, int out_size)
{
    const float* x  = (const float*)d_in[0];
    // d_in[1] = mask (causal tril) — structural, not read
    const float* Wq = (const float*)d_in[2];
    const float* bq = (const float*)d_in[3];
    const float* Wk = (const float*)d_in[4];
    const float* bk = (const float*)d_in[5];
    const float* Wv = (const float*)d_in[6];
    const float* bv = (const float*)d_in[7];
    const float* Wo = (const float*)d_in[8];
    const float* bo = (const float*)d_in[9];
    float* out = (float*)d_out;

    float *Qp, *Kp, *Vp, *Op;
    cudaGetSymbolAddress((void**)&Qp, g_Q);
    cudaGetSymbolAddress((void**)&Kp, g_K);
    cudaGetSymbolAddress((void**)&Vp, g_V);
    cudaGetSymbolAddress((void**)&Op, g_O);

    const int smem_attn = 12480 * sizeof(float);   // 49,920 B
    cudaFuncSetAttribute(attn_kernel,
                         cudaFuncAttributeMaxDynamicSharedMemorySize, smem_attn);

    dim3 blk(256);
    sgemm_bias<<<dim3(CC / 128, MM / 128), blk>>>(x,  Wq, bq, Qp, CC,  CC);
    sgemm_bias<<<dim3(KVD / 128, MM / 128), blk>>>(x, Wk, bk, Kp, KVD, CC);
    sgemm_bias<<<dim3(KVD / 128, MM / 128), blk>>>(x, Wv, bv, Vp, KVD, CC);
    attn_kernel<<<dim3(TT / 64, HQ, BB), blk, smem_attn>>>(Qp, Kp, Vp, Op);
    sgemm_bias<<<dim3(CC / 128, MM / 128), blk>>>(Op, Wo, bo, out, CC, CC);
}

// round 4
// speedup vs baseline: 1.5187x; 1.5187x over previous
#include <cuda_runtime.h>
#include <stdint.h>

#define BB   2
#define TT   2048
#define CC   2048
#define HQ   32
#define HKV  8
#define HD   64
#define MM   (BB*TT)        // 4096
#define KVD  (HKV*HD)       // 512

// Scratch (no allocations allowed anywhere)
__device__ float g_Q[MM*CC];   // 32 MB
__device__ float g_K[MM*KVD];  // 8 MB
__device__ float g_V[MM*KVD];  // 8 MB
__device__ float g_O[MM*CC];   // 32 MB

// ---------------------------------------------------------------------------
// tf32 helpers
// ---------------------------------------------------------------------------
__device__ __forceinline__ float to_tf32(float x) {
    float r;
    asm("cvt.rna.tf32.f32 %0, %1;" : "=f"(r) : "f"(x));
    return r;
}

__device__ __forceinline__ void mma_tf32(float* d, const float* a, const float* b) {
    asm volatile(
        "mma.sync.aligned.m16n8k8.row.col.f32.tf32.tf32.f32 "
        "{%0,%1,%2,%3}, {%4,%5,%6,%7}, {%8,%9}, {%0,%1,%2,%3};"
        : "+f"(d[0]), "+f"(d[1]), "+f"(d[2]), "+f"(d[3])
        : "r"(__float_as_uint(a[0])), "r"(__float_as_uint(a[1])),
          "r"(__float_as_uint(a[2])), "r"(__float_as_uint(a[3])),
          "r"(__float_as_uint(b[0])), "r"(__float_as_uint(b[1])));
}

// ---------------------------------------------------------------------------
// GEMM (tf32 tensor cores): C[M,N] = A[M,K] @ W[K,N] + bias[N]
// 128x128x16 block tile, 256 threads (8 warps, 2x4), warp tile 64x32.
// Smem stride 136 floats -> conflict-free fragment loads.
// ---------------------------------------------------------------------------
#define SST 136
__global__ __launch_bounds__(256) void gemm_tf32(
    const float* __restrict__ A, const float* __restrict__ W,
    const float* __restrict__ bias, float* __restrict__ Co,
    int Nd, int Kd)
{
    __shared__ float As[16][SST];   // [k][m]
    __shared__ float Bs[16][SST];   // [k][n]

    const int tid  = threadIdx.x;
    const int lane = tid & 31;
    const int warp = tid >> 5;
    const int row0 = blockIdx.y * 128;
    const int col0 = blockIdx.x * 128;
    const int wm   = (warp & 1) * 64;   // warp m-offset in tile
    const int wn   = (warp >> 1) * 32;  // warp n-offset in tile

    // global->smem mappings
    const int aRow = tid >> 2;          // 0..63
    const int aK   = (tid & 3) * 4;     // 0,4,8,12
    const int bK   = tid >> 5;          // 0..7
    const int bC   = (tid & 31) * 4;    // 0..124

    const int grp = lane >> 2;          // 0..7
    const int qid = lane & 3;           // 0..3

    float acc[4][4][4];
#pragma unroll
    for (int i = 0; i < 4; i++)
#pragma unroll
        for (int j = 0; j < 4; j++)
#pragma unroll
            for (int r = 0; r < 4; r++) acc[i][j][r] = 0.f;

    for (int k0 = 0; k0 < Kd; k0 += 16) {
        // A tile: 128 rows x 16 k, stored transposed As[k][m]
#pragma unroll
        for (int h = 0; h < 2; h++) {
            const int r = aRow + h * 64;
            float4 a4 = *(const float4*)(A + (size_t)(row0 + r) * Kd + k0 + aK);
            As[aK + 0][r] = to_tf32(a4.x);
            As[aK + 1][r] = to_tf32(a4.y);
            As[aK + 2][r] = to_tf32(a4.z);
            As[aK + 3][r] = to_tf32(a4.w);
        }
        // B tile: 16 k x 128 cols, stored Bs[k][n]
#pragma unroll
        for (int h = 0; h < 2; h++) {
            const int kk = bK + h * 8;
            float4 b4 = *(const float4*)(W + (size_t)(k0 + kk) * Nd + col0 + bC);
            float4 t;
            t.x = to_tf32(b4.x); t.y = to_tf32(b4.y);
            t.z = to_tf32(b4.z); t.w = to_tf32(b4.w);
            *(float4*)(&Bs[kk][bC]) = t;
        }
        __syncthreads();

#pragma unroll
        for (int kk = 0; kk < 16; kk += 8) {
            // A fragments: 4 m-tiles
            float a[4][4];
#pragma unroll
            for (int mt = 0; mt < 4; mt++) {
                const int r = wm + mt * 16 + grp;
                const int c = kk + qid;
                a[mt][0] = As[c][r];
                a[mt][1] = As[c][r + 8];
                a[mt][2] = As[c + 4][r];
                a[mt][3] = As[c + 4][r + 8];
            }
            // B fragments: 4 n-tiles
            float b[4][2];
#pragma unroll
            for (int nt = 0; nt < 4; nt++) {
                const int n = wn + nt * 8 + grp;
                const int c = kk + qid;
                b[nt][0] = Bs[c][n];
                b[nt][1] = Bs[c + 4][n];
            }
#pragma unroll
            for (int mt = 0; mt < 4; mt++)
#pragma unroll
                for (int nt = 0; nt < 4; nt++)
                    mma_tf32(acc[mt][nt], a[mt], b[nt]);
        }
        __syncthreads();
    }

    // Epilogue: acc -> global with bias (float2 stores)
#pragma unroll
    for (int mt = 0; mt < 4; mt++) {
#pragma unroll
        for (int nt = 0; nt < 4; nt++) {
            const int r  = row0 + wm + mt * 16 + grp;
            const int c  = col0 + wn + nt * 8 + qid * 2;
            float2 o0, o1;
            o0.x = acc[mt][nt][0] + bias[c];
            o0.y = acc[mt][nt][1] + bias[c + 1];
            o1.x = acc[mt][nt][2] + bias[c];
            o1.y = acc[mt][nt][3] + bias[c + 1];
            *(float2*)(Co + (size_t)r * Nd + c)       = o0;
            *(float2*)(Co + (size_t)(r + 8) * Nd + c) = o1;
        }
    }
}

// ---------------------------------------------------------------------------
// Flash attention (fp32, causal, GQA). One CTA = (b, h, 64-query tile).
// ---------------------------------------------------------------------------
__global__ __launch_bounds__(256) void attn_kernel(
    const float* __restrict__ Qg, const float* __restrict__ Kg,
    const float* __restrict__ Vg, float* __restrict__ Og)
{
    extern __shared__ float sm[];
    float* Qs   = sm;            // [64][64]  (d, r)
    float* KP   = sm + 4096;     // phase 1: K as (d, c); phase 2: P^T as (c, r)
    float* Vs   = sm + 8192;     // [64][64]  (kv, d)
    float* mrow = sm + 12288;    // [64]
    float* lrow = sm + 12352;    // [64]
    float* arow = sm + 12416;    // [64]

    const int tid = threadIdx.x;
    const int q0  = blockIdx.x * 64;
    const int h   = blockIdx.y;
    const int b   = blockIdx.z;
    const int hkv = h >> 2;                 // N_REP = 4
    const int ty  = tid >> 4, tx = tid & 15;

    {
        const int r  = tid >> 2;
        const int c0 = (tid & 3) * 16;
        const float* qp = Qg + (size_t)(b * TT + q0 + r) * CC + h * HD + c0;
#pragma unroll
        for (int i = 0; i < 4; i++) {
            float4 v = *(const float4*)(qp + i * 4);
            const int d = c0 + i * 4;
            Qs[(d + 0) * 64 + r] = v.x;
            Qs[(d + 1) * 64 + r] = v.y;
            Qs[(d + 2) * 64 + r] = v.z;
            Qs[(d + 3) * 64 + r] = v.w;
        }
    }
    if (tid < 64) { mrow[tid] = -1e30f; lrow[tid] = 0.f; }

    float acc[4][4];
#pragma unroll
    for (int i = 0; i < 4; i++)
#pragma unroll
        for (int j = 0; j < 4; j++) acc[i][j] = 0.f;

    const int ntile = (q0 >> 6) + 1;
    for (int jt = 0; jt < ntile; jt++) {
        const int k0 = jt * 64;
        __syncthreads();
        {
            const int r  = tid >> 2;
            const int c0 = (tid & 3) * 16;
            const float* kp = Kg + (size_t)(b * TT + k0 + r) * KVD + hkv * HD + c0;
            const float* vp = Vg + (size_t)(b * TT + k0 + r) * KVD + hkv * HD + c0;
#pragma unroll
            for (int i = 0; i < 4; i++) {
                const int d = c0 + i * 4;
                float4 kk = *(const float4*)(kp + i * 4);
                KP[(d + 0) * 64 + r] = kk.x;
                KP[(d + 1) * 64 + r] = kk.y;
                KP[(d + 2) * 64 + r] = kk.z;
                KP[(d + 3) * 64 + r] = kk.w;
                float4 vv = *(const float4*)(vp + i * 4);
                *(float4*)(Vs + r * 64 + d) = vv;
            }
        }
        __syncthreads();

        float s[4][4];
#pragma unroll
        for (int i = 0; i < 4; i++)
#pragma unroll
            for (int j = 0; j < 4; j++) s[i][j] = 0.f;
#pragma unroll 8
        for (int d = 0; d < 64; d++) {
            float4 aq = *(const float4*)(Qs + d * 64 + ty * 4);
            float4 bk = *(const float4*)(KP + d * 64 + tx * 4);
            const float av[4] = {aq.x, aq.y, aq.z, aq.w};
            const float bv[4] = {bk.x, bk.y, bk.z, bk.w};
#pragma unroll
            for (int i = 0; i < 4; i++)
#pragma unroll
                for (int j = 0; j < 4; j++)
                    s[i][j] = fmaf(av[i], bv[j], s[i][j]);
        }
        __syncthreads();

        const bool diag = (k0 == q0);
#pragma unroll
        for (int i = 0; i < 4; i++)
#pragma unroll
            for (int j = 0; j < 4; j++) {
                const int r = ty * 4 + i, c = tx * 4 + j;
                float v = s[i][j] * 0.125f;
                if (diag && c > r) v = -1e30f;
                KP[c * 64 + r] = v;
            }
        __syncthreads();

        if (tid < 64) {
            const int r = tid;
            const float m_old = mrow[r];
            float mx = m_old;
#pragma unroll 8
            for (int c = 0; c < 64; c++) mx = fmaxf(mx, KP[c * 64 + r]);
            const float al = __expf(m_old - mx);
            float ls = 0.f;
#pragma unroll 8
            for (int c = 0; c < 64; c++) {
                const float p = __expf(KP[c * 64 + r] - mx);
                KP[c * 64 + r] = p;
                ls += p;
            }
            mrow[r] = mx;
            lrow[r] = lrow[r] * al + ls;
            arow[r] = al;
        }
        __syncthreads();

        const float al0 = arow[ty * 4 + 0];
        const float al1 = arow[ty * 4 + 1];
        const float al2 = arow[ty * 4 + 2];
        const float al3 = arow[ty * 4 + 3];
#pragma unroll
        for (int j = 0; j < 4; j++) {
            acc[0][j] *= al0; acc[1][j] *= al1;
            acc[2][j] *= al2; acc[3][j] *= al3;
        }
#pragma unroll 8
        for (int kv = 0; kv < 64; kv++) {
            float4 pp = *(const float4*)(KP + kv * 64 + ty * 4);
            float4 vv = *(const float4*)(Vs + kv * 64 + tx * 4);
            const float pa[4] = {pp.x, pp.y, pp.z, pp.w};
            const float va[4] = {vv.x, vv.y, vv.z, vv.w};
#pragma unroll
            for (int i = 0; i < 4; i++)
#pragma unroll
                for (int j = 0; j < 4; j++)
                    acc[i][j] = fmaf(pa[i], va[j], acc[i][j]);
        }
    }

#pragma unroll
    for (int i = 0; i < 4; i++) {
        const int r = ty * 4 + i;
        const float inv = 1.f / lrow[r];
        float4 o;
        o.x = acc[i][0] * inv;
        o.y = acc[i][1] * inv;
        o.z = acc[i][2] * inv;
        o.w = acc[i][3] * inv;
        *(float4*)(Og + (size_t)(b * TT + q0 + r) * CC + h * HD + tx * 4) = o;
    }
}

// ---------------------------------------------------------------------------
extern "C" void kernel_launch(void* const* d_in, const int* in_sizes, int n_in,
                              void* d_out, int out_size)
{
    const float* x  = (const float*)d_in[0];
    // d_in[1] = mask (causal tril) — structural, not read
    const float* Wq = (const float*)d_in[2];
    const float* bq = (const float*)d_in[3];
    const float* Wk = (const float*)d_in[4];
    const float* bk = (const float*)d_in[5];
    const float* Wv = (const float*)d_in[6];
    const float* bv = (const float*)d_in[7];
    const float* Wo = (const float*)d_in[8];
    const float* bo = (const float*)d_in[9];
    float* out = (float*)d_out;

    float *Qp, *Kp, *Vp, *Op;
    cudaGetSymbolAddress((void**)&Qp, g_Q);
    cudaGetSymbolAddress((void**)&Kp, g_K);
    cudaGetSymbolAddress((void**)&Vp, g_V);
    cudaGetSymbolAddress((void**)&Op, g_O);

    const int smem_attn = 12480 * sizeof(float);   // 49,920 B
    cudaFuncSetAttribute(attn_kernel,
                         cudaFuncAttributeMaxDynamicSharedMemorySize, smem_attn);

    dim3 blk(256);
    gemm_tf32<<<dim3(CC / 128, MM / 128), blk>>>(x,  Wq, bq, Qp, CC,  CC);
    gemm_tf32<<<dim3(KVD / 128, MM / 128), blk>>>(x, Wk, bk, Kp, KVD, CC);
    gemm_tf32<<<dim3(KVD / 128, MM / 128), blk>>>(x, Wv, bv, Vp, KVD, CC);
    attn_kernel<<<dim3(TT / 64, HQ, BB), blk, smem_attn>>>(Qp, Kp, Vp, Op);
    gemm_tf32<<<dim3(CC / 128, MM / 128), blk>>>(Op, Wo, bo, out, CC, CC);
}

// round 6
// speedup vs baseline: 2.5098x; 1.6526x over previous
#include <cuda_runtime.h>
#include <stdint.h>

#define BB   2
#define TT   2048
#define CC   2048
#define HQ   32
#define HKV  8
#define HD   64
#define MM   (BB*TT)        // 4096
#define KVD  (HKV*HD)       // 512

// Scratch (no allocations allowed anywhere)
__device__ float g_Q[MM*CC];   // 32 MB
__device__ float g_K[MM*KVD];  // 8 MB
__device__ float g_V[MM*KVD];  // 8 MB
__device__ float g_O[MM*CC];   // 32 MB

// ---------------------------------------------------------------------------
// helpers
// ---------------------------------------------------------------------------
__device__ __forceinline__ float to_tf32(float x) {
    float r;
    asm("cvt.rna.tf32.f32 %0, %1;" : "=f"(r) : "f"(x));
    return r;
}

__device__ __forceinline__ float fast_exp2(float x) {
    float r;
    asm("ex2.approx.ftz.f32 %0, %1;" : "=f"(r) : "f"(x));
    return r;
}

__device__ __forceinline__ void mma_tf32(float* d, const float* a, const float* b) {
    asm volatile(
        "mma.sync.aligned.m16n8k8.row.col.f32.tf32.tf32.f32 "
        "{%0,%1,%2,%3}, {%4,%5,%6,%7}, {%8,%9}, {%0,%1,%2,%3};"
        : "+f"(d[0]), "+f"(d[1]), "+f"(d[2]), "+f"(d[3])
        : "r"(__float_as_uint(a[0])), "r"(__float_as_uint(a[1])),
          "r"(__float_as_uint(a[2])), "r"(__float_as_uint(a[3])),
          "r"(__float_as_uint(b[0])), "r"(__float_as_uint(b[1])));
}

// ---------------------------------------------------------------------------
// GEMM (tf32): C[M,N] = A[M,K] @ W[K,N] + bias[N]
// 128x128x16 tile, 256 thr, ping-pong smem double buffer, 1 sync/iter.
// ---------------------------------------------------------------------------
#define SST 136
__global__ __launch_bounds__(256) void gemm_tf32(
    const float* __restrict__ A, const float* __restrict__ W,
    const float* __restrict__ bias, float* __restrict__ Co,
    int Nd, int Kd)
{
    __shared__ float As[2][16][SST];
    __shared__ float Bs[2][16][SST];

    const int tid  = threadIdx.x;
    const int lane = tid & 31;
    const int warp = tid >> 5;
    const int row0 = blockIdx.y * 128;
    const int col0 = blockIdx.x * 128;
    const int wm   = (warp & 1) * 64;
    const int wn   = (warp >> 1) * 32;

    const int aRow = tid >> 2;          // 0..63
    const int aK   = (tid & 3) * 4;     // 0,4,8,12
    const int bK   = tid >> 5;          // 0..7
    const int bC   = (tid & 31) * 4;    // 0..124

    const int grp = lane >> 2;
    const int qid = lane & 3;

    float acc[4][4][4];
#pragma unroll
    for (int i = 0; i < 4; i++)
#pragma unroll
        for (int j = 0; j < 4; j++)
#pragma unroll
            for (int r = 0; r < 4; r++) acc[i][j][r] = 0.f;

    float4 pa[2], pb[2];
    // initial fetch, k0 = 0
#pragma unroll
    for (int h = 0; h < 2; h++) {
        pa[h] = *(const float4*)(A + (size_t)(row0 + aRow + h * 64) * Kd + aK);
        pb[h] = *(const float4*)(W + (size_t)(bK + h * 8) * Nd + col0 + bC);
    }
    // store buffer 0
#pragma unroll
    for (int h = 0; h < 2; h++) {
        const int r = aRow + h * 64;
        As[0][aK + 0][r] = to_tf32(pa[h].x);
        As[0][aK + 1][r] = to_tf32(pa[h].y);
        As[0][aK + 2][r] = to_tf32(pa[h].z);
        As[0][aK + 3][r] = to_tf32(pa[h].w);
        const int kk = bK + h * 8;
        float4 t;
        t.x = to_tf32(pb[h].x); t.y = to_tf32(pb[h].y);
        t.z = to_tf32(pb[h].z); t.w = to_tf32(pb[h].w);
        *(float4*)(&Bs[0][kk][bC]) = t;
    }
    __syncthreads();

    const int niter = Kd / 16;
    for (int it = 0; it < niter; it++) {
        const int cur = it & 1;
        if (it + 1 < niter) {
            const int k0 = (it + 1) * 16;
#pragma unroll
            for (int h = 0; h < 2; h++) {
                pa[h] = *(const float4*)(A + (size_t)(row0 + aRow + h * 64) * Kd + k0 + aK);
                pb[h] = *(const float4*)(W + (size_t)(k0 + bK + h * 8) * Nd + col0 + bC);
            }
        }

#pragma unroll
        for (int kk = 0; kk < 16; kk += 8) {
            float a[4][4];
#pragma unroll
            for (int mt = 0; mt < 4; mt++) {
                const int r = wm + mt * 16 + grp;
                const int c = kk + qid;
                a[mt][0] = As[cur][c][r];
                a[mt][1] = As[cur][c][r + 8];
                a[mt][2] = As[cur][c + 4][r];
                a[mt][3] = As[cur][c + 4][r + 8];
            }
            float b[4][2];
#pragma unroll
            for (int nt = 0; nt < 4; nt++) {
                const int n = wn + nt * 8 + grp;
                const int c = kk + qid;
                b[nt][0] = Bs[cur][c][n];
                b[nt][1] = Bs[cur][c + 4][n];
            }
#pragma unroll
            for (int mt = 0; mt < 4; mt++)
#pragma unroll
                for (int nt = 0; nt < 4; nt++)
                    mma_tf32(acc[mt][nt], a[mt], b[nt]);
        }

        if (it + 1 < niter) {
            const int nxt = cur ^ 1;
#pragma unroll
            for (int h = 0; h < 2; h++) {
                const int r = aRow + h * 64;
                As[nxt][aK + 0][r] = to_tf32(pa[h].x);
                As[nxt][aK + 1][r] = to_tf32(pa[h].y);
                As[nxt][aK + 2][r] = to_tf32(pa[h].z);
                As[nxt][aK + 3][r] = to_tf32(pa[h].w);
                const int kk = bK + h * 8;
                float4 t;
                t.x = to_tf32(pb[h].x); t.y = to_tf32(pb[h].y);
                t.z = to_tf32(pb[h].z); t.w = to_tf32(pb[h].w);
                *(float4*)(&Bs[nxt][kk][bC]) = t;
            }
        }
        __syncthreads();
    }

#pragma unroll
    for (int mt = 0; mt < 4; mt++) {
#pragma unroll
        for (int nt = 0; nt < 4; nt++) {
            const int r  = row0 + wm + mt * 16 + grp;
            const int c  = col0 + wn + nt * 8 + qid * 2;
            float2 o0, o1;
            o0.x = acc[mt][nt][0] + bias[c];
            o0.y = acc[mt][nt][1] + bias[c + 1];
            o1.x = acc[mt][nt][2] + bias[c];
            o1.y = acc[mt][nt][3] + bias[c + 1];
            *(float2*)(Co + (size_t)r * Nd + c)       = o0;
            *(float2*)(Co + (size_t)(r + 8) * Nd + c) = o1;
        }
    }
}

// ---------------------------------------------------------------------------
// Tensor-core flash attention (tf32 with Q/P splits, causal, GQA).
// CTA = (128 q-rows, h, b); 8 warps, warp owns 16 q-rows.
// kv tiles of 64. Register online softmax (shfl over qid group).
// ---------------------------------------------------------------------------
#define ATS 136
#define KVS 76
#define SMF (4*64*ATS + 2*64*KVS)          // floats of dynamic smem
#define SCALE 0.18033688011112042f          // log2(e)/sqrt(64)

__global__ __launch_bounds__(256, 1) void attn_tc(
    const float* __restrict__ Qg, const float* __restrict__ Kg,
    const float* __restrict__ Vg, float* __restrict__ Og)
{
    extern __shared__ float sm[];
    float* Qhi = sm;
    float* Qlo = sm + 64 * ATS;
    float* Phi = sm + 2 * 64 * ATS;
    float* Plo = sm + 3 * 64 * ATS;
    float* Ks  = sm + 4 * 64 * ATS;            // [64 tok][76]
    float* Vs  = sm + 4 * 64 * ATS + 64 * KVS; // [64 tok][76]

    const int tid  = threadIdx.x;
    const int lane = tid & 31;
    const int warp = tid >> 5;
    const int grp  = lane >> 2;
    const int qid  = lane & 3;
    const int q0   = blockIdx.x * 128;
    const int h    = blockIdx.y;
    const int b    = blockIdx.z;
    const int hkv  = h >> 2;
    const int m0   = warp * 16;

    // ---- load Q tile (128 x 64), split to tf32 hi/lo, layout [d][m] ----
#pragma unroll
    for (int i = 0; i < 8; i++) {
        const int idx = tid + i * 256;
        const int row = idx >> 4;
        const int d0  = (idx & 15) * 4;
        float4 v = *(const float4*)(Qg + (size_t)(b * TT + q0 + row) * CC + h * HD + d0);
        float q[4] = {v.x, v.y, v.z, v.w};
#pragma unroll
        for (int j = 0; j < 4; j++) {
            const float hi = to_tf32(q[j]);
            Qhi[(d0 + j) * ATS + row] = hi;
            Qlo[(d0 + j) * ATS + row] = to_tf32(q[j] - hi);
        }
    }

    float m_0 = -1e30f, m_1 = -1e30f, l_0 = 0.f, l_1 = 0.f;
    float o[8][4];
#pragma unroll
    for (int nt = 0; nt < 8; nt++)
#pragma unroll
        for (int e = 0; e < 4; e++) o[nt][e] = 0.f;

    const int ntile     = (q0 >> 6) + 2;
    const int maskstart = q0 >> 6;

    for (int jt = 0; jt < ntile; jt++) {
        const int k0 = jt * 64;
        __syncthreads();   // prior tile done with Ks/Vs (iter0: orders Q stores too)

        // ---- load K,V tile (64 tok x 64 d), natural layout, tf32 ----
#pragma unroll
        for (int i = 0; i < 4; i++) {
            const int idx = tid + i * 256;
            const int tok = idx >> 4;
            const int d0  = (idx & 15) * 4;
            const size_t base = (size_t)(b * TT + k0 + tok) * KVD + hkv * HD + d0;
            float4 kk4 = *(const float4*)(Kg + base);
            float4 tk;
            tk.x = to_tf32(kk4.x); tk.y = to_tf32(kk4.y);
            tk.z = to_tf32(kk4.z); tk.w = to_tf32(kk4.w);
            *(float4*)(Ks + tok * KVS + d0) = tk;
            float4 vv4 = *(const float4*)(Vg + base);
            float4 tv;
            tv.x = to_tf32(vv4.x); tv.y = to_tf32(vv4.y);
            tv.z = to_tf32(vv4.z); tv.w = to_tf32(vv4.w);
            *(float4*)(Vs + tok * KVS + d0) = tv;
        }
        __syncthreads();

        // ---- S = Q K^T  (split Q: 2 mmas per tile) ----
        float s[8][4];
#pragma unroll
        for (int nt = 0; nt < 8; nt++)
#pragma unroll
            for (int e = 0; e < 4; e++) s[nt][e] = 0.f;

#pragma unroll
        for (int kk = 0; kk < 8; kk++) {
            const int c = kk * 8 + qid;
            float ah[4], al[4];
            ah[0] = Qhi[c * ATS + m0 + grp];
            ah[1] = Qhi[c * ATS + m0 + grp + 8];
            ah[2] = Qhi[(c + 4) * ATS + m0 + grp];
            ah[3] = Qhi[(c + 4) * ATS + m0 + grp + 8];
            al[0] = Qlo[c * ATS + m0 + grp];
            al[1] = Qlo[c * ATS + m0 + grp + 8];
            al[2] = Qlo[(c + 4) * ATS + m0 + grp];
            al[3] = Qlo[(c + 4) * ATS + m0 + grp + 8];
#pragma unroll
            for (int nt = 0; nt < 8; nt++) {
                const int n = nt * 8 + grp;
                float bb[2] = { Ks[n * KVS + c], Ks[n * KVS + c + 4] };
                mma_tf32(s[nt], ah, bb);
                mma_tf32(s[nt], al, bb);
            }
        }

        // ---- scale (log2 domain) + causal mask ----
#pragma unroll
        for (int nt = 0; nt < 8; nt++)
#pragma unroll
            for (int e = 0; e < 4; e++) s[nt][e] *= SCALE;
        if (jt >= maskstart) {
#pragma unroll
            for (int nt = 0; nt < 8; nt++)
#pragma unroll
                for (int e = 0; e < 4; e++) {
                    const int row = m0 + grp + ((e >> 1) * 8);
                    const int col = nt * 8 + qid * 2 + (e & 1);
                    if (k0 + col > q0 + row) s[nt][e] = -1e30f;
                }
        }

        // ---- register online softmax (rows r0 = m0+grp, r1 = r0+8) ----
        float mx0 = -1e30f, mx1 = -1e30f;
#pragma unroll
        for (int nt = 0; nt < 8; nt++) {
            mx0 = fmaxf(mx0, fmaxf(s[nt][0], s[nt][1]));
            mx1 = fmaxf(mx1, fmaxf(s[nt][2], s[nt][3]));
        }
        mx0 = fmaxf(mx0, __shfl_xor_sync(0xffffffffu, mx0, 1));
        mx0 = fmaxf(mx0, __shfl_xor_sync(0xffffffffu, mx0, 2));
        mx1 = fmaxf(mx1, __shfl_xor_sync(0xffffffffu, mx1, 1));
        mx1 = fmaxf(mx1, __shfl_xor_sync(0xffffffffu, mx1, 2));

        const float mn0 = fmaxf(m_0, mx0);
        const float mn1 = fmaxf(m_1, mx1);
        const float a0  = fast_exp2(m_0 - mn0);
        const float a1  = fast_exp2(m_1 - mn1);
        m_0 = mn0; m_1 = mn1;

        float ps0 = 0.f, ps1 = 0.f;
#pragma unroll
        for (int nt = 0; nt < 8; nt++) {
#pragma unroll
            for (int e = 0; e < 2; e++) {
                const float p = fast_exp2(s[nt][e] - mn0);
                ps0 += p;
                const int col = nt * 8 + qid * 2 + e;
                const int row = m0 + grp;
                const float ph = to_tf32(p);
                Phi[col * ATS + row] = ph;
                Plo[col * ATS + row] = to_tf32(p - ph);
            }
#pragma unroll
            for (int e = 2; e < 4; e++) {
                const float p = fast_exp2(s[nt][e] - mn1);
                ps1 += p;
                const int col = nt * 8 + qid * 2 + (e & 1);
                const int row = m0 + grp + 8;
                const float ph = to_tf32(p);
                Phi[col * ATS + row] = ph;
                Plo[col * ATS + row] = to_tf32(p - ph);
            }
        }
        ps0 += __shfl_xor_sync(0xffffffffu, ps0, 1);
        ps0 += __shfl_xor_sync(0xffffffffu, ps0, 2);
        ps1 += __shfl_xor_sync(0xffffffffu, ps1, 1);
        ps1 += __shfl_xor_sync(0xffffffffu, ps1, 2);
        l_0 = l_0 * a0 + ps0;
        l_1 = l_1 * a1 + ps1;
        __syncwarp();   // own-warp P stores visible to own-warp fragment loads

        // ---- rescale O, then O += P V (split P: 2 mmas) ----
#pragma unroll
        for (int nt = 0; nt < 8; nt++) {
            o[nt][0] *= a0; o[nt][1] *= a0;
            o[nt][2] *= a1; o[nt][3] *= a1;
        }
#pragma unroll
        for (int kk = 0; kk < 8; kk++) {
            const int c = kk * 8 + qid;
            float ah[4], al[4];
            ah[0] = Phi[c * ATS + m0 + grp];
            ah[1] = Phi[c * ATS + m0 + grp + 8];
            ah[2] = Phi[(c + 4) * ATS + m0 + grp];
            ah[3] = Phi[(c + 4) * ATS + m0 + grp + 8];
            al[0] = Plo[c * ATS + m0 + grp];
            al[1] = Plo[c * ATS + m0 + grp + 8];
            al[2] = Plo[(c + 4) * ATS + m0 + grp];
            al[3] = Plo[(c + 4) * ATS + m0 + grp + 8];
#pragma unroll
            for (int nt = 0; nt < 8; nt++) {
                const int n = nt * 8 + grp;
                float bb[2] = { Vs[c * KVS + n], Vs[(c + 4) * KVS + n] };
                mma_tf32(o[nt], ah, bb);
                mma_tf32(o[nt], al, bb);
            }
        }
    }

    // ---- epilogue: O/l -> g_O ----
    const float inv0 = 1.f / l_0;
    const float inv1 = 1.f / l_1;
    const int r0 = q0 + m0 + grp;
    const int r1 = r0 + 8;
#pragma unroll
    for (int nt = 0; nt < 8; nt++) {
        const int col = h * HD + nt * 8 + qid * 2;
        float2 u0, u1;
        u0.x = o[nt][0] * inv0; u0.y = o[nt][1] * inv0;
        u1.x = o[nt][2] * inv1; u1.y = o[nt][3] * inv1;
        *(float2*)(Og + (size_t)(b * TT + r0) * CC + col) = u0;
        *(float2*)(Og + (size_t)(b * TT + r1) * CC + col) = u1;
    }
}

// ---------------------------------------------------------------------------
extern "C" void kernel_launch(void* const* d_in, const int* in_sizes, int n_in,
                              void* d_out, int out_size)
{
    const float* x  = (const float*)d_in[0];
    // d_in[1] = mask (causal tril) — structural, not read
    const float* Wq = (const float*)d_in[2];
    const float* bq = (const float*)d_in[3];
    const float* Wk = (const float*)d_in[4];
    const float* bk = (const float*)d_in[5];
    const float* Wv = (const float*)d_in[6];
    const float* bv = (const float*)d_in[7];
    const float* Wo = (const float*)d_in[8];
    const float* bo = (const float*)d_in[9];
    float* out = (float*)d_out;

    float *Qp, *Kp, *Vp, *Op;
    cudaGetSymbolAddress((void**)&Qp, g_Q);
    cudaGetSymbolAddress((void**)&Kp, g_K);
    cudaGetSymbolAddress((void**)&Vp, g_V);
    cudaGetSymbolAddress((void**)&Op, g_O);

    const int smem_attn = SMF * sizeof(float);   // 178,176 B
    cudaFuncSetAttribute(attn_tc,
                         cudaFuncAttributeMaxDynamicSharedMemorySize, smem_attn);

    dim3 blk(256);
    gemm_tf32<<<dim3(CC / 128, MM / 128), blk>>>(x,  Wq, bq, Qp, CC,  CC);
    gemm_tf32<<<dim3(KVD / 128, MM / 128), blk>>>(x, Wk, bk, Kp, KVD, CC);
    gemm_tf32<<<dim3(KVD / 128, MM / 128), blk>>>(x, Wv, bv, Vp, KVD, CC);
    attn_tc<<<dim3(TT / 128, HQ, BB), blk, smem_attn>>>(Qp, Kp, Vp, Op);
    gemm_tf32<<<dim3(CC / 128, MM / 128), blk>>>(Op, Wo, bo, out, CC, CC);
}

// round 7
// speedup vs baseline: 2.8168x; 1.1223x over previous
#include <cuda_runtime.h>
#include <stdint.h>

#define BB   2
#define TT   2048
#define CC   2048
#define HQ   32
#define HKV  8
#define HD   64
#define MM   (BB*TT)        // 4096
#define KVD  (HKV*HD)       // 512

// Scratch (no allocations allowed anywhere)
__device__ float g_Q[MM*CC];   // 32 MB
__device__ float g_K[MM*KVD];  // 8 MB
__device__ float g_V[MM*KVD];  // 8 MB
__device__ float g_O[MM*CC];   // 32 MB

// ---------------------------------------------------------------------------
// helpers
// ---------------------------------------------------------------------------
__device__ __forceinline__ float to_tf32(float x) {
    float r;
    asm("cvt.rna.tf32.f32 %0, %1;" : "=f"(r) : "f"(x));
    return r;
}

__device__ __forceinline__ float fast_exp2(float x) {
    float r;
    asm("ex2.approx.ftz.f32 %0, %1;" : "=f"(r) : "f"(x));
    return r;
}

__device__ __forceinline__ void mma_tf32(float* d, const float* a, const float* b) {
    asm volatile(
        "mma.sync.aligned.m16n8k8.row.col.f32.tf32.tf32.f32 "
        "{%0,%1,%2,%3}, {%4,%5,%6,%7}, {%8,%9}, {%0,%1,%2,%3};"
        : "+f"(d[0]), "+f"(d[1]), "+f"(d[2]), "+f"(d[3])
        : "r"(__float_as_uint(a[0])), "r"(__float_as_uint(a[1])),
          "r"(__float_as_uint(a[2])), "r"(__float_as_uint(a[3])),
          "r"(__float_as_uint(b[0])), "r"(__float_as_uint(b[1])));
}

// ---------------------------------------------------------------------------
// GEMM body (tf32): C[row0:+128, col0:+128] = A @ W + bias
// ping-pong smem double buffer, 1 sync/iter.
// ---------------------------------------------------------------------------
#define SST 136
struct GemmSmem {
    float As[2][16][SST];
    float Bs[2][16][SST];
};

__device__ __forceinline__ void gemm_body(
    const float* __restrict__ A, const float* __restrict__ W,
    const float* __restrict__ bias, float* __restrict__ Co,
    int Nd, int Kd, int row0, int col0, GemmSmem& S)
{
    const int tid  = threadIdx.x;
    const int lane = tid & 31;
    const int warp = tid >> 5;
    const int wm   = (warp & 1) * 64;
    const int wn   = (warp >> 1) * 32;

    const int aRow = tid >> 2;          // 0..63
    const int aK   = (tid & 3) * 4;     // 0,4,8,12
    const int bK   = tid >> 5;          // 0..7
    const int bC   = (tid & 31) * 4;    // 0..124

    const int grp = lane >> 2;
    const int qid = lane & 3;

    float acc[4][4][4];
#pragma unroll
    for (int i = 0; i < 4; i++)
#pragma unroll
        for (int j = 0; j < 4; j++)
#pragma unroll
            for (int r = 0; r < 4; r++) acc[i][j][r] = 0.f;

    float4 pa[2], pb[2];
#pragma unroll
    for (int h = 0; h < 2; h++) {
        pa[h] = *(const float4*)(A + (size_t)(row0 + aRow + h * 64) * Kd + aK);
        pb[h] = *(const float4*)(W + (size_t)(bK + h * 8) * Nd + col0 + bC);
    }
#pragma unroll
    for (int h = 0; h < 2; h++) {
        const int r = aRow + h * 64;
        S.As[0][aK + 0][r] = to_tf32(pa[h].x);
        S.As[0][aK + 1][r] = to_tf32(pa[h].y);
        S.As[0][aK + 2][r] = to_tf32(pa[h].z);
        S.As[0][aK + 3][r] = to_tf32(pa[h].w);
        const int kk = bK + h * 8;
        float4 t;
        t.x = to_tf32(pb[h].x); t.y = to_tf32(pb[h].y);
        t.z = to_tf32(pb[h].z); t.w = to_tf32(pb[h].w);
        *(float4*)(&S.Bs[0][kk][bC]) = t;
    }
    __syncthreads();

    const int niter = Kd / 16;
    for (int it = 0; it < niter; it++) {
        const int cur = it & 1;
        if (it + 1 < niter) {
            const int k0 = (it + 1) * 16;
#pragma unroll
            for (int h = 0; h < 2; h++) {
                pa[h] = *(const float4*)(A + (size_t)(row0 + aRow + h * 64) * Kd + k0 + aK);
                pb[h] = *(const float4*)(W + (size_t)(k0 + bK + h * 8) * Nd + col0 + bC);
            }
        }

#pragma unroll
        for (int kk = 0; kk < 16; kk += 8) {
            float a[4][4];
#pragma unroll
            for (int mt = 0; mt < 4; mt++) {
                const int r = wm + mt * 16 + grp;
                const int c = kk + qid;
                a[mt][0] = S.As[cur][c][r];
                a[mt][1] = S.As[cur][c][r + 8];
                a[mt][2] = S.As[cur][c + 4][r];
                a[mt][3] = S.As[cur][c + 4][r + 8];
            }
            float b[4][2];
#pragma unroll
            for (int nt = 0; nt < 4; nt++) {
                const int n = wn + nt * 8 + grp;
                const int c = kk + qid;
                b[nt][0] = S.Bs[cur][c][n];
                b[nt][1] = S.Bs[cur][c + 4][n];
            }
#pragma unroll
            for (int mt = 0; mt < 4; mt++)
#pragma unroll
                for (int nt = 0; nt < 4; nt++)
                    mma_tf32(acc[mt][nt], a[mt], b[nt]);
        }

        if (it + 1 < niter) {
            const int nxt = cur ^ 1;
#pragma unroll
            for (int h = 0; h < 2; h++) {
                const int r = aRow + h * 64;
                S.As[nxt][aK + 0][r] = to_tf32(pa[h].x);
                S.As[nxt][aK + 1][r] = to_tf32(pa[h].y);
                S.As[nxt][aK + 2][r] = to_tf32(pa[h].z);
                S.As[nxt][aK + 3][r] = to_tf32(pa[h].w);
                const int kk = bK + h * 8;
                float4 t;
                t.x = to_tf32(pb[h].x); t.y = to_tf32(pb[h].y);
                t.z = to_tf32(pb[h].z); t.w = to_tf32(pb[h].w);
                *(float4*)(&S.Bs[nxt][kk][bC]) = t;
            }
        }
        __syncthreads();
    }

#pragma unroll
    for (int mt = 0; mt < 4; mt++) {
#pragma unroll
        for (int nt = 0; nt < 4; nt++) {
            const int r  = row0 + wm + mt * 16 + grp;
            const int c  = col0 + wn + nt * 8 + qid * 2;
            float2 o0, o1;
            o0.x = acc[mt][nt][0] + bias[c];
            o0.y = acc[mt][nt][1] + bias[c + 1];
            o1.x = acc[mt][nt][2] + bias[c];
            o1.y = acc[mt][nt][3] + bias[c + 1];
            *(float2*)(Co + (size_t)r * Nd + c)       = o0;
            *(float2*)(Co + (size_t)(r + 8) * Nd + c) = o1;
        }
    }
}

__global__ __launch_bounds__(256) void gemm_tf32(
    const float* __restrict__ A, const float* __restrict__ W,
    const float* __restrict__ bias, float* __restrict__ Co,
    int Nd, int Kd)
{
    __shared__ GemmSmem S;
    gemm_body(A, W, bias, Co, Nd, Kd, blockIdx.y * 128, blockIdx.x * 128, S);
}

// Fused K+V projection: grid.x = 8; x<4 -> K tile, else V tile.
__global__ __launch_bounds__(256) void gemm_tf32_kv(
    const float* __restrict__ A,
    const float* __restrict__ Wk, const float* __restrict__ bk, float* __restrict__ Ko,
    const float* __restrict__ Wv, const float* __restrict__ bv, float* __restrict__ Vo)
{
    __shared__ GemmSmem S;
    const bool isV = blockIdx.x >= 4;
    const int col0 = (blockIdx.x & 3) * 128;
    gemm_body(A, isV ? Wv : Wk, isV ? bv : bk, isV ? Vo : Ko,
              KVD, CC, blockIdx.y * 128, col0, S);
}

// ---------------------------------------------------------------------------
// Tensor-core flash attention (tf32, Q split hi/lo, single-P PV, causal, GQA).
// CTA = (128 q-rows, h, b); 8 warps, warp owns 16 q-rows.
// Double-buffered K/V tiles (64 keys) with register prefetch; 1 sync/tile.
// ---------------------------------------------------------------------------
#define ATS 136
#define KVS 76
#define SMF (3*64*ATS + 4*64*KVS)           // 45,568 floats = 182,272 B
#define SCALE 0.18033688011112042f           // log2(e)/sqrt(64)

__global__ __launch_bounds__(256, 1) void attn_tc(
    const float* __restrict__ Qg, const float* __restrict__ Kg,
    const float* __restrict__ Vg, float* __restrict__ Og)
{
    extern __shared__ float sm[];
    float* Qhi = sm;
    float* Qlo = sm + 64 * ATS;
    float* Phi = sm + 2 * 64 * ATS;
    float* KV  = sm + 3 * 64 * ATS;   // [buf][ Ks 64*KVS | Vs 64*KVS ]

    const int tid  = threadIdx.x;
    const int lane = tid & 31;
    const int warp = tid >> 5;
    const int grp  = lane >> 2;
    const int qid  = lane & 3;
    const int q0   = (gridDim.x - 1 - blockIdx.x) * 128;   // long CTAs first
    const int h    = blockIdx.y;
    const int b    = blockIdx.z;
    const int hkv  = h >> 2;
    const int m0   = warp * 16;

    // KV loader mapping (per thread: 4 chunks)
    const int ldTok = tid >> 4;          // 0..15 (+16 per chunk)
    const int ldD   = (tid & 15) * 4;    // 0..60

    // ---- load Q tile (128 x 64), split tf32 hi/lo, layout [d][m] ----
#pragma unroll
    for (int i = 0; i < 8; i++) {
        const int idx = tid + i * 256;
        const int row = idx >> 4;
        const int d0  = (idx & 15) * 4;
        float4 v = *(const float4*)(Qg + (size_t)(b * TT + q0 + row) * CC + h * HD + d0);
        float q[4] = {v.x, v.y, v.z, v.w};
#pragma unroll
        for (int j = 0; j < 4; j++) {
            const float hi = to_tf32(q[j]);
            Qhi[(d0 + j) * ATS + row] = hi;
            Qlo[(d0 + j) * ATS + row] = to_tf32(q[j] - hi);
        }
    }

    const int ntile     = (q0 >> 6) + 2;
    const int maskstart = q0 >> 6;

    // ---- prefetch + store tile 0 into buffer 0 ----
    float4 kreg[4], vreg[4];
#pragma unroll
    for (int i = 0; i < 4; i++) {
        const size_t base = (size_t)(b * TT + ldTok + i * 16) * KVD + hkv * HD + ldD;
        kreg[i] = *(const float4*)(Kg + base);
        vreg[i] = *(const float4*)(Vg + base);
    }
    {
        float* Ks = KV;
        float* Vs = KV + 64 * KVS;
#pragma unroll
        for (int i = 0; i < 4; i++) {
            const int tok = ldTok + i * 16;
            float4 tk, tv;
            tk.x = to_tf32(kreg[i].x); tk.y = to_tf32(kreg[i].y);
            tk.z = to_tf32(kreg[i].z); tk.w = to_tf32(kreg[i].w);
            tv.x = to_tf32(vreg[i].x); tv.y = to_tf32(vreg[i].y);
            tv.z = to_tf32(vreg[i].z); tv.w = to_tf32(vreg[i].w);
            *(float4*)(Ks + tok * KVS + ldD) = tk;
            *(float4*)(Vs + tok * KVS + ldD) = tv;
        }
    }
    __syncthreads();

    float m_0 = -1e30f, m_1 = -1e30f, l_0 = 0.f, l_1 = 0.f;
    float o[8][4];
#pragma unroll
    for (int nt = 0; nt < 8; nt++)
#pragma unroll
        for (int e = 0; e < 4; e++) o[nt][e] = 0.f;

    for (int jt = 0; jt < ntile; jt++) {
        const int cur = jt & 1;
        float* Ks = KV + cur * (2 * 64 * KVS);
        float* Vs = Ks + 64 * KVS;

        // prefetch next tile (global loads issued before compute)
        const bool more = (jt + 1 < ntile);
        if (more) {
            const int k0n = (jt + 1) * 64;
#pragma unroll
            for (int i = 0; i < 4; i++) {
                const size_t base = (size_t)(b * TT + k0n + ldTok + i * 16) * KVD + hkv * HD + ldD;
                kreg[i] = *(const float4*)(Kg + base);
                vreg[i] = *(const float4*)(Vg + base);
            }
        }

        // ---- S = Q K^T  (split Q: 2 mmas per fragment) ----
        float s[8][4];
#pragma unroll
        for (int nt = 0; nt < 8; nt++)
#pragma unroll
            for (int e = 0; e < 4; e++) s[nt][e] = 0.f;

#pragma unroll
        for (int kk = 0; kk < 8; kk++) {
            const int c = kk * 8 + qid;
            float ah[4], al[4];
            ah[0] = Qhi[c * ATS + m0 + grp];
            ah[1] = Qhi[c * ATS + m0 + grp + 8];
            ah[2] = Qhi[(c + 4) * ATS + m0 + grp];
            ah[3] = Qhi[(c + 4) * ATS + m0 + grp + 8];
            al[0] = Qlo[c * ATS + m0 + grp];
            al[1] = Qlo[c * ATS + m0 + grp + 8];
            al[2] = Qlo[(c + 4) * ATS + m0 + grp];
            al[3] = Qlo[(c + 4) * ATS + m0 + grp + 8];
#pragma unroll
            for (int nt = 0; nt < 8; nt++) {
                const int n = nt * 8 + grp;
                float bb[2] = { Ks[n * KVS + c], Ks[n * KVS + c + 4] };
                mma_tf32(s[nt], ah, bb);
                mma_tf32(s[nt], al, bb);
            }
        }

        // ---- scale (log2 domain) + causal mask ----
#pragma unroll
        for (int nt = 0; nt < 8; nt++)
#pragma unroll
            for (int e = 0; e < 4; e++) s[nt][e] *= SCALE;
        if (jt >= maskstart) {
            const int k0 = jt * 64;
#pragma unroll
            for (int nt = 0; nt < 8; nt++)
#pragma unroll
                for (int e = 0; e < 4; e++) {
                    const int row = m0 + grp + ((e >> 1) * 8);
                    const int col = nt * 8 + qid * 2 + (e & 1);
                    if (k0 + col > q0 + row) s[nt][e] = -1e30f;
                }
        }

        // ---- register online softmax (rows r0 = m0+grp, r1 = r0+8) ----
        float mx0 = -1e30f, mx1 = -1e30f;
#pragma unroll
        for (int nt = 0; nt < 8; nt++) {
            mx0 = fmaxf(mx0, fmaxf(s[nt][0], s[nt][1]));
            mx1 = fmaxf(mx1, fmaxf(s[nt][2], s[nt][3]));
        }
        mx0 = fmaxf(mx0, __shfl_xor_sync(0xffffffffu, mx0, 1));
        mx0 = fmaxf(mx0, __shfl_xor_sync(0xffffffffu, mx0, 2));
        mx1 = fmaxf(mx1, __shfl_xor_sync(0xffffffffu, mx1, 1));
        mx1 = fmaxf(mx1, __shfl_xor_sync(0xffffffffu, mx1, 2));

        const float mn0 = fmaxf(m_0, mx0);
        const float mn1 = fmaxf(m_1, mx1);
        const float a0  = fast_exp2(m_0 - mn0);
        const float a1  = fast_exp2(m_1 - mn1);
        m_0 = mn0; m_1 = mn1;

        float ps0 = 0.f, ps1 = 0.f;
#pragma unroll
        for (int nt = 0; nt < 8; nt++) {
#pragma unroll
            for (int e = 0; e < 2; e++) {
                const float p = fast_exp2(s[nt][e] - mn0);
                ps0 += p;
                Phi[(nt * 8 + qid * 2 + e) * ATS + m0 + grp] = to_tf32(p);
            }
#pragma unroll
            for (int e = 2; e < 4; e++) {
                const float p = fast_exp2(s[nt][e] - mn1);
                ps1 += p;
                Phi[(nt * 8 + qid * 2 + (e & 1)) * ATS + m0 + grp + 8] = to_tf32(p);
            }
        }
        ps0 += __shfl_xor_sync(0xffffffffu, ps0, 1);
        ps0 += __shfl_xor_sync(0xffffffffu, ps0, 2);
        ps1 += __shfl_xor_sync(0xffffffffu, ps1, 1);
        ps1 += __shfl_xor_sync(0xffffffffu, ps1, 2);
        l_0 = l_0 * a0 + ps0;
        l_1 = l_1 * a1 + ps1;
        __syncwarp();   // own-warp P stores -> own-warp fragment loads

        // ---- rescale O, then O += P V ----
#pragma unroll
        for (int nt = 0; nt < 8; nt++) {
            o[nt][0] *= a0; o[nt][1] *= a0;
            o[nt][2] *= a1; o[nt][3] *= a1;
        }
#pragma unroll
        for (int kk = 0; kk < 8; kk++) {
            const int c = kk * 8 + qid;
            float ah[4];
            ah[0] = Phi[c * ATS + m0 + grp];
            ah[1] = Phi[c * ATS + m0 + grp + 8];
            ah[2] = Phi[(c + 4) * ATS + m0 + grp];
            ah[3] = Phi[(c + 4) * ATS + m0 + grp + 8];
#pragma unroll
            for (int nt = 0; nt < 8; nt++) {
                const int n = nt * 8 + grp;
                float bb[2] = { Vs[c * KVS + n], Vs[(c + 4) * KVS + n] };
                mma_tf32(o[nt], ah, bb);
            }
        }

        // ---- store prefetched tile into alternate buffer ----
        if (more) {
            float* Kn = KV + (cur ^ 1) * (2 * 64 * KVS);
            float* Vn = Kn + 64 * KVS;
#pragma unroll
            for (int i = 0; i < 4; i++) {
                const int tok = ldTok + i * 16;
                float4 tk, tv;
                tk.x = to_tf32(kreg[i].x); tk.y = to_tf32(kreg[i].y);
                tk.z = to_tf32(kreg[i].z); tk.w = to_tf32(kreg[i].w);
                tv.x = to_tf32(vreg[i].x); tv.y = to_tf32(vreg[i].y);
                tv.z = to_tf32(vreg[i].z); tv.w = to_tf32(vreg[i].w);
                *(float4*)(Kn + tok * KVS + ldD) = tk;
                *(float4*)(Vn + tok * KVS + ldD) = tv;
            }
        }
        __syncthreads();
    }

    // ---- epilogue: O/l -> g_O ----
    const float inv0 = 1.f / l_0;
    const float inv1 = 1.f / l_1;
    const int r0 = q0 + m0 + grp;
    const int r1 = r0 + 8;
#pragma unroll
    for (int nt = 0; nt < 8; nt++) {
        const int col = h * HD + nt * 8 + qid * 2;
        float2 u0, u1;
        u0.x = o[nt][0] * inv0; u0.y = o[nt][1] * inv0;
        u1.x = o[nt][2] * inv1; u1.y = o[nt][3] * inv1;
        *(float2*)(Og + (size_t)(b * TT + r0) * CC + col) = u0;
        *(float2*)(Og + (size_t)(b * TT + r1) * CC + col) = u1;
    }
}

// ---------------------------------------------------------------------------
extern "C" void kernel_launch(void* const* d_in, const int* in_sizes, int n_in,
                              void* d_out, int out_size)
{
    const float* x  = (const float*)d_in[0];
    // d_in[1] = mask (causal tril) — structural, not read
    const float* Wq = (const float*)d_in[2];
    const float* bq = (const float*)d_in[3];
    const float* Wk = (const float*)d_in[4];
    const float* bk = (const float*)d_in[5];
    const float* Wv = (const float*)d_in[6];
    const float* bv = (const float*)d_in[7];
    const float* Wo = (const float*)d_in[8];
    const float* bo = (const float*)d_in[9];
    float* out = (float*)d_out;

    float *Qp, *Kp, *Vp, *Op;
    cudaGetSymbolAddress((void**)&Qp, g_Q);
    cudaGetSymbolAddress((void**)&Kp, g_K);
    cudaGetSymbolAddress((void**)&Vp, g_V);
    cudaGetSymbolAddress((void**)&Op, g_O);

    const int smem_attn = SMF * sizeof(float);   // 182,272 B
    cudaFuncSetAttribute(attn_tc,
                         cudaFuncAttributeMaxDynamicSharedMemorySize, smem_attn);

    dim3 blk(256);
    gemm_tf32<<<dim3(CC / 128, MM / 128), blk>>>(x, Wq, bq, Qp, CC, CC);
    gemm_tf32_kv<<<dim3(8, MM / 128), blk>>>(x, Wk, bk, Kp, Wv, bv, Vp);
    attn_tc<<<dim3(TT / 128, HQ, BB), blk, smem_attn>>>(Qp, Kp, Vp, Op);
    gemm_tf32<<<dim3(CC / 128, MM / 128), blk>>>(Op, Wo, bo, out, CC, CC);
}

// round 8
// speedup vs baseline: 3.1220x; 1.1084x over previous
#include <cuda_runtime.h>
#include <stdint.h>

#define BB   2
#define TT   2048
#define CC   2048
#define HQ   32
#define HKV  8
#define HD   64
#define MM   (BB*TT)        // 4096
#define KVD  (HKV*HD)       // 512

// Scratch (no allocations allowed anywhere)
__device__ float g_Q[MM*CC];     // 32 MB
__device__ float g_K[MM*KVD];    // 8 MB
__device__ float g_V[MM*KVD];    // 8 MB
__device__ float g_O[MM*CC];     // 32 MB  (tf32-rounded by attn epilogue)
__device__ float g_Xc[MM*CC];    // tf32-rounded x
__device__ float g_Wqc[CC*CC];
__device__ float g_Wkc[CC*KVD];
__device__ float g_Wvc[CC*KVD];
__device__ float g_Woc[CC*CC];

// ---------------------------------------------------------------------------
// helpers
// ---------------------------------------------------------------------------
__device__ __forceinline__ float to_tf32(float x) {
    float r;
    asm("cvt.rna.tf32.f32 %0, %1;" : "=f"(r) : "f"(x));
    return r;
}

__device__ __forceinline__ float fast_exp2(float x) {
    float r;
    asm("ex2.approx.ftz.f32 %0, %1;" : "=f"(r) : "f"(x));
    return r;
}

__device__ __forceinline__ void mma_tf32(float* d, const float* a, const float* b) {
    asm volatile(
        "mma.sync.aligned.m16n8k8.row.col.f32.tf32.tf32.f32 "
        "{%0,%1,%2,%3}, {%4,%5,%6,%7}, {%8,%9}, {%0,%1,%2,%3};"
        : "+f"(d[0]), "+f"(d[1]), "+f"(d[2]), "+f"(d[3])
        : "r"(__float_as_uint(a[0])), "r"(__float_as_uint(a[1])),
          "r"(__float_as_uint(a[2])), "r"(__float_as_uint(a[3])),
          "r"(__float_as_uint(b[0])), "r"(__float_as_uint(b[1])));
}

// ---------------------------------------------------------------------------
// tf32 pre-rounding pass: x, Wq, Wk, Wv, Wo  ->  g_Xc, g_Wqc, ...
// ---------------------------------------------------------------------------
__global__ __launch_bounds__(256) void cvt_pass(
    const float* __restrict__ x,  const float* __restrict__ wq,
    const float* __restrict__ wk, const float* __restrict__ wv,
    const float* __restrict__ wo)
{
    const float* src; float* dst; int n4;
    switch (blockIdx.y) {
        case 0:  src = x;  dst = g_Xc;  n4 = MM * CC / 4;  break;
        case 1:  src = wq; dst = g_Wqc; n4 = CC * CC / 4;  break;
        case 2:  src = wk; dst = g_Wkc; n4 = CC * KVD / 4; break;
        case 3:  src = wv; dst = g_Wvc; n4 = CC * KVD / 4; break;
        default: src = wo; dst = g_Woc; n4 = CC * CC / 4;  break;
    }
    for (int i = blockIdx.x * blockDim.x + threadIdx.x; i < n4;
         i += gridDim.x * blockDim.x) {
        float4 v = ((const float4*)src)[i];
        v.x = to_tf32(v.x); v.y = to_tf32(v.y);
        v.z = to_tf32(v.z); v.w = to_tf32(v.w);
        ((float4*)dst)[i] = v;
    }
}

// ---------------------------------------------------------------------------
// GEMM body (inputs pre-rounded to tf32): C = A @ W + bias
// 128x128x16 tile, 256 thr, ping-pong double buffer, 1 sync/iter.
// A staged row-major [m][20] (pad 20 -> conflict-free frags, float4 STS).
// ---------------------------------------------------------------------------
#define SSTA 20
#define SSTB 136

__device__ __forceinline__ void gemm_body(
    const float* __restrict__ A, const float* __restrict__ W,
    const float* __restrict__ bias, float* __restrict__ Co,
    int Nd, int Kd, int row0, int col0)
{
    __shared__ float As[2][128][SSTA];
    __shared__ float Bs[2][16][SSTB];

    const int tid  = threadIdx.x;
    const int lane = tid & 31;
    const int warp = tid >> 5;
    const int wm   = (warp & 1) * 64;
    const int wn   = (warp >> 1) * 32;

    const int aRow = tid >> 2;          // 0..63
    const int aK   = (tid & 3) * 4;     // 0,4,8,12
    const int bK   = tid >> 5;          // 0..7
    const int bC   = (tid & 31) * 4;    // 0..124

    const int grp = lane >> 2;
    const int qid = lane & 3;

    float acc[4][4][4];
#pragma unroll
    for (int i = 0; i < 4; i++)
#pragma unroll
        for (int j = 0; j < 4; j++)
#pragma unroll
            for (int r = 0; r < 4; r++) acc[i][j][r] = 0.f;

    float4 pa[2], pb[2];
#pragma unroll
    for (int h = 0; h < 2; h++) {
        pa[h] = *(const float4*)(A + (size_t)(row0 + aRow + h * 64) * Kd + aK);
        pb[h] = *(const float4*)(W + (size_t)(bK + h * 8) * Nd + col0 + bC);
    }
#pragma unroll
    for (int h = 0; h < 2; h++) {
        *(float4*)(&As[0][aRow + h * 64][aK]) = pa[h];
        *(float4*)(&Bs[0][bK + h * 8][bC])    = pb[h];
    }
    __syncthreads();

    const float* Ac = &As[0][0][0]; float* An = &As[1][0][0];
    const float* Bc = &Bs[0][0][0]; float* Bn = &Bs[1][0][0];

    const int niter = Kd / 16;
    for (int it = 0; it < niter; it++) {
        if (it + 1 < niter) {
            const int k0 = (it + 1) * 16;
#pragma unroll
            for (int h = 0; h < 2; h++) {
                pa[h] = *(const float4*)(A + (size_t)(row0 + aRow + h * 64) * Kd + k0 + aK);
                pb[h] = *(const float4*)(W + (size_t)(k0 + bK + h * 8) * Nd + col0 + bC);
            }
        }

#pragma unroll
        for (int kk = 0; kk < 16; kk += 8) {
            const int c = kk + qid;
            float a[4][4];
#pragma unroll
            for (int mt = 0; mt < 4; mt++) {
                const int r = wm + mt * 16 + grp;
                a[mt][0] = Ac[r * SSTA + c];
                a[mt][1] = Ac[(r + 8) * SSTA + c];
                a[mt][2] = Ac[r * SSTA + c + 4];
                a[mt][3] = Ac[(r + 8) * SSTA + c + 4];
            }
            float b[4][2];
#pragma unroll
            for (int nt = 0; nt < 4; nt++) {
                const int n = wn + nt * 8 + grp;
                b[nt][0] = Bc[c * SSTB + n];
                b[nt][1] = Bc[(c + 4) * SSTB + n];
            }
#pragma unroll
            for (int mt = 0; mt < 4; mt++)
#pragma unroll
                for (int nt = 0; nt < 4; nt++)
                    mma_tf32(acc[mt][nt], a[mt], b[nt]);
        }

        if (it + 1 < niter) {
#pragma unroll
            for (int h = 0; h < 2; h++) {
                *(float4*)(&An[(aRow + h * 64) * SSTA + aK]) = pa[h];
                *(float4*)(&Bn[(bK + h * 8) * SSTB + bC])    = pb[h];
            }
        }
        // swap buffers
        { const float* t = Ac; Ac = An; An = (float*)t; }
        { const float* t = Bc; Bc = Bn; Bn = (float*)t; }
        __syncthreads();
    }

#pragma unroll
    for (int mt = 0; mt < 4; mt++) {
#pragma unroll
        for (int nt = 0; nt < 4; nt++) {
            const int r  = row0 + wm + mt * 16 + grp;
            const int c  = col0 + wn + nt * 8 + qid * 2;
            float2 o0, o1;
            o0.x = acc[mt][nt][0] + bias[c];
            o0.y = acc[mt][nt][1] + bias[c + 1];
            o1.x = acc[mt][nt][2] + bias[c];
            o1.y = acc[mt][nt][3] + bias[c + 1];
            *(float2*)(Co + (size_t)r * Nd + c)       = o0;
            *(float2*)(Co + (size_t)(r + 8) * Nd + c) = o1;
        }
    }
}

// Fused Q+K+V projection. grid.x = 24: [0,16) Q cols, [16,20) K, [20,24) V.
__global__ __launch_bounds__(256, 2) void gemm_qkv(
    const float* __restrict__ bq, const float* __restrict__ bk,
    const float* __restrict__ bv)
{
    const int bx = blockIdx.x;
    if (bx < 16)
        gemm_body(g_Xc, g_Wqc, bq, g_Q, CC,  CC, blockIdx.y * 128, bx * 128);
    else if (bx < 20)
        gemm_body(g_Xc, g_Wkc, bk, g_K, KVD, CC, blockIdx.y * 128, (bx - 16) * 128);
    else
        gemm_body(g_Xc, g_Wvc, bv, g_V, KVD, CC, blockIdx.y * 128, (bx - 20) * 128);
}

// Output projection: out = g_O @ Woc + bo
__global__ __launch_bounds__(256, 2) void gemm_out(
    const float* __restrict__ bo, float* __restrict__ out)
{
    gemm_body(g_O, g_Woc, bo, out, CC, CC, blockIdx.y * 128, blockIdx.x * 128);
}

// ---------------------------------------------------------------------------
// Tensor-core flash attention (tf32, Q split hi/lo in REGISTERS, causal, GQA).
// CTA = (128 q-rows, h, b); 8 warps, warp owns 16 q-rows.
// K stored [tok][d] stride 76; V stored transposed [d][tok] stride 68.
// Double-buffered K/V, register prefetch, 1 syncthreads/tile.
// Phi aliases the (dead after prologue) Q staging area.
// ---------------------------------------------------------------------------
#define ATS  136
#define KVSK 76
#define KVSV 68
#define SM_KV0 (2*64*ATS)                      // 17408 floats
#define SM_BUF (64*KVSK + 64*KVSV)             // 9216 floats
#define SMF  (SM_KV0 + 2*SM_BUF)               // 35840 floats = 143,360 B
#define SCALE 0.18033688011112042f             // log2(e)/sqrt(64)

__global__ __launch_bounds__(256, 1) void attn_tc(
    const float* __restrict__ Qg, const float* __restrict__ Kg,
    const float* __restrict__ Vg, float* __restrict__ Og)
{
    extern __shared__ float sm[];
    float* Qhi = sm;                  // prologue only
    float* Qlo = sm + 64 * ATS;       // prologue only
    float* Phi = sm;                  // aliases Qhi after prologue

    const int tid  = threadIdx.x;
    const int lane = tid & 31;
    const int warp = tid >> 5;
    const int grp  = lane >> 2;
    const int qid  = lane & 3;
    const int q0   = (gridDim.x - 1 - blockIdx.x) * 128;   // long CTAs first
    const int h    = blockIdx.y;
    const int b    = blockIdx.z;
    const int hkv  = h >> 2;
    const int m0   = warp * 16;

    // K loader: tok fast over warps
    const int kTok = tid >> 4;           // 0..15 (+16/chunk)
    const int kD   = (tid & 15) * 4;     // 0..60
    // V loader (transposed store): tok = lane-low, d = lane-high
    const int vTok = tid & 15;           // 0..15 (+16/chunk)
    const int vD   = (tid >> 4) * 4;     // 0..60

    const int ntile     = (q0 >> 6) + 2;
    const int maskstart = q0 >> 6;

    // ---- issue KV tile-0 global loads early ----
    float4 kreg[4], vreg[4];
#pragma unroll
    for (int i = 0; i < 4; i++) {
        kreg[i] = *(const float4*)(Kg + (size_t)(b * TT + kTok + i * 16) * KVD + hkv * HD + kD);
        vreg[i] = *(const float4*)(Vg + (size_t)(b * TT + vTok + i * 16) * KVD + hkv * HD + vD);
    }

    // ---- stage Q (128 x 64) split hi/lo, layout [d][m] ----
#pragma unroll
    for (int i = 0; i < 8; i++) {
        const int idx = tid + i * 256;
        const int row = idx >> 4;
        const int d0  = (idx & 15) * 4;
        float4 v = *(const float4*)(Qg + (size_t)(b * TT + q0 + row) * CC + h * HD + d0);
        float q[4] = {v.x, v.y, v.z, v.w};
#pragma unroll
        for (int j = 0; j < 4; j++) {
            const float hi = to_tf32(q[j]);
            Qhi[(d0 + j) * ATS + row] = hi;
            Qlo[(d0 + j) * ATS + row] = to_tf32(q[j] - hi);
        }
    }
    __syncthreads();

    // ---- hoist Q fragments into registers (loop-invariant) ----
    float qh[8][4], ql[8][4];
#pragma unroll
    for (int kk = 0; kk < 8; kk++) {
        const int c = kk * 8 + qid;
        qh[kk][0] = Qhi[c * ATS + m0 + grp];
        qh[kk][1] = Qhi[c * ATS + m0 + grp + 8];
        qh[kk][2] = Qhi[(c + 4) * ATS + m0 + grp];
        qh[kk][3] = Qhi[(c + 4) * ATS + m0 + grp + 8];
        ql[kk][0] = Qlo[c * ATS + m0 + grp];
        ql[kk][1] = Qlo[c * ATS + m0 + grp + 8];
        ql[kk][2] = Qlo[(c + 4) * ATS + m0 + grp];
        ql[kk][3] = Qlo[(c + 4) * ATS + m0 + grp + 8];
    }

    // ---- store KV tile 0 into buffer 0 ----
    {
        float* K0 = sm + SM_KV0;
        float* V0 = K0 + 64 * KVSK;
#pragma unroll
        for (int i = 0; i < 4; i++) {
            *(float4*)(K0 + (kTok + i * 16) * KVSK + kD) = kreg[i];
            const int tok = vTok + i * 16;
            V0[(vD + 0) * KVSV + tok] = vreg[i].x;
            V0[(vD + 1) * KVSV + tok] = vreg[i].y;
            V0[(vD + 2) * KVSV + tok] = vreg[i].z;
            V0[(vD + 3) * KVSV + tok] = vreg[i].w;
        }
    }
    __syncthreads();   // KV0 visible; also orders Q-frag reads before Phi writes

    float m_0 = -1e30f, m_1 = -1e30f, l_0 = 0.f, l_1 = 0.f;
    float o[8][4];
#pragma unroll
    for (int nt = 0; nt < 8; nt++)
#pragma unroll
        for (int e = 0; e < 4; e++) o[nt][e] = 0.f;

    for (int jt = 0; jt < ntile; jt++) {
        float* Ks = sm + SM_KV0 + (jt & 1) * SM_BUF;
        float* Vt = Ks + 64 * KVSK;
        const bool more = (jt + 1 < ntile);

        // prefetch next K (issued before compute)
        if (more) {
            const int k0n = (jt + 1) * 64;
#pragma unroll
            for (int i = 0; i < 4; i++)
                kreg[i] = *(const float4*)(Kg + (size_t)(b * TT + k0n + kTok + i * 16) * KVD + hkv * HD + kD);
        }

        // ---- S = Q K^T  (split Q: 2 mmas per fragment) ----
        float s[8][4];
#pragma unroll
        for (int nt = 0; nt < 8; nt++)
#pragma unroll
            for (int e = 0; e < 4; e++) s[nt][e] = 0.f;

#pragma unroll
        for (int kk = 0; kk < 8; kk++) {
            const int c = kk * 8 + qid;
#pragma unroll
            for (int nt = 0; nt < 8; nt++) {
                const int n = nt * 8 + grp;
                float bb[2] = { Ks[n * KVSK + c], Ks[n * KVSK + c + 4] };
                mma_tf32(s[nt], qh[kk], bb);
                mma_tf32(s[nt], ql[kk], bb);
            }
        }

        // prefetch next V (after S issue; still most of tile to land)
        if (more) {
            const int k0n = (jt + 1) * 64;
#pragma unroll
            for (int i = 0; i < 4; i++)
                vreg[i] = *(const float4*)(Vg + (size_t)(b * TT + k0n + vTok + i * 16) * KVD + hkv * HD + vD);
        }

        // ---- scale (log2 domain) + causal mask ----
#pragma unroll
        for (int nt = 0; nt < 8; nt++)
#pragma unroll
            for (int e = 0; e < 4; e++) s[nt][e] *= SCALE;
        if (jt >= maskstart) {
            const int k0 = jt * 64;
#pragma unroll
            for (int nt = 0; nt < 8; nt++)
#pragma unroll
                for (int e = 0; e < 4; e++) {
                    const int row = m0 + grp + ((e >> 1) * 8);
                    const int col = nt * 8 + qid * 2 + (e & 1);
                    if (k0 + col > q0 + row) s[nt][e] = -1e30f;
                }
        }

        // ---- register online softmax ----
        float mx0 = -1e30f, mx1 = -1e30f;
#pragma unroll
        for (int nt = 0; nt < 8; nt++) {
            mx0 = fmaxf(mx0, fmaxf(s[nt][0], s[nt][1]));
            mx1 = fmaxf(mx1, fmaxf(s[nt][2], s[nt][3]));
        }
        mx0 = fmaxf(mx0, __shfl_xor_sync(0xffffffffu, mx0, 1));
        mx0 = fmaxf(mx0, __shfl_xor_sync(0xffffffffu, mx0, 2));
        mx1 = fmaxf(mx1, __shfl_xor_sync(0xffffffffu, mx1, 1));
        mx1 = fmaxf(mx1, __shfl_xor_sync(0xffffffffu, mx1, 2));

        const float mn0 = fmaxf(m_0, mx0);
        const float mn1 = fmaxf(m_1, mx1);
        const float a0  = fast_exp2(m_0 - mn0);
        const float a1  = fast_exp2(m_1 - mn1);
        m_0 = mn0; m_1 = mn1;

        float ps0 = 0.f, ps1 = 0.f;
#pragma unroll
        for (int nt = 0; nt < 8; nt++) {
#pragma unroll
            for (int e = 0; e < 2; e++) {
                const float p = fast_exp2(s[nt][e] - mn0);
                ps0 += p;
                Phi[(nt * 8 + qid * 2 + e) * ATS + m0 + grp] = to_tf32(p);
            }
#pragma unroll
            for (int e = 2; e < 4; e++) {
                const float p = fast_exp2(s[nt][e] - mn1);
                ps1 += p;
                Phi[(nt * 8 + qid * 2 + (e & 1)) * ATS + m0 + grp + 8] = to_tf32(p);
            }
        }
        ps0 += __shfl_xor_sync(0xffffffffu, ps0, 1);
        ps0 += __shfl_xor_sync(0xffffffffu, ps0, 2);
        ps1 += __shfl_xor_sync(0xffffffffu, ps1, 1);
        ps1 += __shfl_xor_sync(0xffffffffu, ps1, 2);
        l_0 = l_0 * a0 + ps0;
        l_1 = l_1 * a1 + ps1;
        __syncwarp();   // own-warp P stores -> own-warp fragment loads

        // ---- rescale O, then O += P V ----
#pragma unroll
        for (int nt = 0; nt < 8; nt++) {
            o[nt][0] *= a0; o[nt][1] *= a0;
            o[nt][2] *= a1; o[nt][3] *= a1;
        }
#pragma unroll
        for (int kk = 0; kk < 8; kk++) {
            const int c = kk * 8 + qid;
            float ah[4];
            ah[0] = Phi[c * ATS + m0 + grp];
            ah[1] = Phi[c * ATS + m0 + grp + 8];
            ah[2] = Phi[(c + 4) * ATS + m0 + grp];
            ah[3] = Phi[(c + 4) * ATS + m0 + grp + 8];
#pragma unroll
            for (int nt = 0; nt < 8; nt++) {
                const int n = nt * 8 + grp;
                float bb[2] = { Vt[n * KVSV + c], Vt[n * KVSV + c + 4] };
                mma_tf32(o[nt], ah, bb);
            }
        }

        // ---- store prefetched tile into alternate buffer ----
        if (more) {
            float* Kn = sm + SM_KV0 + ((jt + 1) & 1) * SM_BUF;
            float* Vn = Kn + 64 * KVSK;
#pragma unroll
            for (int i = 0; i < 4; i++) {
                *(float4*)(Kn + (kTok + i * 16) * KVSK + kD) = kreg[i];
                const int tok = vTok + i * 16;
                Vn[(vD + 0) * KVSV + tok] = vreg[i].x;
                Vn[(vD + 1) * KVSV + tok] = vreg[i].y;
                Vn[(vD + 2) * KVSV + tok] = vreg[i].z;
                Vn[(vD + 3) * KVSV + tok] = vreg[i].w;
            }
        }
        __syncthreads();
    }

    // ---- epilogue: tf32-rounded O/l -> g_O (pre-rounded for out-proj) ----
    const float inv0 = 1.f / l_0;
    const float inv1 = 1.f / l_1;
    const int r0 = q0 + m0 + grp;
    const int r1 = r0 + 8;
#pragma unroll
    for (int nt = 0; nt < 8; nt++) {
        const int col = h * HD + nt * 8 + qid * 2;
        float2 u0, u1;
        u0.x = to_tf32(o[nt][0] * inv0); u0.y = to_tf32(o[nt][1] * inv0);
        u1.x = to_tf32(o[nt][2] * inv1); u1.y = to_tf32(o[nt][3] * inv1);
        *(float2*)(Og + (size_t)(b * TT + r0) * CC + col) = u0;
        *(float2*)(Og + (size_t)(b * TT + r1) * CC + col) = u1;
    }
}

// ---------------------------------------------------------------------------
extern "C" void kernel_launch(void* const* d_in, const int* in_sizes, int n_in,
                              void* d_out, int out_size)
{
    const float* x  = (const float*)d_in[0];
    // d_in[1] = mask (causal tril) — structural, not read
    const float* Wq = (const float*)d_in[2];
    const float* bq = (const float*)d_in[3];
    const float* Wk = (const float*)d_in[4];
    const float* bk = (const float*)d_in[5];
    const float* Wv = (const float*)d_in[6];
    const float* bv = (const float*)d_in[7];
    const float* Wo = (const float*)d_in[8];
    const float* bo = (const float*)d_in[9];
    float* out = (float*)d_out;

    float *Qp, *Kp, *Vp, *Op;
    cudaGetSymbolAddress((void**)&Qp, g_Q);
    cudaGetSymbolAddress((void**)&Kp, g_K);
    cudaGetSymbolAddress((void**)&Vp, g_V);
    cudaGetSymbolAddress((void**)&Op, g_O);

    const int smem_attn = SMF * sizeof(float);   // 143,360 B
    cudaFuncSetAttribute(attn_tc,
                         cudaFuncAttributeMaxDynamicSharedMemorySize, smem_attn);

    dim3 blk(256);
    cvt_pass<<<dim3(256, 5), blk>>>(x, Wq, Wk, Wv, Wo);
    gemm_qkv<<<dim3(24, MM / 128), blk>>>(bq, bk, bv);
    attn_tc<<<dim3(TT / 128, HQ, BB), blk, smem_attn>>>(Qp, Kp, Vp, Op);
    gemm_out<<<dim3(CC / 128, MM / 128), blk>>>(bo, out);
}

// round 10
// speedup vs baseline: 3.1639x; 1.0134x over previous
#include <cuda_runtime.h>
#include <stdint.h>

#define BB   2
#define TT   2048
#define CC   2048
#define HQ   32
#define HKV  8
#define HD   64
#define MM   (BB*TT)        // 4096
#define KVD  (HKV*HD)       // 512

// Scratch (no allocations allowed anywhere)
__device__ float g_Q[MM*CC];     // 32 MB
__device__ float g_K[MM*KVD];    // 8 MB  (tf32-rounded by projection epilogue)
__device__ float g_V[MM*KVD];    // 8 MB  (tf32-rounded by projection epilogue)
__device__ float g_O[MM*CC];     // 32 MB (tf32-rounded by attn epilogue)
__device__ float g_Xc[MM*CC];    // tf32-rounded x
__device__ float g_Wqc[CC*CC];
__device__ float g_Wkc[CC*KVD];
__device__ float g_Wvc[CC*KVD];
__device__ float g_Woc[CC*CC];

// ---------------------------------------------------------------------------
// helpers
// ---------------------------------------------------------------------------
__device__ __forceinline__ float to_tf32(float x) {
    float r;
    asm("cvt.rna.tf32.f32 %0, %1;" : "=f"(r) : "f"(x));
    return r;
}

__device__ __forceinline__ float fast_exp2(float x) {
    float r;
    asm("ex2.approx.ftz.f32 %0, %1;" : "=f"(r) : "f"(x));
    return r;
}

__device__ __forceinline__ void mma_tf32(float* d, const float* a, const float* b) {
    asm volatile(
        "mma.sync.aligned.m16n8k8.row.col.f32.tf32.tf32.f32 "
        "{%0,%1,%2,%3}, {%4,%5,%6,%7}, {%8,%9}, {%0,%1,%2,%3};"
        : "+f"(d[0]), "+f"(d[1]), "+f"(d[2]), "+f"(d[3])
        : "r"(__float_as_uint(a[0])), "r"(__float_as_uint(a[1])),
          "r"(__float_as_uint(a[2])), "r"(__float_as_uint(a[3])),
          "r"(__float_as_uint(b[0])), "r"(__float_as_uint(b[1])));
}

__device__ __forceinline__ void cp16(float* dst, const float* src) {
    unsigned d = (unsigned)__cvta_generic_to_shared(dst);
    asm volatile("cp.async.cg.shared.global [%0], [%1], 16;" :: "r"(d), "l"(src));
}
#define CP_COMMIT()  asm volatile("cp.async.commit_group;" ::: "memory")
#define CP_WAIT2()   asm volatile("cp.async.wait_group 2;"  ::: "memory")

// ---------------------------------------------------------------------------
// tf32 pre-rounding pass: x, Wq, Wk, Wv, Wo
// ---------------------------------------------------------------------------
__global__ __launch_bounds__(256) void cvt_pass(
    const float* __restrict__ x,  const float* __restrict__ wq,
    const float* __restrict__ wk, const float* __restrict__ wv,
    const float* __restrict__ wo)
{
    const float* src; float* dst; int n4;
    switch (blockIdx.y) {
        case 0:  src = x;  dst = g_Xc;  n4 = MM * CC / 4;  break;
        case 1:  src = wq; dst = g_Wqc; n4 = CC * CC / 4;  break;
        case 2:  src = wk; dst = g_Wkc; n4 = CC * KVD / 4; break;
        case 3:  src = wv; dst = g_Wvc; n4 = CC * KVD / 4; break;
        default: src = wo; dst = g_Woc; n4 = CC * CC / 4;  break;
    }
    for (int i = blockIdx.x * blockDim.x + threadIdx.x; i < n4;
         i += gridDim.x * blockDim.x) {
        float4 v = ((const float4*)src)[i];
        v.x = to_tf32(v.x); v.y = to_tf32(v.y);
        v.z = to_tf32(v.z); v.w = to_tf32(v.w);
        ((float4*)dst)[i] = v;
    }
}

// ---------------------------------------------------------------------------
// GEMM body (inputs pre-rounded tf32): C = A @ W + bias
// 128x128x16 tile, 256 thr, 4-stage cp.async pipeline, 1 sync/iter.
// A staged [m][20]; B staged [k][136].
// ---------------------------------------------------------------------------
#define SSTA 20
#define SSTB 136
#define GSTG 4
#define GEMM_SMEM_FLOATS (GSTG * (128*SSTA + 16*SSTB))   // 18,944
#define GEMM_SMEM_BYTES  (GEMM_SMEM_FLOATS * 4)          // 75,776

__device__ __forceinline__ void gemm_body(
    const float* __restrict__ A, const float* __restrict__ W,
    const float* __restrict__ bias, float* __restrict__ Co,
    int Nd, int Kd, int row0, int col0, bool roundOut, float* smem)
{
    float* AsB = smem;                       // [GSTG][128][SSTA]
    float* BsB = smem + GSTG * 128 * SSTA;   // [GSTG][16][SSTB]

    const int tid  = threadIdx.x;
    const int lane = tid & 31;
    const int warp = tid >> 5;
    const int wm   = (warp & 1) * 64;
    const int wn   = (warp >> 1) * 32;

    // cp.async loader mappings
    const int aRow = tid >> 1;            // 0..127
    const int aK   = (tid & 1) * 8;       // 0 or 8
    const int bK   = tid >> 5;            // 0..7
    const int bC   = (tid & 31) * 4;      // 0..124

    const int grp = lane >> 2;
    const int qid = lane & 3;

    float acc[4][4][4];
#pragma unroll
    for (int i = 0; i < 4; i++)
#pragma unroll
        for (int j = 0; j < 4; j++)
#pragma unroll
            for (int r = 0; r < 4; r++) acc[i][j][r] = 0.f;

    const int niter = Kd / 16;

    // prologue: issue stages 0..2
#pragma unroll
    for (int s = 0; s < GSTG - 1; s++) {
        const int k0 = s * 16;
        float* Ad = AsB + s * 128 * SSTA;
        float* Bd = BsB + s * 16 * SSTB;
        cp16(Ad + aRow * SSTA + aK,     A + (size_t)(row0 + aRow) * Kd + k0 + aK);
        cp16(Ad + aRow * SSTA + aK + 4, A + (size_t)(row0 + aRow) * Kd + k0 + aK + 4);
        cp16(Bd + bK * SSTB + bC,       W + (size_t)(k0 + bK) * Nd + col0 + bC);
        cp16(Bd + (bK + 8) * SSTB + bC, W + (size_t)(k0 + bK + 8) * Nd + col0 + bC);
        CP_COMMIT();
    }

    for (int it = 0; it < niter; it++) {
        CP_WAIT2();
        __syncthreads();
        const float* Ac = AsB + (it & 3) * 128 * SSTA;
        const float* Bc = BsB + (it & 3) * 16 * SSTB;

#pragma unroll
        for (int kk = 0; kk < 16; kk += 8) {
            const int c = kk + qid;
            float a[4][4];
#pragma unroll
            for (int mt = 0; mt < 4; mt++) {
                const int r = wm + mt * 16 + grp;
                a[mt][0] = Ac[r * SSTA + c];
                a[mt][1] = Ac[(r + 8) * SSTA + c];
                a[mt][2] = Ac[r * SSTA + c + 4];
                a[mt][3] = Ac[(r + 8) * SSTA + c + 4];
            }
            float b[4][2];
#pragma unroll
            for (int nt = 0; nt < 4; nt++) {
                const int n = wn + nt * 8 + grp;
                b[nt][0] = Bc[c * SSTB + n];
                b[nt][1] = Bc[(c + 4) * SSTB + n];
            }
#pragma unroll
            for (int mt = 0; mt < 4; mt++)
#pragma unroll
                for (int nt = 0; nt < 4; nt++)
                    mma_tf32(acc[mt][nt], a[mt], b[nt]);
        }

        if (it + GSTG - 1 < niter) {
            const int k0 = (it + GSTG - 1) * 16;
            const int s  = (it + GSTG - 1) & 3;
            float* Ad = AsB + s * 128 * SSTA;
            float* Bd = BsB + s * 16 * SSTB;
            cp16(Ad + aRow * SSTA + aK,     A + (size_t)(row0 + aRow) * Kd + k0 + aK);
            cp16(Ad + aRow * SSTA + aK + 4, A + (size_t)(row0 + aRow) * Kd + k0 + aK + 4);
            cp16(Bd + bK * SSTB + bC,       W + (size_t)(k0 + bK) * Nd + col0 + bC);
            cp16(Bd + (bK + 8) * SSTB + bC, W + (size_t)(k0 + bK + 8) * Nd + col0 + bC);
        }
        CP_COMMIT();
    }

#pragma unroll
    for (int mt = 0; mt < 4; mt++) {
#pragma unroll
        for (int nt = 0; nt < 4; nt++) {
            const int r  = row0 + wm + mt * 16 + grp;
            const int c  = col0 + wn + nt * 8 + qid * 2;
            float2 o0, o1;
            o0.x = acc[mt][nt][0] + bias[c];
            o0.y = acc[mt][nt][1] + bias[c + 1];
            o1.x = acc[mt][nt][2] + bias[c];
            o1.y = acc[mt][nt][3] + bias[c + 1];
            if (roundOut) {
                o0.x = to_tf32(o0.x); o0.y = to_tf32(o0.y);
                o1.x = to_tf32(o1.x); o1.y = to_tf32(o1.y);
            }
            *(float2*)(Co + (size_t)r * Nd + c)       = o0;
            *(float2*)(Co + (size_t)(r + 8) * Nd + c) = o1;
        }
    }
}

// Fused Q+K+V projection. grid.x = 24: [0,16) Q, [16,20) K, [20,24) V.
// K/V outputs rna-rounded to tf32 (consumed as raw-truncated by attn mma).
__global__ __launch_bounds__(256, 2) void gemm_qkv(
    const float* __restrict__ bq, const float* __restrict__ bk,
    const float* __restrict__ bv)
{
    extern __shared__ float smem[];
    const int bx = blockIdx.x;
    if (bx < 16)
        gemm_body(g_Xc, g_Wqc, bq, g_Q, CC,  CC, blockIdx.y * 128, bx * 128, false, smem);
    else if (bx < 20)
        gemm_body(g_Xc, g_Wkc, bk, g_K, KVD, CC, blockIdx.y * 128, (bx - 16) * 128, true, smem);
    else
        gemm_body(g_Xc, g_Wvc, bv, g_V, KVD, CC, blockIdx.y * 128, (bx - 20) * 128, true, smem);
}

__global__ __launch_bounds__(256, 2) void gemm_out(
    const float* __restrict__ bo, float* __restrict__ out)
{
    extern __shared__ float smem[];
    gemm_body(g_O, g_Woc, bo, out, CC, CC, blockIdx.y * 128, blockIdx.x * 128, false, smem);
}

// ---------------------------------------------------------------------------
// Tensor-core flash attention (tf32, Q split hi/lo in registers, causal, GQA).
// CTA = (128 q-rows, h, b); 8 warps, warp owns 16 q-rows.
// Permuted-k smem layouts (pairs (c,c+4) adjacent) -> all fragment loads are
// conflict-free LDS.64. K: [tok][88]; V^T: [d][88]; P: [row][88].
// Double-buffered K/V, register prefetch, 1 syncthreads/tile.
// ---------------------------------------------------------------------------
#define KVP  88                                 // permuted stride (LDS.64 conflict-free)
#define ATS  136                                // Q staging stride (prologue only)
#define SM_PHI  (128*KVP)                       // 11264 floats
#define SM_BUF  (2*64*KVP)                      // 11264 floats (K + V^T)
#define SMF  (SM_PHI + 2*SM_BUF)                // 33792 floats = 135,168 B
#define SCALE 0.18033688011112042f              // log2(e)/sqrt(64)

__global__ __launch_bounds__(256, 1) void attn_tc(
    const float* __restrict__ Qg, const float* __restrict__ Kg,
    const float* __restrict__ Vg, float* __restrict__ Og)
{
    extern __shared__ float sm[];
    float* Qhi = sm;                  // prologue only (aliases Phi + KV0 head)
    float* Qlo = sm + 64 * ATS;       // prologue only
    float* Phi = sm;                  // [128][KVP], k-permuted

    const int tid  = threadIdx.x;
    const int lane = tid & 31;
    const int warp = tid >> 5;
    const int grp  = lane >> 2;
    const int qid  = lane & 3;
    const int q0   = (gridDim.x - 1 - blockIdx.x) * 128;   // long CTAs first
    const int h    = blockIdx.y;
    const int b    = blockIdx.z;
    const int hkv  = h >> 2;
    const int m0   = warp * 16;

    // K loader: tok = tid>>4 (+16/chunk), d = (tid&15)*4
    const int kTok = tid >> 4;
    const int kD   = (tid & 15) * 4;
    const int kPB  = ((kD >> 3) << 3) + ((kD >> 2) & 1);   // permuted base for kD..kD+3 (stride 2)
    // V loader (transposed store): tok = tid&15 (+16/chunk), d = (tid>>4)*4
    const int vTok = tid & 15;
    const int vD   = (tid >> 4) * 4;

    const int ntile     = (q0 >> 6) + 2;
    const int maskstart = q0 >> 6;

    // ---- issue KV tile-0 global loads early ----
    float4 kreg[4], vreg[4];
#pragma unroll
    for (int i = 0; i < 4; i++) {
        kreg[i] = *(const float4*)(Kg + (size_t)(b * TT + kTok + i * 16) * KVD + hkv * HD + kD);
        vreg[i] = *(const float4*)(Vg + (size_t)(b * TT + vTok + i * 16) * KVD + hkv * HD + vD);
    }

    // ---- stage Q (128 x 64) split hi/lo, layout [d][m] ----
#pragma unroll
    for (int i = 0; i < 8; i++) {
        const int idx = tid + i * 256;
        const int row = idx >> 4;
        const int d0  = (idx & 15) * 4;
        float4 v = *(const float4*)(Qg + (size_t)(b * TT + q0 + row) * CC + h * HD + d0);
        float q[4] = {v.x, v.y, v.z, v.w};
#pragma unroll
        for (int j = 0; j < 4; j++) {
            const float hi = to_tf32(q[j]);
            Qhi[(d0 + j) * ATS + row] = hi;
            Qlo[(d0 + j) * ATS + row] = to_tf32(q[j] - hi);
        }
    }
    __syncthreads();

    // ---- hoist Q fragments into registers (loop-invariant) ----
    float qh[8][4], ql[8][4];
#pragma unroll
    for (int kk = 0; kk < 8; kk++) {
        const int c = kk * 8 + qid;
        qh[kk][0] = Qhi[c * ATS + m0 + grp];
        qh[kk][1] = Qhi[c * ATS + m0 + grp + 8];
        qh[kk][2] = Qhi[(c + 4) * ATS + m0 + grp];
        qh[kk][3] = Qhi[(c + 4) * ATS + m0 + grp + 8];
        ql[kk][0] = Qlo[c * ATS + m0 + grp];
        ql[kk][1] = Qlo[c * ATS + m0 + grp + 8];
        ql[kk][2] = Qlo[(c + 4) * ATS + m0 + grp];
        ql[kk][3] = Qlo[(c + 4) * ATS + m0 + grp + 8];
    }
    __syncthreads();   // all warps done reading staging before KV0 overwrites it

    // ---- store KV tile 0 into buffer 0 (permuted layouts) ----
    {
        float* K0 = sm + SM_PHI;
        float* V0 = K0 + 64 * KVP;
#pragma unroll
        for (int i = 0; i < 4; i++) {
            const int ktok = kTok + i * 16;
            K0[ktok * KVP + kPB + 0] = kreg[i].x;
            K0[ktok * KVP + kPB + 2] = kreg[i].y;
            K0[ktok * KVP + kPB + 4] = kreg[i].z;
            K0[ktok * KVP + kPB + 6] = kreg[i].w;
            const int vt = vTok + i * 16;
            const int pt = ((vt >> 3) << 3) + ((vt & 3) << 1) + ((vt >> 2) & 1);
            V0[(vD + 0) * KVP + pt] = vreg[i].x;
            V0[(vD + 1) * KVP + pt] = vreg[i].y;
            V0[(vD + 2) * KVP + pt] = vreg[i].z;
            V0[(vD + 3) * KVP + pt] = vreg[i].w;
        }
    }
    __syncthreads();

    float m_0 = -1e30f, m_1 = -1e30f, l_0 = 0.f, l_1 = 0.f;
    float o[8][4];
#pragma unroll
    for (int nt = 0; nt < 8; nt++)
#pragma unroll
        for (int e = 0; e < 4; e++) o[nt][e] = 0.f;

    for (int jt = 0; jt < ntile; jt++) {
        float* Ks = sm + SM_PHI + (jt & 1) * SM_BUF;
        float* Vt = Ks + 64 * KVP;
        const bool more = (jt + 1 < ntile);

        if (more) {
            const int k0n = (jt + 1) * 64;
#pragma unroll
            for (int i = 0; i < 4; i++)
                kreg[i] = *(const float4*)(Kg + (size_t)(b * TT + k0n + kTok + i * 16) * KVD + hkv * HD + kD);
        }

        // ---- S = Q K^T (split Q: 2 mmas per fragment; B frags via LDS.64) ----
        float s[8][4];
#pragma unroll
        for (int nt = 0; nt < 8; nt++)
#pragma unroll
            for (int e = 0; e < 4; e++) s[nt][e] = 0.f;

#pragma unroll
        for (int kk = 0; kk < 8; kk++) {
            const int p = kk * 8 + qid * 2;
#pragma unroll
            for (int nt = 0; nt < 8; nt++) {
                const int n = nt * 8 + grp;
                float2 kb = *(const float2*)(Ks + n * KVP + p);
                float bb[2] = { kb.x, kb.y };
                mma_tf32(s[nt], qh[kk], bb);
                mma_tf32(s[nt], ql[kk], bb);
            }
        }

        if (more) {
            const int k0n = (jt + 1) * 64;
#pragma unroll
            for (int i = 0; i < 4; i++)
                vreg[i] = *(const float4*)(Vg + (size_t)(b * TT + k0n + vTok + i * 16) * KVD + hkv * HD + vD);
        }

        // ---- scale (log2 domain) + causal mask ----
#pragma unroll
        for (int nt = 0; nt < 8; nt++)
#pragma unroll
            for (int e = 0; e < 4; e++) s[nt][e] *= SCALE;
        if (jt >= maskstart) {
            const int k0 = jt * 64;
#pragma unroll
            for (int nt = 0; nt < 8; nt++)
#pragma unroll
                for (int e = 0; e < 4; e++) {
                    const int row = m0 + grp + ((e >> 1) * 8);
                    const int col = nt * 8 + qid * 2 + (e & 1);
                    if (k0 + col > q0 + row) s[nt][e] = -1e30f;
                }
        }

        // ---- register online softmax ----
        float mx0 = -1e30f, mx1 = -1e30f;
#pragma unroll
        for (int nt = 0; nt < 8; nt++) {
            mx0 = fmaxf(mx0, fmaxf(s[nt][0], s[nt][1]));
            mx1 = fmaxf(mx1, fmaxf(s[nt][2], s[nt][3]));
        }
        mx0 = fmaxf(mx0, __shfl_xor_sync(0xffffffffu, mx0, 1));
        mx0 = fmaxf(mx0, __shfl_xor_sync(0xffffffffu, mx0, 2));
        mx1 = fmaxf(mx1, __shfl_xor_sync(0xffffffffu, mx1, 1));
        mx1 = fmaxf(mx1, __shfl_xor_sync(0xffffffffu, mx1, 2));

        const float mn0 = fmaxf(m_0, mx0);
        const float mn1 = fmaxf(m_1, mx1);
        const float a0  = fast_exp2(m_0 - mn0);
        const float a1  = fast_exp2(m_1 - mn1);
        m_0 = mn0; m_1 = mn1;

        float ps0 = 0.f, ps1 = 0.f;
#pragma unroll
        for (int nt = 0; nt < 8; nt++) {
#pragma unroll
            for (int e = 0; e < 2; e++) {
                const float p = fast_exp2(s[nt][e] - mn0);
                ps0 += p;
                const int v = qid * 2 + e;
                const int posv = ((v & 3) << 1) + (v >> 2);
                Phi[(m0 + grp) * KVP + nt * 8 + posv] = to_tf32(p);
            }
#pragma unroll
            for (int e = 2; e < 4; e++) {
                const float p = fast_exp2(s[nt][e] - mn1);
                ps1 += p;
                const int v = qid * 2 + (e & 1);
                const int posv = ((v & 3) << 1) + (v >> 2);
                Phi[(m0 + grp + 8) * KVP + nt * 8 + posv] = to_tf32(p);
            }
        }
        ps0 += __shfl_xor_sync(0xffffffffu, ps0, 1);
        ps0 += __shfl_xor_sync(0xffffffffu, ps0, 2);
        ps1 += __shfl_xor_sync(0xffffffffu, ps1, 1);
        ps1 += __shfl_xor_sync(0xffffffffu, ps1, 2);
        l_0 = l_0 * a0 + ps0;
        l_1 = l_1 * a1 + ps1;
        __syncwarp();   // own-warp P stores -> own-warp fragment loads

        // ---- rescale O, then O += P V (A and B frags via LDS.64) ----
#pragma unroll
        for (int nt = 0; nt < 8; nt++) {
            o[nt][0] *= a0; o[nt][1] *= a0;
            o[nt][2] *= a1; o[nt][3] *= a1;
        }
#pragma unroll
        for (int kk = 0; kk < 8; kk++) {
            const int p = kk * 8 + qid * 2;
            float2 f0 = *(const float2*)(Phi + (m0 + grp) * KVP + p);
            float2 f1 = *(const float2*)(Phi + (m0 + grp + 8) * KVP + p);
            float ah[4] = { f0.x, f1.x, f0.y, f1.y };
#pragma unroll
            for (int nt = 0; nt < 8; nt++) {
                const int n = nt * 8 + grp;
                float2 vb = *(const float2*)(Vt + n * KVP + p);
                float bb[2] = { vb.x, vb.y };
                mma_tf32(o[nt], ah, bb);
            }
        }

        // ---- store prefetched tile into alternate buffer ----
        if (more) {
            float* Kn = sm + SM_PHI + ((jt + 1) & 1) * SM_BUF;
            float* Vn = Kn + 64 * KVP;
#pragma unroll
            for (int i = 0; i < 4; i++) {
                const int ktok = kTok + i * 16;
                Kn[ktok * KVP + kPB + 0] = kreg[i].x;
                Kn[ktok * KVP + kPB + 2] = kreg[i].y;
                Kn[ktok * KVP + kPB + 4] = kreg[i].z;
                Kn[ktok * KVP + kPB + 6] = kreg[i].w;
                const int vt = vTok + i * 16;
                const int pt = ((vt >> 3) << 3) + ((vt & 3) << 1) + ((vt >> 2) & 1);
                Vn[(vD + 0) * KVP + pt] = vreg[i].x;
                Vn[(vD + 1) * KVP + pt] = vreg[i].y;
                Vn[(vD + 2) * KVP + pt] = vreg[i].z;
                Vn[(vD + 3) * KVP + pt] = vreg[i].w;
            }
        }
        __syncthreads();
    }

    // ---- epilogue: tf32-rounded O/l -> g_O (pre-rounded for out-proj) ----
    const float inv0 = 1.f / l_0;
    const float inv1 = 1.f / l_1;
    const int r0 = q0 + m0 + grp;
    const int r1 = r0 + 8;
#pragma unroll
    for (int nt = 0; nt < 8; nt++) {
        const int col = h * HD + nt * 8 + qid * 2;
        float2 u0, u1;
        u0.x = to_tf32(o[nt][0] * inv0); u0.y = to_tf32(o[nt][1] * inv0);
        u1.x = to_tf32(o[nt][2] * inv1); u1.y = to_tf32(o[nt][3] * inv1);
        *(float2*)(Og + (size_t)(b * TT + r0) * CC + col) = u0;
        *(float2*)(Og + (size_t)(b * TT + r1) * CC + col) = u1;
    }
}

// ---------------------------------------------------------------------------
extern "C" void kernel_launch(void* const* d_in, const int* in_sizes, int n_in,
                              void* d_out, int out_size)
{
    const float* x  = (const float*)d_in[0];
    // d_in[1] = mask (causal tril) — structural, not read
    const float* Wq = (const float*)d_in[2];
    const float* bq = (const float*)d_in[3];
    const float* Wk = (const float*)d_in[4];
    const float* bk = (const float*)d_in[5];
    const float* Wv = (const float*)d_in[6];
    const float* bv = (const float*)d_in[7];
    const float* Wo = (const float*)d_in[8];
    const float* bo = (const float*)d_in[9];
    float* out = (float*)d_out;

    float *Qp, *Kp, *Vp, *Op;
    cudaGetSymbolAddress((void**)&Qp, g_Q);
    cudaGetSymbolAddress((void**)&Kp, g_K);
    cudaGetSymbolAddress((void**)&Vp, g_V);
    cudaGetSymbolAddress((void**)&Op, g_O);

    const int smem_attn = SMF * sizeof(float);       // 135,168 B
    cudaFuncSetAttribute(attn_tc,
                         cudaFuncAttributeMaxDynamicSharedMemorySize, smem_attn);
    cudaFuncSetAttribute(gemm_qkv,
                         cudaFuncAttributeMaxDynamicSharedMemorySize, GEMM_SMEM_BYTES);
    cudaFuncSetAttribute(gemm_out,
                         cudaFuncAttributeMaxDynamicSharedMemorySize, GEMM_SMEM_BYTES);

    dim3 blk(256);
    cvt_pass<<<dim3(256, 5), blk>>>(x, Wq, Wk, Wv, Wo);
    gemm_qkv<<<dim3(24, MM / 128), blk, GEMM_SMEM_BYTES>>>(bq, bk, bv);
    attn_tc<<<dim3(TT / 128, HQ, BB), blk, smem_attn>>>(Qp, Kp, Vp, Op);
    gemm_out<<<dim3(CC / 128, MM / 128), blk, GEMM_SMEM_BYTES>>>(bo, out);
}

// round 11
// speedup vs baseline: 3.2106x; 1.0148x over previous
#include <cuda_runtime.h>
#include <stdint.h>

#define BB   2
#define TT   2048
#define CC   2048
#define HQ   32
#define HKV  8
#define HD   64
#define MM   (BB*TT)        // 4096
#define KVD  (HKV*HD)       // 512

// Scratch (no allocations allowed anywhere)
__device__ float g_Q[MM*CC];     // 32 MB
__device__ float g_K[MM*KVD];    // 8 MB  (tf32-rounded)
__device__ float g_V[MM*KVD];    // 8 MB  (tf32-rounded)
__device__ float g_O[MM*CC];     // 32 MB (tf32-rounded, k-PERMUTED layout)
__device__ float g_Xc[MM*CC];    // tf32-rounded x, k-PERMUTED layout
__device__ float g_Wqc[CC*CC];
__device__ float g_Wkc[CC*KVD];
__device__ float g_Wvc[CC*KVD];
__device__ float g_Woc[CC*CC];

// ---------------------------------------------------------------------------
// helpers
// ---------------------------------------------------------------------------
__device__ __forceinline__ float to_tf32(float x) {
    float r;
    asm("cvt.rna.tf32.f32 %0, %1;" : "=f"(r) : "f"(x));
    return r;
}

__device__ __forceinline__ float fast_exp2(float x) {
    float r;
    asm("ex2.approx.ftz.f32 %0, %1;" : "=f"(r) : "f"(x));
    return r;
}

// within-16 k-permutation: pos(k) = (k&3)*4 + (k>>2)
__device__ __forceinline__ int kperm(int c16) {
    return ((c16 & 3) << 2) + (c16 >> 2);
}

__device__ __forceinline__ void mma_tf32(float* d, const float* a, const float* b) {
    asm volatile(
        "mma.sync.aligned.m16n8k8.row.col.f32.tf32.tf32.f32 "
        "{%0,%1,%2,%3}, {%4,%5,%6,%7}, {%8,%9}, {%0,%1,%2,%3};"
        : "+f"(d[0]), "+f"(d[1]), "+f"(d[2]), "+f"(d[3])
        : "r"(__float_as_uint(a[0])), "r"(__float_as_uint(a[1])),
          "r"(__float_as_uint(a[2])), "r"(__float_as_uint(a[3])),
          "r"(__float_as_uint(b[0])), "r"(__float_as_uint(b[1])));
}

__device__ __forceinline__ void cp16(float* dst, const float* src) {
    unsigned d = (unsigned)__cvta_generic_to_shared(dst);
    asm volatile("cp.async.cg.shared.global [%0], [%1], 16;" :: "r"(d), "l"(src));
}
#define CP_COMMIT()  asm volatile("cp.async.commit_group;" ::: "memory")
#define CP_WAIT3()   asm volatile("cp.async.wait_group 3;"  ::: "memory")

// ---------------------------------------------------------------------------
// tf32 pre-rounding pass. y==0: x -> g_Xc with within-16 k-permutation
// (4x4 transpose of each 16-float block). y>=1: plain rounding W copies.
// ---------------------------------------------------------------------------
__global__ __launch_bounds__(256) void cvt_pass(
    const float* __restrict__ x,  const float* __restrict__ wq,
    const float* __restrict__ wk, const float* __restrict__ wv,
    const float* __restrict__ wo)
{
    const int gtid = blockIdx.x * blockDim.x + threadIdx.x;
    const int gstr = gridDim.x * blockDim.x;
    if (blockIdx.y == 0) {
        const int nblk = MM * CC / 16;
        for (int i = gtid; i < nblk; i += gstr) {
            const float4* src = (const float4*)x + (size_t)i * 4;
            float4 v0 = src[0], v1 = src[1], v2 = src[2], v3 = src[3];
            float4* dst = (float4*)g_Xc + (size_t)i * 4;
            float4 o;
            o.x = to_tf32(v0.x); o.y = to_tf32(v1.x); o.z = to_tf32(v2.x); o.w = to_tf32(v3.x);
            dst[0] = o;
            o.x = to_tf32(v0.y); o.y = to_tf32(v1.y); o.z = to_tf32(v2.y); o.w = to_tf32(v3.y);
            dst[1] = o;
            o.x = to_tf32(v0.z); o.y = to_tf32(v1.z); o.z = to_tf32(v2.z); o.w = to_tf32(v3.z);
            dst[2] = o;
            o.x = to_tf32(v0.w); o.y = to_tf32(v1.w); o.z = to_tf32(v2.w); o.w = to_tf32(v3.w);
            dst[3] = o;
        }
        return;
    }
    const float* src; float* dst; int n4;
    switch (blockIdx.y) {
        case 1:  src = wq; dst = g_Wqc; n4 = CC * CC / 4;  break;
        case 2:  src = wk; dst = g_Wkc; n4 = CC * KVD / 4; break;
        case 3:  src = wv; dst = g_Wvc; n4 = CC * KVD / 4; break;
        default: src = wo; dst = g_Woc; n4 = CC * CC / 4;  break;
    }
    for (int i = gtid; i < n4; i += gstr) {
        float4 v = ((const float4*)src)[i];
        v.x = to_tf32(v.x); v.y = to_tf32(v.y);
        v.z = to_tf32(v.z); v.w = to_tf32(v.w);
        ((float4*)dst)[i] = v;
    }
}

// ---------------------------------------------------------------------------
// GEMM body: C = A @ W + bias.  A is k-PERMUTED (pos = (k&3)*4 + k>>2).
// 128x128x16 tile, 256 thr, 5-stage cp.async, A frags via LDS.128.
// ---------------------------------------------------------------------------
#define SSTB 136
#define GSTG 5
#define ASTG (128*16)                                    // 2048 floats / stage
#define BSTG (16*SSTB)                                   // 2176 floats / stage
#define GEMM_SMEM_FLOATS (GSTG * (ASTG + BSTG))          // 21,120
#define GEMM_SMEM_BYTES  (GEMM_SMEM_FLOATS * 4)          // 84,480

__device__ __forceinline__ void gemm_body(
    const float* __restrict__ A, const float* __restrict__ W,
    const float* __restrict__ bias, float* __restrict__ Co,
    int Nd, int Kd, int row0, int col0, bool roundOut, float* smem)
{
    float* AsB = smem;                   // [GSTG][128][16]
    float* BsB = smem + GSTG * ASTG;     // [GSTG][16][SSTB]

    const int tid  = threadIdx.x;
    const int lane = tid & 31;
    const int warp = tid >> 5;
    const int wm   = (warp & 1) * 64;
    const int wn   = (warp >> 1) * 32;

    // loader mappings
    const int aRow = tid >> 1;            // 0..127
    const int aOff = (tid & 1) * 8;       // 0 or 8
    const int bK   = tid >> 5;            // 0..7
    const int bC   = (tid & 31) * 4;      // 0..124

    const int grp = lane >> 2;
    const int qid = lane & 3;

    float acc[4][4][4];
#pragma unroll
    for (int i = 0; i < 4; i++)
#pragma unroll
        for (int j = 0; j < 4; j++)
#pragma unroll
            for (int r = 0; r < 4; r++) acc[i][j][r] = 0.f;

    const int niter = Kd / 16;

    // prologue: issue stages 0..3
#pragma unroll
    for (int s = 0; s < GSTG - 1; s++) {
        const int k0 = s * 16;
        float* Ad = AsB + s * ASTG;
        float* Bd = BsB + s * BSTG;
        cp16(Ad + aRow * 16 + aOff,      A + (size_t)(row0 + aRow) * Kd + k0 + aOff);
        cp16(Ad + aRow * 16 + aOff + 4,  A + (size_t)(row0 + aRow) * Kd + k0 + aOff + 4);
        cp16(Bd + bK * SSTB + bC,        W + (size_t)(k0 + bK) * Nd + col0 + bC);
        cp16(Bd + (bK + 8) * SSTB + bC,  W + (size_t)(k0 + bK + 8) * Nd + col0 + bC);
        CP_COMMIT();
    }

    int cs = 0, ss = GSTG - 1;
    for (int it = 0; it < niter; it++) {
        CP_WAIT3();
        __syncthreads();
        const float* Ac = AsB + cs * ASTG;
        const float* Bc = BsB + cs * BSTG;

        // A fragments for BOTH kk-halves: 8 x LDS.128
        float4 A0[4], A1[4];
#pragma unroll
        for (int mt = 0; mt < 4; mt++) {
            const int r = wm + mt * 16 + grp;
            A0[mt] = *(const float4*)(Ac + r * 16 + 4 * qid);
            A1[mt] = *(const float4*)(Ac + (r + 8) * 16 + 4 * qid);
        }

#pragma unroll
        for (int half = 0; half < 2; half++) {
            const int c = half * 8 + qid;
            float b[4][2];
#pragma unroll
            for (int nt = 0; nt < 4; nt++) {
                const int n = wn + nt * 8 + grp;
                b[nt][0] = Bc[c * SSTB + n];
                b[nt][1] = Bc[(c + 4) * SSTB + n];
            }
#pragma unroll
            for (int mt = 0; mt < 4; mt++) {
                float a[4];
                if (half == 0) {
                    a[0] = A0[mt].x; a[1] = A1[mt].x; a[2] = A0[mt].y; a[3] = A1[mt].y;
                } else {
                    a[0] = A0[mt].z; a[1] = A1[mt].z; a[2] = A0[mt].w; a[3] = A1[mt].w;
                }
#pragma unroll
                for (int nt = 0; nt < 4; nt++)
                    mma_tf32(acc[mt][nt], a, b[nt]);
            }
        }

        if (it + GSTG - 1 < niter) {
            const int k0 = (it + GSTG - 1) * 16;
            float* Ad = AsB + ss * ASTG;
            float* Bd = BsB + ss * BSTG;
            cp16(Ad + aRow * 16 + aOff,      A + (size_t)(row0 + aRow) * Kd + k0 + aOff);
            cp16(Ad + aRow * 16 + aOff + 4,  A + (size_t)(row0 + aRow) * Kd + k0 + aOff + 4);
            cp16(Bd + bK * SSTB + bC,        W + (size_t)(k0 + bK) * Nd + col0 + bC);
            cp16(Bd + (bK + 8) * SSTB + bC,  W + (size_t)(k0 + bK + 8) * Nd + col0 + bC);
        }
        CP_COMMIT();
        cs = (cs + 1 == GSTG) ? 0 : cs + 1;
        ss = (ss + 1 == GSTG) ? 0 : ss + 1;
    }

#pragma unroll
    for (int mt = 0; mt < 4; mt++) {
#pragma unroll
        for (int nt = 0; nt < 4; nt++) {
            const int r  = row0 + wm + mt * 16 + grp;
            const int c  = col0 + wn + nt * 8 + qid * 2;
            float2 o0, o1;
            o0.x = acc[mt][nt][0] + bias[c];
            o0.y = acc[mt][nt][1] + bias[c + 1];
            o1.x = acc[mt][nt][2] + bias[c];
            o1.y = acc[mt][nt][3] + bias[c + 1];
            if (roundOut) {
                o0.x = to_tf32(o0.x); o0.y = to_tf32(o0.y);
                o1.x = to_tf32(o1.x); o1.y = to_tf32(o1.y);
            }
            *(float2*)(Co + (size_t)r * Nd + c)       = o0;
            *(float2*)(Co + (size_t)(r + 8) * Nd + c) = o1;
        }
    }
}

// Fused Q+K+V projection. grid.x = 24: [0,16) Q, [16,20) K, [20,24) V.
__global__ __launch_bounds__(256, 2) void gemm_qkv(
    const float* __restrict__ bq, const float* __restrict__ bk,
    const float* __restrict__ bv)
{
    extern __shared__ float smem[];
    const int bx = blockIdx.x;
    if (bx < 16)
        gemm_body(g_Xc, g_Wqc, bq, g_Q, CC,  CC, blockIdx.y * 128, bx * 128, false, smem);
    else if (bx < 20)
        gemm_body(g_Xc, g_Wkc, bk, g_K, KVD, CC, blockIdx.y * 128, (bx - 16) * 128, true, smem);
    else
        gemm_body(g_Xc, g_Wvc, bv, g_V, KVD, CC, blockIdx.y * 128, (bx - 20) * 128, true, smem);
}

__global__ __launch_bounds__(256, 2) void gemm_out(
    const float* __restrict__ bo, float* __restrict__ out)
{
    extern __shared__ float smem[];
    gemm_body(g_O, g_Woc, bo, out, CC, CC, blockIdx.y * 128, blockIdx.x * 128, false, smem);
}

// ---------------------------------------------------------------------------
// Tensor-core flash attention (tf32, Q split hi/lo in registers, causal, GQA).
// Unchanged from R10 except epilogue writes g_O in k-PERMUTED layout.
// ---------------------------------------------------------------------------
#define KVP  88
#define ATS  136
#define SM_PHI  (128*KVP)
#define SM_BUF  (2*64*KVP)
#define SMF  (SM_PHI + 2*SM_BUF)               // 33792 floats = 135,168 B
#define SCALE 0.18033688011112042f             // log2(e)/sqrt(64)

__global__ __launch_bounds__(256, 1) void attn_tc(
    const float* __restrict__ Qg, const float* __restrict__ Kg,
    const float* __restrict__ Vg, float* __restrict__ Og)
{
    extern __shared__ float sm[];
    float* Qhi = sm;
    float* Qlo = sm + 64 * ATS;
    float* Phi = sm;                  // aliases staging after prologue

    const int tid  = threadIdx.x;
    const int lane = tid & 31;
    const int warp = tid >> 5;
    const int grp  = lane >> 2;
    const int qid  = lane & 3;
    const int q0   = (gridDim.x - 1 - blockIdx.x) * 128;
    const int h    = blockIdx.y;
    const int b    = blockIdx.z;
    const int hkv  = h >> 2;
    const int m0   = warp * 16;

    const int kTok = tid >> 4;
    const int kD   = (tid & 15) * 4;
    const int kPB  = ((kD >> 3) << 3) + ((kD >> 2) & 1);
    const int vTok = tid & 15;
    const int vD   = (tid >> 4) * 4;

    const int ntile     = (q0 >> 6) + 2;
    const int maskstart = q0 >> 6;

    float4 kreg[4], vreg[4];
#pragma unroll
    for (int i = 0; i < 4; i++) {
        kreg[i] = *(const float4*)(Kg + (size_t)(b * TT + kTok + i * 16) * KVD + hkv * HD + kD);
        vreg[i] = *(const float4*)(Vg + (size_t)(b * TT + vTok + i * 16) * KVD + hkv * HD + vD);
    }

#pragma unroll
    for (int i = 0; i < 8; i++) {
        const int idx = tid + i * 256;
        const int row = idx >> 4;
        const int d0  = (idx & 15) * 4;
        float4 v = *(const float4*)(Qg + (size_t)(b * TT + q0 + row) * CC + h * HD + d0);
        float q[4] = {v.x, v.y, v.z, v.w};
#pragma unroll
        for (int j = 0; j < 4; j++) {
            const float hi = to_tf32(q[j]);
            Qhi[(d0 + j) * ATS + row] = hi;
            Qlo[(d0 + j) * ATS + row] = to_tf32(q[j] - hi);
        }
    }
    __syncthreads();

    float qh[8][4], ql[8][4];
#pragma unroll
    for (int kk = 0; kk < 8; kk++) {
        const int c = kk * 8 + qid;
        qh[kk][0] = Qhi[c * ATS + m0 + grp];
        qh[kk][1] = Qhi[c * ATS + m0 + grp + 8];
        qh[kk][2] = Qhi[(c + 4) * ATS + m0 + grp];
        qh[kk][3] = Qhi[(c + 4) * ATS + m0 + grp + 8];
        ql[kk][0] = Qlo[c * ATS + m0 + grp];
        ql[kk][1] = Qlo[c * ATS + m0 + grp + 8];
        ql[kk][2] = Qlo[(c + 4) * ATS + m0 + grp];
        ql[kk][3] = Qlo[(c + 4) * ATS + m0 + grp + 8];
    }
    __syncthreads();

    {
        float* K0 = sm + SM_PHI;
        float* V0 = K0 + 64 * KVP;
#pragma unroll
        for (int i = 0; i < 4; i++) {
            const int ktok = kTok + i * 16;
            K0[ktok * KVP + kPB + 0] = kreg[i].x;
            K0[ktok * KVP + kPB + 2] = kreg[i].y;
            K0[ktok * KVP + kPB + 4] = kreg[i].z;
            K0[ktok * KVP + kPB + 6] = kreg[i].w;
            const int vt = vTok + i * 16;
            const int pt = ((vt >> 3) << 3) + ((vt & 3) << 1) + ((vt >> 2) & 1);
            V0[(vD + 0) * KVP + pt] = vreg[i].x;
            V0[(vD + 1) * KVP + pt] = vreg[i].y;
            V0[(vD + 2) * KVP + pt] = vreg[i].z;
            V0[(vD + 3) * KVP + pt] = vreg[i].w;
        }
    }
    __syncthreads();

    float m_0 = -1e30f, m_1 = -1e30f, l_0 = 0.f, l_1 = 0.f;
    float o[8][4];
#pragma unroll
    for (int nt = 0; nt < 8; nt++)
#pragma unroll
        for (int e = 0; e < 4; e++) o[nt][e] = 0.f;

    for (int jt = 0; jt < ntile; jt++) {
        float* Ks = sm + SM_PHI + (jt & 1) * SM_BUF;
        float* Vt = Ks + 64 * KVP;
        const bool more = (jt + 1 < ntile);

        if (more) {
            const int k0n = (jt + 1) * 64;
#pragma unroll
            for (int i = 0; i < 4; i++)
                kreg[i] = *(const float4*)(Kg + (size_t)(b * TT + k0n + kTok + i * 16) * KVD + hkv * HD + kD);
        }

        float s[8][4];
#pragma unroll
        for (int nt = 0; nt < 8; nt++)
#pragma unroll
            for (int e = 0; e < 4; e++) s[nt][e] = 0.f;

#pragma unroll
        for (int kk = 0; kk < 8; kk++) {
            const int p = kk * 8 + qid * 2;
#pragma unroll
            for (int nt = 0; nt < 8; nt++) {
                const int n = nt * 8 + grp;
                float2 kb = *(const float2*)(Ks + n * KVP + p);
                float bb[2] = { kb.x, kb.y };
                mma_tf32(s[nt], qh[kk], bb);
                mma_tf32(s[nt], ql[kk], bb);
            }
        }

        if (more) {
            const int k0n = (jt + 1) * 64;
#pragma unroll
            for (int i = 0; i < 4; i++)
                vreg[i] = *(const float4*)(Vg + (size_t)(b * TT + k0n + vTok + i * 16) * KVD + hkv * HD + vD);
        }

#pragma unroll
        for (int nt = 0; nt < 8; nt++)
#pragma unroll
            for (int e = 0; e < 4; e++) s[nt][e] *= SCALE;
        if (jt >= maskstart) {
            const int k0 = jt * 64;
#pragma unroll
            for (int nt = 0; nt < 8; nt++)
#pragma unroll
                for (int e = 0; e < 4; e++) {
                    const int row = m0 + grp + ((e >> 1) * 8);
                    const int col = nt * 8 + qid * 2 + (e & 1);
                    if (k0 + col > q0 + row) s[nt][e] = -1e30f;
                }
        }

        float mx0 = -1e30f, mx1 = -1e30f;
#pragma unroll
        for (int nt = 0; nt < 8; nt++) {
            mx0 = fmaxf(mx0, fmaxf(s[nt][0], s[nt][1]));
            mx1 = fmaxf(mx1, fmaxf(s[nt][2], s[nt][3]));
        }
        mx0 = fmaxf(mx0, __shfl_xor_sync(0xffffffffu, mx0, 1));
        mx0 = fmaxf(mx0, __shfl_xor_sync(0xffffffffu, mx0, 2));
        mx1 = fmaxf(mx1, __shfl_xor_sync(0xffffffffu, mx1, 1));
        mx1 = fmaxf(mx1, __shfl_xor_sync(0xffffffffu, mx1, 2));

        const float mn0 = fmaxf(m_0, mx0);
        const float mn1 = fmaxf(m_1, mx1);
        const float a0  = fast_exp2(m_0 - mn0);
        const float a1  = fast_exp2(m_1 - mn1);
        m_0 = mn0; m_1 = mn1;

        float ps0 = 0.f, ps1 = 0.f;
#pragma unroll
        for (int nt = 0; nt < 8; nt++) {
#pragma unroll
            for (int e = 0; e < 2; e++) {
                const float p = fast_exp2(s[nt][e] - mn0);
                ps0 += p;
                const int v = qid * 2 + e;
                const int posv = ((v & 3) << 1) + (v >> 2);
                Phi[(m0 + grp) * KVP + nt * 8 + posv] = to_tf32(p);
            }
#pragma unroll
            for (int e = 2; e < 4; e++) {
                const float p = fast_exp2(s[nt][e] - mn1);
                ps1 += p;
                const int v = qid * 2 + (e & 1);
                const int posv = ((v & 3) << 1) + (v >> 2);
                Phi[(m0 + grp + 8) * KVP + nt * 8 + posv] = to_tf32(p);
            }
        }
        ps0 += __shfl_xor_sync(0xffffffffu, ps0, 1);
        ps0 += __shfl_xor_sync(0xffffffffu, ps0, 2);
        ps1 += __shfl_xor_sync(0xffffffffu, ps1, 1);
        ps1 += __shfl_xor_sync(0xffffffffu, ps1, 2);
        l_0 = l_0 * a0 + ps0;
        l_1 = l_1 * a1 + ps1;
        __syncwarp();

#pragma unroll
        for (int nt = 0; nt < 8; nt++) {
            o[nt][0] *= a0; o[nt][1] *= a0;
            o[nt][2] *= a1; o[nt][3] *= a1;
        }
#pragma unroll
        for (int kk = 0; kk < 8; kk++) {
            const int p = kk * 8 + qid * 2;
            float2 f0 = *(const float2*)(Phi + (m0 + grp) * KVP + p);
            float2 f1 = *(const float2*)(Phi + (m0 + grp + 8) * KVP + p);
            float ah[4] = { f0.x, f1.x, f0.y, f1.y };
#pragma unroll
            for (int nt = 0; nt < 8; nt++) {
                const int n = nt * 8 + grp;
                float2 vb = *(const float2*)(Vt + n * KVP + p);
                float bb[2] = { vb.x, vb.y };
                mma_tf32(o[nt], ah, bb);
            }
        }

        if (more) {
            float* Kn = sm + SM_PHI + ((jt + 1) & 1) * SM_BUF;
            float* Vn = Kn + 64 * KVP;
#pragma unroll
            for (int i = 0; i < 4; i++) {
                const int ktok = kTok + i * 16;
                Kn[ktok * KVP + kPB + 0] = kreg[i].x;
                Kn[ktok * KVP + kPB + 2] = kreg[i].y;
                Kn[ktok * KVP + kPB + 4] = kreg[i].z;
                Kn[ktok * KVP + kPB + 6] = kreg[i].w;
                const int vt = vTok + i * 16;
                const int pt = ((vt >> 3) << 3) + ((vt & 3) << 1) + ((vt >> 2) & 1);
                Vn[(vD + 0) * KVP + pt] = vreg[i].x;
                Vn[(vD + 1) * KVP + pt] = vreg[i].y;
                Vn[(vD + 2) * KVP + pt] = vreg[i].z;
                Vn[(vD + 3) * KVP + pt] = vreg[i].w;
            }
        }
        __syncthreads();
    }

    // ---- epilogue: tf32-rounded O/l -> g_O in k-PERMUTED layout ----
    const float inv0 = 1.f / l_0;
    const float inv1 = 1.f / l_1;
    const int r0 = q0 + m0 + grp;
    const int r1 = r0 + 8;
#pragma unroll
    for (int nt = 0; nt < 8; nt++) {
        const int colb = nt * 8 + qid * 2;
#pragma unroll
        for (int j = 0; j < 2; j++) {
            const int c16 = (colb + j) & 15;
            const int pos = h * HD + ((colb + j) & ~15) + kperm(c16);
            Og[(size_t)(b * TT + r0) * CC + pos] = to_tf32(o[nt][0 + j] * inv0);
            Og[(size_t)(b * TT + r1) * CC + pos] = to_tf32(o[nt][2 + j] * inv1);
        }
    }
}

// ---------------------------------------------------------------------------
extern "C" void kernel_launch(void* const* d_in, const int* in_sizes, int n_in,
                              void* d_out, int out_size)
{
    const float* x  = (const float*)d_in[0];
    // d_in[1] = mask (causal tril) — structural, not read
    const float* Wq = (const float*)d_in[2];
    const float* bq = (const float*)d_in[3];
    const float* Wk = (const float*)d_in[4];
    const float* bk = (const float*)d_in[5];
    const float* Wv = (const float*)d_in[6];
    const float* bv = (const float*)d_in[7];
    const float* Wo = (const float*)d_in[8];
    const float* bo = (const float*)d_in[9];
    float* out = (float*)d_out;

    float *Qp, *Kp, *Vp, *Op;
    cudaGetSymbolAddress((void**)&Qp, g_Q);
    cudaGetSymbolAddress((void**)&Kp, g_K);
    cudaGetSymbolAddress((void**)&Vp, g_V);
    cudaGetSymbolAddress((void**)&Op, g_O);

    const int smem_attn = SMF * sizeof(float);       // 135,168 B
    cudaFuncSetAttribute(attn_tc,
                         cudaFuncAttributeMaxDynamicSharedMemorySize, smem_attn);
    cudaFuncSetAttribute(gemm_qkv,
                         cudaFuncAttributeMaxDynamicSharedMemorySize, GEMM_SMEM_BYTES);
    cudaFuncSetAttribute(gemm_out,
                         cudaFuncAttributeMaxDynamicSharedMemorySize, GEMM_SMEM_BYTES);

    dim3 blk(256);
    cvt_pass<<<dim3(256, 5), blk>>>(x, Wq, Wk, Wv, Wo);
    gemm_qkv<<<dim3(24, MM / 128), blk, GEMM_SMEM_BYTES>>>(bq, bk, bv);
    attn_tc<<<dim3(TT / 128, HQ, BB), blk, smem_attn>>>(Qp, Kp, Vp, Op);
    gemm_out<<<dim3(CC / 128, MM / 128), blk, GEMM_SMEM_BYTES>>>(bo, out);
}

// round 12
// speedup vs baseline: 3.4676x; 1.0801x over previous
#include <cuda_runtime.h>
#include <stdint.h>

#define BB   2
#define TT   2048
#define CC   2048
#define HQ   32
#define HKV  8
#define HD   64
#define MM   (BB*TT)        // 4096
#define KVD  (HKV*HD)       // 512

// Scratch (no allocations allowed anywhere)
__device__ float g_Q[MM*CC];     // 32 MB
__device__ float g_K[MM*KVD];    // 8 MB  (tf32-rounded)
__device__ float g_V[MM*KVD];    // 8 MB  (tf32-rounded)
__device__ float g_O[MM*CC];     // 32 MB (tf32-rounded, k-PERMUTED layout)
__device__ float g_Xc[MM*CC];    // tf32-rounded x, k-PERMUTED layout
__device__ float g_Wqc[CC*CC];
__device__ float g_Wkc[CC*KVD];
__device__ float g_Wvc[CC*KVD];
__device__ float g_Woc[CC*CC];

// ---------------------------------------------------------------------------
// helpers
// ---------------------------------------------------------------------------
__device__ __forceinline__ float to_tf32(float x) {
    float r;
    asm("cvt.rna.tf32.f32 %0, %1;" : "=f"(r) : "f"(x));
    return r;
}

__device__ __forceinline__ float fast_exp2(float x) {
    float r;
    asm("ex2.approx.ftz.f32 %0, %1;" : "=f"(r) : "f"(x));
    return r;
}

// within-16 k-permutation: pos(k) = (k&3)*4 + (k>>2)
__device__ __forceinline__ int kperm(int c16) {
    return ((c16 & 3) << 2) + (c16 >> 2);
}

__device__ __forceinline__ void mma_tf32(float* d, const float* a, const float* b) {
    asm volatile(
        "mma.sync.aligned.m16n8k8.row.col.f32.tf32.tf32.f32 "
        "{%0,%1,%2,%3}, {%4,%5,%6,%7}, {%8,%9}, {%0,%1,%2,%3};"
        : "+f"(d[0]), "+f"(d[1]), "+f"(d[2]), "+f"(d[3])
        : "r"(__float_as_uint(a[0])), "r"(__float_as_uint(a[1])),
          "r"(__float_as_uint(a[2])), "r"(__float_as_uint(a[3])),
          "r"(__float_as_uint(b[0])), "r"(__float_as_uint(b[1])));
}

__device__ __forceinline__ void cp16(float* dst, const float* src) {
    unsigned d = (unsigned)__cvta_generic_to_shared(dst);
    asm volatile("cp.async.cg.shared.global [%0], [%1], 16;" :: "r"(d), "l"(src));
}
#define CP_COMMIT()  asm volatile("cp.async.commit_group;" ::: "memory")
#define CP_WAIT2()   asm volatile("cp.async.wait_group 2;"  ::: "memory")
#define CP_WAIT1()   asm volatile("cp.async.wait_group 1;"  ::: "memory")

// ---------------------------------------------------------------------------
// tf32 pre-rounding pass. y==0: x -> g_Xc with within-16 k-permutation.
// y>=1: plain rounded W copies.
// ---------------------------------------------------------------------------
__global__ __launch_bounds__(256) void cvt_pass(
    const float* __restrict__ x,  const float* __restrict__ wq,
    const float* __restrict__ wk, const float* __restrict__ wv,
    const float* __restrict__ wo)
{
    const int gtid = blockIdx.x * blockDim.x + threadIdx.x;
    const int gstr = gridDim.x * blockDim.x;
    if (blockIdx.y == 0) {
        const int nblk = MM * CC / 16;
        for (int i = gtid; i < nblk; i += gstr) {
            const float4* src = (const float4*)x + (size_t)i * 4;
            float4 v0 = src[0], v1 = src[1], v2 = src[2], v3 = src[3];
            float4* dst = (float4*)g_Xc + (size_t)i * 4;
            float4 o;
            o.x = to_tf32(v0.x); o.y = to_tf32(v1.x); o.z = to_tf32(v2.x); o.w = to_tf32(v3.x);
            dst[0] = o;
            o.x = to_tf32(v0.y); o.y = to_tf32(v1.y); o.z = to_tf32(v2.y); o.w = to_tf32(v3.y);
            dst[1] = o;
            o.x = to_tf32(v0.z); o.y = to_tf32(v1.z); o.z = to_tf32(v2.z); o.w = to_tf32(v3.z);
            dst[2] = o;
            o.x = to_tf32(v0.w); o.y = to_tf32(v1.w); o.z = to_tf32(v2.w); o.w = to_tf32(v3.w);
            dst[3] = o;
        }
        return;
    }
    const float* src; float* dst; int n4;
    switch (blockIdx.y) {
        case 1:  src = wq; dst = g_Wqc; n4 = CC * CC / 4;  break;
        case 2:  src = wk; dst = g_Wkc; n4 = CC * KVD / 4; break;
        case 3:  src = wv; dst = g_Wvc; n4 = CC * KVD / 4; break;
        default: src = wo; dst = g_Woc; n4 = CC * CC / 4;  break;
    }
    for (int i = gtid; i < n4; i += gstr) {
        float4 v = ((const float4*)src)[i];
        v.x = to_tf32(v.x); v.y = to_tf32(v.y);
        v.z = to_tf32(v.z); v.w = to_tf32(v.w);
        ((float4*)dst)[i] = v;
    }
}

// ---------------------------------------------------------------------------
// GEMM body: C[128 x 256] = A @ W + bias.  A k-PERMUTED.
// 256 thr, 8 warps (2m x 4n), warp tile 64x64 (4mt x 8nt mma).
// 4-stage cp.async pipeline; 1 sync/iter.
// ---------------------------------------------------------------------------
#define SSTB 264
#define GSTG 4
#define ASTG (128*16)                                   // 2048 floats / stage
#define BSTG (16*SSTB)                                  // 4224 floats / stage
#define GEMM_SMEM_FLOATS (GSTG * (ASTG + BSTG))         // 25,088
#define GEMM_SMEM_BYTES  (GEMM_SMEM_FLOATS * 4)         // 100,352

__device__ __forceinline__ void gemm_body(
    const float* __restrict__ A, const float* __restrict__ W,
    const float* __restrict__ bias, float* __restrict__ Co,
    int Nd, int Kd, int row0, int col0, bool roundOut, float* smem)
{
    float* AsB = smem;                   // [GSTG][128][16]
    float* BsB = smem + GSTG * ASTG;     // [GSTG][16][SSTB]

    const int tid  = threadIdx.x;
    const int lane = tid & 31;
    const int warp = tid >> 5;
    const int wm   = (warp & 1) * 64;
    const int wn   = (warp >> 1) * 64;

    const int aRow = tid >> 1;            // 0..127
    const int aOff = (tid & 1) * 8;       // 0 or 8

    const int grp = lane >> 2;
    const int qid = lane & 3;

    float acc[4][8][4];
#pragma unroll
    for (int i = 0; i < 4; i++)
#pragma unroll
        for (int j = 0; j < 8; j++)
#pragma unroll
            for (int r = 0; r < 4; r++) acc[i][j][r] = 0.f;

    const int niter = Kd / 16;

    // prologue: issue stages 0..2
#pragma unroll
    for (int s = 0; s < GSTG - 1; s++) {
        const int k0 = s * 16;
        float* Ad = AsB + s * ASTG;
        float* Bd = BsB + s * BSTG;
        cp16(Ad + aRow * 16 + aOff,     A + (size_t)(row0 + aRow) * Kd + k0 + aOff);
        cp16(Ad + aRow * 16 + aOff + 4, A + (size_t)(row0 + aRow) * Kd + k0 + aOff + 4);
#pragma unroll
        for (int j = 0; j < 4; j++) {
            const int ch  = tid + j * 256;
            const int br  = ch >> 6;          // 0..15
            const int bc4 = (ch & 63) * 4;    // 0..252
            cp16(Bd + br * SSTB + bc4, W + (size_t)(k0 + br) * Nd + col0 + bc4);
        }
        CP_COMMIT();
    }

    int cs = 0, ss = GSTG - 1;
    for (int it = 0; it < niter; it++) {
        CP_WAIT2();
        __syncthreads();
        const float* Ac = AsB + cs * ASTG;
        const float* Bc = BsB + cs * BSTG;

        // A fragments for both kk-halves: 8 x LDS.128
        float4 A0[4], A1[4];
#pragma unroll
        for (int mt = 0; mt < 4; mt++) {
            const int r = wm + mt * 16 + grp;
            A0[mt] = *(const float4*)(Ac + r * 16 + 4 * qid);
            A1[mt] = *(const float4*)(Ac + (r + 8) * 16 + 4 * qid);
        }

#pragma unroll
        for (int half = 0; half < 2; half++) {
            const int c = half * 8 + qid;
            float b[8][2];
#pragma unroll
            for (int nt = 0; nt < 8; nt++) {
                const int n = wn + nt * 8 + grp;
                b[nt][0] = Bc[c * SSTB + n];
                b[nt][1] = Bc[(c + 4) * SSTB + n];
            }
#pragma unroll
            for (int mt = 0; mt < 4; mt++) {
                float a[4];
                if (half == 0) {
                    a[0] = A0[mt].x; a[1] = A1[mt].x; a[2] = A0[mt].y; a[3] = A1[mt].y;
                } else {
                    a[0] = A0[mt].z; a[1] = A1[mt].z; a[2] = A0[mt].w; a[3] = A1[mt].w;
                }
#pragma unroll
                for (int nt = 0; nt < 8; nt++)
                    mma_tf32(acc[mt][nt], a, b[nt]);
            }
        }

        if (it + GSTG - 1 < niter) {
            const int k0 = (it + GSTG - 1) * 16;
            float* Ad = AsB + ss * ASTG;
            float* Bd = BsB + ss * BSTG;
            cp16(Ad + aRow * 16 + aOff,     A + (size_t)(row0 + aRow) * Kd + k0 + aOff);
            cp16(Ad + aRow * 16 + aOff + 4, A + (size_t)(row0 + aRow) * Kd + k0 + aOff + 4);
#pragma unroll
            for (int j = 0; j < 4; j++) {
                const int ch  = tid + j * 256;
                const int br  = ch >> 6;
                const int bc4 = (ch & 63) * 4;
                cp16(Bd + br * SSTB + bc4, W + (size_t)(k0 + br) * Nd + col0 + bc4);
            }
        }
        CP_COMMIT();
        cs = (cs + 1 == GSTG) ? 0 : cs + 1;
        ss = (ss + 1 == GSTG) ? 0 : ss + 1;
    }

#pragma unroll
    for (int mt = 0; mt < 4; mt++) {
#pragma unroll
        for (int nt = 0; nt < 8; nt++) {
            const int r = row0 + wm + mt * 16 + grp;
            const int c = col0 + wn + nt * 8 + qid * 2;
            float2 o0, o1;
            o0.x = acc[mt][nt][0] + bias[c];
            o0.y = acc[mt][nt][1] + bias[c + 1];
            o1.x = acc[mt][nt][2] + bias[c];
            o1.y = acc[mt][nt][3] + bias[c + 1];
            if (roundOut) {
                o0.x = to_tf32(o0.x); o0.y = to_tf32(o0.y);
                o1.x = to_tf32(o1.x); o1.y = to_tf32(o1.y);
            }
            *(float2*)(Co + (size_t)r * Nd + c)       = o0;
            *(float2*)(Co + (size_t)(r + 8) * Nd + c) = o1;
        }
    }
}

// Fused Q+K+V projection. grid.x = 12: [0,8) Q (N=2048), [8,10) K, [10,12) V.
__global__ __launch_bounds__(256, 1) void gemm_qkv(
    const float* __restrict__ bq, const float* __restrict__ bk,
    const float* __restrict__ bv)
{
    extern __shared__ float smem[];
    const int bx = blockIdx.x;
    if (bx < 8)
        gemm_body(g_Xc, g_Wqc, bq, g_Q, CC,  CC, blockIdx.y * 128, bx * 256, false, smem);
    else if (bx < 10)
        gemm_body(g_Xc, g_Wkc, bk, g_K, KVD, CC, blockIdx.y * 128, (bx - 8) * 256, true, smem);
    else
        gemm_body(g_Xc, g_Wvc, bv, g_V, KVD, CC, blockIdx.y * 128, (bx - 10) * 256, true, smem);
}

__global__ __launch_bounds__(256, 1) void gemm_out(
    const float* __restrict__ bo, float* __restrict__ out)
{
    extern __shared__ float smem[];
    gemm_body(g_O, g_Woc, bo, out, CC, CC, blockIdx.y * 128, blockIdx.x * 256, false, smem);
}

// ---------------------------------------------------------------------------
// Tensor-core flash attention: 128-thread CTAs (64 q-rows), 2 CTAs/SM.
// K/V via cp.async double buffer (K [tok][68], V [tok][72] natural layouts,
// conflict-free scalar fragment loads). Q split hi/lo in registers.
// Phi [row][72] with k-paired permutation (LDS.64 A-frags).
// ---------------------------------------------------------------------------
#define QTS  68
#define KSK  68
#define VSK  72
#define PSK  72
#define SM_K   (64*KSK)                    // 4352
#define SM_V   (64*VSK)                    // 4608
#define SM_BUF (SM_K + SM_V)               // 8960
#define SM_PHI (64*PSK)                    // 4608
#define ATT_SMF (SM_PHI + 2*SM_BUF)        // 22528 floats = 90,112 B
#define SCALE 0.18033688011112042f         // log2(e)/sqrt(64)

__global__ __launch_bounds__(128, 2) void attn_tc(
    const float* __restrict__ Qg, const float* __restrict__ Kg,
    const float* __restrict__ Vg, float* __restrict__ Og)
{
    extern __shared__ float sm[];
    float* Phi = sm;                       // [64][PSK] after prologue
    float* Qhi = sm;                       // staging (prologue only)
    float* Qlo = sm + 64 * QTS;

    const int tid  = threadIdx.x;
    const int lane = tid & 31;
    const int warp = tid >> 5;             // 0..3
    const int grp  = lane >> 2;
    const int qid  = lane & 3;
    const int q0   = (gridDim.x - 1 - blockIdx.x) * 64;   // long CTAs first
    const int h    = blockIdx.y;
    const int b    = blockIdx.z;
    const int hkv  = h >> 2;
    const int m0   = warp * 16;

    const int ntile = (q0 >> 6) + 1;       // last tile is the diagonal

    // tile jt lives in buffer ((jt&1)^1): tile0 -> buf1 (doesn't overlap staging)
    // issue K+V cp.async for tile jt
    auto issue_kv = [&](int jt) {
        float* base = sm + SM_PHI + (((jt & 1) ^ 1) ? SM_BUF : 0);
        float* Kd = base;
        float* Vd = base + SM_K;
        const size_t gb = (size_t)(b * TT + jt * 64) * KVD + hkv * HD;
#pragma unroll
        for (int i = 0; i < 8; i++) {
            const int ch  = tid + i * 128;
            const int tok = ch >> 4;
            const int c4  = (ch & 15) * 4;
            cp16(Kd + tok * KSK + c4, Kg + gb + (size_t)tok * KVD + c4);
        }
#pragma unroll
        for (int i = 0; i < 8; i++) {
            const int ch  = tid + i * 128;
            const int tok = ch >> 4;
            const int c4  = (ch & 15) * 4;
            cp16(Vd + tok * VSK + c4, Vg + gb + (size_t)tok * KVD + c4);
        }
    };

    issue_kv(0);
    CP_COMMIT();

    // ---- stage Q (64 x 64) split hi/lo, layout [d][m] ----
#pragma unroll
    for (int i = 0; i < 8; i++) {
        const int idx = tid + i * 128;
        const int row = idx >> 4;           // 0..63
        const int d0  = (idx & 15) * 4;
        float4 v = *(const float4*)(Qg + (size_t)(b * TT + q0 + row) * CC + h * HD + d0);
        float q[4] = {v.x, v.y, v.z, v.w};
#pragma unroll
        for (int j = 0; j < 4; j++) {
            const float hi = to_tf32(q[j]);
            Qhi[(d0 + j) * QTS + row] = hi;
            Qlo[(d0 + j) * QTS + row] = to_tf32(q[j] - hi);
        }
    }
    __syncthreads();

    // ---- hoist Q fragments to registers ----
    float qh[8][4], ql[8][4];
#pragma unroll
    for (int kk = 0; kk < 8; kk++) {
        const int c = kk * 8 + qid;
        qh[kk][0] = Qhi[c * QTS + m0 + grp];
        qh[kk][1] = Qhi[c * QTS + m0 + grp + 8];
        qh[kk][2] = Qhi[(c + 4) * QTS + m0 + grp];
        qh[kk][3] = Qhi[(c + 4) * QTS + m0 + grp + 8];
        ql[kk][0] = Qlo[c * QTS + m0 + grp];
        ql[kk][1] = Qlo[c * QTS + m0 + grp + 8];
        ql[kk][2] = Qlo[(c + 4) * QTS + m0 + grp];
        ql[kk][3] = Qlo[(c + 4) * QTS + m0 + grp + 8];
    }
    __syncthreads();   // staging reads done before buf0 cp (iter0) overwrites it

    float m_0 = -1e30f, m_1 = -1e30f, l_0 = 0.f, l_1 = 0.f;
    float o[8][4];
#pragma unroll
    for (int nt = 0; nt < 8; nt++)
#pragma unroll
        for (int e = 0; e < 4; e++) o[nt][e] = 0.f;

    for (int jt = 0; jt < ntile; jt++) {
        if (jt + 1 < ntile) issue_kv(jt + 1);
        CP_COMMIT();
        CP_WAIT1();
        __syncthreads();

        float* Ks = sm + SM_PHI + (((jt & 1) ^ 1) ? SM_BUF : 0);
        float* Vs = Ks + SM_K;

        // ---- S = Q K^T ----
        float s[8][4];
#pragma unroll
        for (int nt = 0; nt < 8; nt++)
#pragma unroll
            for (int e = 0; e < 4; e++) s[nt][e] = 0.f;

#pragma unroll
        for (int kk = 0; kk < 8; kk++) {
            const int c = kk * 8 + qid;
#pragma unroll
            for (int nt = 0; nt < 8; nt++) {
                const int n = nt * 8 + grp;
                float bb[2] = { Ks[n * KSK + c], Ks[n * KSK + c + 4] };
                mma_tf32(s[nt], qh[kk], bb);
                mma_tf32(s[nt], ql[kk], bb);
            }
        }

        // ---- scale + causal mask (only diagonal tile) ----
#pragma unroll
        for (int nt = 0; nt < 8; nt++)
#pragma unroll
            for (int e = 0; e < 4; e++) s[nt][e] *= SCALE;
        if (jt == ntile - 1) {
            const int k0 = jt * 64;
#pragma unroll
            for (int nt = 0; nt < 8; nt++)
#pragma unroll
                for (int e = 0; e < 4; e++) {
                    const int row = m0 + grp + ((e >> 1) * 8);
                    const int col = nt * 8 + qid * 2 + (e & 1);
                    if (k0 + col > q0 + row) s[nt][e] = -1e30f;
                }
        }

        // ---- register online softmax ----
        float mx0 = -1e30f, mx1 = -1e30f;
#pragma unroll
        for (int nt = 0; nt < 8; nt++) {
            mx0 = fmaxf(mx0, fmaxf(s[nt][0], s[nt][1]));
            mx1 = fmaxf(mx1, fmaxf(s[nt][2], s[nt][3]));
        }
        mx0 = fmaxf(mx0, __shfl_xor_sync(0xffffffffu, mx0, 1));
        mx0 = fmaxf(mx0, __shfl_xor_sync(0xffffffffu, mx0, 2));
        mx1 = fmaxf(mx1, __shfl_xor_sync(0xffffffffu, mx1, 1));
        mx1 = fmaxf(mx1, __shfl_xor_sync(0xffffffffu, mx1, 2));

        const float mn0 = fmaxf(m_0, mx0);
        const float mn1 = fmaxf(m_1, mx1);
        const float a0  = fast_exp2(m_0 - mn0);
        const float a1  = fast_exp2(m_1 - mn1);
        m_0 = mn0; m_1 = mn1;

        float ps0 = 0.f, ps1 = 0.f;
#pragma unroll
        for (int nt = 0; nt < 8; nt++) {
#pragma unroll
            for (int e = 0; e < 2; e++) {
                const float p = fast_exp2(s[nt][e] - mn0);
                ps0 += p;
                const int v = qid * 2 + e;
                const int posv = ((v & 3) << 1) + (v >> 2);
                Phi[(m0 + grp) * PSK + nt * 8 + posv] = to_tf32(p);
            }
#pragma unroll
            for (int e = 2; e < 4; e++) {
                const float p = fast_exp2(s[nt][e] - mn1);
                ps1 += p;
                const int v = qid * 2 + (e & 1);
                const int posv = ((v & 3) << 1) + (v >> 2);
                Phi[(m0 + grp + 8) * PSK + nt * 8 + posv] = to_tf32(p);
            }
        }
        ps0 += __shfl_xor_sync(0xffffffffu, ps0, 1);
        ps0 += __shfl_xor_sync(0xffffffffu, ps0, 2);
        ps1 += __shfl_xor_sync(0xffffffffu, ps1, 1);
        ps1 += __shfl_xor_sync(0xffffffffu, ps1, 2);
        l_0 = l_0 * a0 + ps0;
        l_1 = l_1 * a1 + ps1;
        __syncwarp();   // own-warp P stores -> own-warp fragment loads

        // ---- rescale O, then O += P V ----
#pragma unroll
        for (int nt = 0; nt < 8; nt++) {
            o[nt][0] *= a0; o[nt][1] *= a0;
            o[nt][2] *= a1; o[nt][3] *= a1;
        }
#pragma unroll
        for (int kk = 0; kk < 8; kk++) {
            const int p = kk * 8 + qid * 2;
            float2 f0 = *(const float2*)(Phi + (m0 + grp) * PSK + p);
            float2 f1 = *(const float2*)(Phi + (m0 + grp + 8) * PSK + p);
            float ah[4] = { f0.x, f1.x, f0.y, f1.y };
            const int c = kk * 8 + qid;
#pragma unroll
            for (int nt = 0; nt < 8; nt++) {
                const int n = nt * 8 + grp;
                float bb[2] = { Vs[c * VSK + n], Vs[(c + 4) * VSK + n] };
                mma_tf32(o[nt], ah, bb);
            }
        }
        __syncthreads();   // all warps done with this tile's K/V before overwrite
    }

    // ---- epilogue: tf32-rounded O/l -> g_O in k-PERMUTED layout ----
    const float inv0 = 1.f / l_0;
    const float inv1 = 1.f / l_1;
    const int r0 = q0 + m0 + grp;
    const int r1 = r0 + 8;
#pragma unroll
    for (int nt = 0; nt < 8; nt++) {
        const int colb = nt * 8 + qid * 2;
#pragma unroll
        for (int j = 0; j < 2; j++) {
            const int c16 = (colb + j) & 15;
            const int pos = h * HD + ((colb + j) & ~15) + kperm(c16);
            Og[(size_t)(b * TT + r0) * CC + pos] = to_tf32(o[nt][0 + j] * inv0);
            Og[(size_t)(b * TT + r1) * CC + pos] = to_tf32(o[nt][2 + j] * inv1);
        }
    }
}

// ---------------------------------------------------------------------------
extern "C" void kernel_launch(void* const* d_in, const int* in_sizes, int n_in,
                              void* d_out, int out_size)
{
    const float* x  = (const float*)d_in[0];
    // d_in[1] = mask (causal tril) — structural, not read
    const float* Wq = (const float*)d_in[2];
    const float* bq = (const float*)d_in[3];
    const float* Wk = (const float*)d_in[4];
    const float* bk = (const float*)d_in[5];
    const float* Wv = (const float*)d_in[6];
    const float* bv = (const float*)d_in[7];
    const float* Wo = (const float*)d_in[8];
    const float* bo = (const float*)d_in[9];
    float* out = (float*)d_out;

    float *Qp, *Kp, *Vp, *Op;
    cudaGetSymbolAddress((void**)&Qp, g_Q);
    cudaGetSymbolAddress((void**)&Kp, g_K);
    cudaGetSymbolAddress((void**)&Vp, g_V);
    cudaGetSymbolAddress((void**)&Op, g_O);

    const int smem_attn = ATT_SMF * sizeof(float);   // 90,112 B
    cudaFuncSetAttribute(attn_tc,
                         cudaFuncAttributeMaxDynamicSharedMemorySize, smem_attn);
    cudaFuncSetAttribute(gemm_qkv,
                         cudaFuncAttributeMaxDynamicSharedMemorySize, GEMM_SMEM_BYTES);
    cudaFuncSetAttribute(gemm_out,
                         cudaFuncAttributeMaxDynamicSharedMemorySize, GEMM_SMEM_BYTES);

    dim3 gblk(256);
    dim3 ablk(128);
    cvt_pass<<<dim3(256, 5), gblk>>>(x, Wq, Wk, Wv, Wo);
    gemm_qkv<<<dim3(12, MM / 128), gblk, GEMM_SMEM_BYTES>>>(bq, bk, bv);
    attn_tc<<<dim3(TT / 64, HQ, BB), ablk, smem_attn>>>(Qp, Kp, Vp, Op);
    gemm_out<<<dim3(CC / 256, MM / 128), gblk, GEMM_SMEM_BYTES>>>(bo, out);
}

// round 16
// speedup vs baseline: 5.4038x; 1.5584x over previous
#include <cuda_runtime.h>
#include <cuda_fp16.h>
#include <stdint.h>

#define BB   2
#define TT   2048
#define CC   2048
#define HQ   32
#define HKV  8
#define HD   64
#define MM   (BB*TT)        // 4096
#define KVD  (HKV*HD)       // 512

// Scratch (no allocations allowed anywhere). fp16 operands, producer-written.
__device__ __half g_Qh[MM*CC];    // Q hi, k-permuted A layout
__device__ __half g_Ql[MM*CC];    // Q lo (residual), k-permuted
__device__ __half g_Kh[MM*KVD];   // K plain [tok][kvdim]
__device__ __half g_Vt[KVD*MM];   // V transposed [kvdim][tok]
__device__ __half g_Oh[MM*CC];    // attn out, k-permuted A layout
__device__ __half g_Xh[MM*CC];    // x, k-permuted A layout
__device__ __half g_Wqt[CC*CC];   // weights transposed [n][k]
__device__ __half g_Wkt[KVD*CC];
__device__ __half g_Wvt[KVD*CC];
__device__ __half g_Wot[CC*CC];

// ---------------------------------------------------------------------------
// helpers
// ---------------------------------------------------------------------------
__device__ __forceinline__ float fast_exp2(float x) {
    float r;
    asm("ex2.approx.ftz.f32 %0, %1;" : "=f"(r) : "f"(x));
    return r;
}
__device__ __forceinline__ uint32_t pack2(float a, float b) {
    __half2 t = __halves2half2(__float2half_rn(a), __float2half_rn(b));
    return *(uint32_t*)&t;
}
// f16 mma: D(16x8,f32) += A(16x16,f16) * B(16x8,f16)
__device__ __forceinline__ void mma_f16(float* d,
    uint32_t a0, uint32_t a1, uint32_t a2, uint32_t a3,
    uint32_t b0, uint32_t b1)
{
    asm volatile(
        "mma.sync.aligned.m16n8k16.row.col.f32.f16.f16.f32 "
        "{%0,%1,%2,%3}, {%4,%5,%6,%7}, {%8,%9}, {%0,%1,%2,%3};"
        : "+f"(d[0]), "+f"(d[1]), "+f"(d[2]), "+f"(d[3])
        : "r"(a0), "r"(a1), "r"(a2), "r"(a3), "r"(b0), "r"(b1));
}
__device__ __forceinline__ void cp16(void* dst, const void* src) {
    unsigned d = (unsigned)__cvta_generic_to_shared(dst);
    asm volatile("cp.async.cg.shared.global [%0], [%1], 16;" :: "r"(d), "l"(src));
}
#define CP_COMMIT()  asm volatile("cp.async.commit_group;" ::: "memory")
#define CP_WAIT1()   asm volatile("cp.async.wait_group 1;"  ::: "memory")

// ---------------------------------------------------------------------------
// cvt_x: x fp32 -> g_Xh fp16, k-permuted per 16-group:
// cluster q holds [2q, 2q+1, 2q+8, 2q+9]
// ---------------------------------------------------------------------------
__global__ __launch_bounds__(256) void cvt_x(const float* __restrict__ x)
{
    const int ngrp = MM * CC / 16;
    for (int g = blockIdx.x * blockDim.x + threadIdx.x; g < ngrp;
         g += gridDim.x * blockDim.x) {
        const float4* p = (const float4*)(x + (size_t)g * 16);
        float4 a = p[0], bq = p[1], c = p[2], d = p[3];
        uint32_t h[8];
        h[0] = pack2(a.x, a.y);  h[1] = pack2(c.x, c.y);
        h[2] = pack2(a.z, a.w);  h[3] = pack2(c.z, c.w);
        h[4] = pack2(bq.x, bq.y); h[5] = pack2(d.x, d.y);
        h[6] = pack2(bq.z, bq.w); h[7] = pack2(d.z, d.w);
        uint4* o = (uint4*)(g_Xh + (size_t)g * 16);
        o[0] = make_uint4(h[0], h[1], h[2], h[3]);
        o[1] = make_uint4(h[4], h[5], h[6], h[7]);
    }
}

// ---------------------------------------------------------------------------
// transpose_w: W[K][N] fp32 -> Wt[N][K] fp16 (K-major). 32x32 smem tiles.
// ---------------------------------------------------------------------------
__global__ __launch_bounds__(256) void transpose_w(
    const float* __restrict__ wq, const float* __restrict__ wk,
    const float* __restrict__ wv, const float* __restrict__ wo)
{
    __shared__ float t[32][33];
    const float* src; __half* dst; int Nd;
    switch (blockIdx.z) {
        case 0:  src = wq; dst = g_Wqt; Nd = CC;  break;
        case 1:  src = wk; dst = g_Wkt; Nd = KVD; break;
        case 2:  src = wv; dst = g_Wvt; Nd = KVD; break;
        default: src = wo; dst = g_Wot; Nd = CC;  break;
    }
    const int n0 = blockIdx.x * 32;
    if (n0 >= Nd) return;
    const int k0 = blockIdx.y * 32;
    const int tx = threadIdx.x & 31, ty = threadIdx.x >> 5;
#pragma unroll
    for (int i = 0; i < 32; i += 8)
        t[ty + i][tx] = src[(size_t)(k0 + ty + i) * Nd + n0 + tx];
    __syncthreads();
#pragma unroll
    for (int i = 0; i < 32; i += 8)
        dst[(size_t)(n0 + ty + i) * CC + k0 + tx] = __float2half_rn(t[tx][ty + i]);
}

// ---------------------------------------------------------------------------
// fp16 GEMM body: C[row0:+128, col0:+256] = A @ Bt^T + bias
// A fp16 k-permuted [m][2048]; Bt fp16 [n][2048] K-major.
// 256 thr, 8 warps (2m x 4n), warp tile 64x64, k32/iter, 3-stage cp.async.
// smem/stage: A 2 planes [128][16]h, B 2 planes [256][24]h = 32KB.
// Output modes: 0 fp32+bias, 1 Q hi/lo fp16 permuted, 2 K fp16 plain,
//               3 V fp16 transposed.
// ---------------------------------------------------------------------------
#define GSTG_B   32768
#define GEMM_SMEM_BYTES (3 * GSTG_B)   // 98,304

__device__ __forceinline__ void gemm_h_body(
    const __half* __restrict__ A, const __half* __restrict__ Bt,
    const float* __restrict__ bias, int mode,
    float* Cf, __half* Ch, __half* Ch2,
    int Nd, int row0, int col0, char* smem)
{
    const int tid  = threadIdx.x;
    const int lane = tid & 31;
    const int warp = tid >> 5;
    const int wm   = (warp & 1) * 64;
    const int wn   = (warp >> 1) * 64;
    const int grp  = lane >> 2;
    const int qid  = lane & 3;

    float acc[4][8][4];
#pragma unroll
    for (int i = 0; i < 4; i++)
#pragma unroll
        for (int j = 0; j < 8; j++)
#pragma unroll
            for (int r = 0; r < 4; r++) acc[i][j][r] = 0.f;

    // stage fill: A 2 chunks/thread, B 4 chunks/thread (16B each)
    auto fill = [&](int t, int s) {
        char* base = smem + s * GSTG_B;
#pragma unroll
        for (int i = 0; i < 2; i++) {
            const int ch = tid + i * 256;          // < 512
            const int row = ch >> 2, kg = (ch >> 1) & 1, hh = ch & 1;
            cp16(base + kg * 4096 + (row * 16 + hh * 8) * 2,
                 A + (size_t)(row0 + row) * CC + t * 32 + kg * 16 + hh * 8);
        }
#pragma unroll
        for (int i = 0; i < 4; i++) {
            const int ch = tid + i * 256;          // < 1024
            const int row = ch >> 2, kg = (ch >> 1) & 1, hh = ch & 1;
            cp16(base + 8192 + kg * 12288 + (row * 24 + hh * 8) * 2,
                 Bt + (size_t)(col0 + row) * CC + t * 32 + kg * 16 + hh * 8);
        }
    };

    fill(0, 0); CP_COMMIT();
    fill(1, 1); CP_COMMIT();

    const int niter = CC / 32;   // 64
    int cs = 0;
    for (int t = 0; t < niter; t++) {
        CP_WAIT1();
        __syncthreads();
        const __half* Ab = (const __half*)(smem + cs * GSTG_B);
        const __half* Bb = (const __half*)(smem + cs * GSTG_B + 8192);

#pragma unroll
        for (int kg = 0; kg < 2; kg++) {
            const __half* Ap = Ab + kg * 2048;
            const __half* Bp = Bb + kg * 6144;
            uint2 aLo[4], aHi[4];
#pragma unroll
            for (int mt = 0; mt < 4; mt++) {
                const int r = wm + mt * 16 + grp;
                aLo[mt] = *(const uint2*)(Ap + r * 16 + 4 * qid);
                aHi[mt] = *(const uint2*)(Ap + (r + 8) * 16 + 4 * qid);
            }
#pragma unroll
            for (int nt = 0; nt < 8; nt++) {
                const int n = wn + nt * 8 + grp;
                uint32_t b0 = *(const uint32_t*)(Bp + n * 24 + 2 * qid);
                uint32_t b1 = *(const uint32_t*)(Bp + n * 24 + 8 + 2 * qid);
#pragma unroll
                for (int mt = 0; mt < 4; mt++)
                    mma_f16(acc[mt][nt], aLo[mt].x, aHi[mt].x,
                            aLo[mt].y, aHi[mt].y, b0, b1);
            }
        }

        if (t + 2 < niter) fill(t + 2, (t + 2) % 3);
        CP_COMMIT();
        cs = (cs + 1 == 3) ? 0 : cs + 1;
    }

    // epilogue
#pragma unroll
    for (int mt = 0; mt < 4; mt++) {
#pragma unroll
        for (int nt = 0; nt < 8; nt++) {
            const int r = row0 + wm + mt * 16 + grp;
            const int c = col0 + wn + nt * 8 + qid * 2;
            float v00 = acc[mt][nt][0] + bias[c];
            float v01 = acc[mt][nt][1] + bias[c + 1];
            float v10 = acc[mt][nt][2] + bias[c];
            float v11 = acc[mt][nt][3] + bias[c + 1];
            if (mode == 0) {
                *(float2*)(Cf + (size_t)r * Nd + c)       = make_float2(v00, v01);
                *(float2*)(Cf + (size_t)(r + 8) * Nd + c) = make_float2(v10, v11);
            } else if (mode == 1) {
                const int pos = (c & ~15) + 4 * qid + ((c & 8) ? 2 : 0);
                __half h00 = __float2half_rn(v00), h01 = __float2half_rn(v01);
                __half h10 = __float2half_rn(v10), h11 = __float2half_rn(v11);
                *(__half2*)(Ch + (size_t)r * CC + pos)       = __halves2half2(h00, h01);
                *(__half2*)(Ch + (size_t)(r + 8) * CC + pos) = __halves2half2(h10, h11);
                *(__half2*)(Ch2 + (size_t)r * CC + pos) =
                    __halves2half2(__float2half_rn(v00 - __half2float(h00)),
                                   __float2half_rn(v01 - __half2float(h01)));
                *(__half2*)(Ch2 + (size_t)(r + 8) * CC + pos) =
                    __halves2half2(__float2half_rn(v10 - __half2float(h10)),
                                   __float2half_rn(v11 - __half2float(h11)));
            } else if (mode == 2) {
                *(__half2*)(Ch + (size_t)r * Nd + c) =
                    __halves2half2(__float2half_rn(v00), __float2half_rn(v01));
                *(__half2*)(Ch + (size_t)(r + 8) * Nd + c) =
                    __halves2half2(__float2half_rn(v10), __float2half_rn(v11));
            } else {  // V transposed
                Ch[(size_t)c * MM + r]           = __float2half_rn(v00);
                Ch[(size_t)(c + 1) * MM + r]     = __float2half_rn(v01);
                Ch[(size_t)c * MM + r + 8]       = __float2half_rn(v10);
                Ch[(size_t)(c + 1) * MM + r + 8] = __float2half_rn(v11);
            }
        }
    }
}

// Fused Q+K+V projection. grid.x = 12: [0,8) Q, [8,10) K, [10,12) V.
__global__ __launch_bounds__(256, 1) void gemm_qkv(
    const float* __restrict__ bq, const float* __restrict__ bk,
    const float* __restrict__ bv)
{
    extern __shared__ char smem[];
    const int bx = blockIdx.x;
    if (bx < 8)
        gemm_h_body(g_Xh, g_Wqt, bq, 1, nullptr, g_Qh, g_Ql, CC,
                    blockIdx.y * 128, bx * 256, smem);
    else if (bx < 10)
        gemm_h_body(g_Xh, g_Wkt, bk, 2, nullptr, g_Kh, nullptr, KVD,
                    blockIdx.y * 128, (bx - 8) * 256, smem);
    else
        gemm_h_body(g_Xh, g_Wvt, bv, 3, nullptr, g_Vt, nullptr, KVD,
                    blockIdx.y * 128, (bx - 10) * 256, smem);
}

__global__ __launch_bounds__(256, 1) void gemm_out(
    const float* __restrict__ bo, float* __restrict__ out)
{
    extern __shared__ char smem[];
    gemm_h_body(g_Oh, g_Wot, bo, 0, out, nullptr, nullptr, CC,
                blockIdx.y * 128, blockIdx.x * 256, smem);
}

// ---------------------------------------------------------------------------
// fp16 flash attention: 128-thr CTAs (64 q-rows), causal, GQA.
// Q hi/lo fragments via direct LDG (no staging). K [tok][72]h, V^T [d][72]h
// via cp.async double buffer. P in 4 permuted planes [64][16]h (STS/LDS.64).
// FIXED (R15 bug): K/V loaders now cover all 512 16B-chunks per tile.
// ---------------------------------------------------------------------------
#define KVS_H  72
#define SM_P_H   4096                      // 4 planes * 64 * 16 halves
#define SM_KV_H  (64*KVS_H)                // 4608 halves per K or V tile
#define ATT_SMEM_BYTES ((SM_P_H + 4*SM_KV_H) * 2)   // 45,056
#define SCALE 0.18033688011112042f         // log2(e)/sqrt(64)

__global__ __launch_bounds__(128, 3) void attn_h(
    float* __restrict__ dummy)
{
    extern __shared__ __half smh[];
    __half* Pp = smh;                      // planes: kg*1024 halves

    const int tid  = threadIdx.x;
    const int lane = tid & 31;
    const int warp = tid >> 5;
    const int grp  = lane >> 2;
    const int qid  = lane & 3;
    const int q0   = (gridDim.x - 1 - blockIdx.x) * 64;   // long CTAs first
    const int h    = blockIdx.y;
    const int b    = blockIdx.z;
    const int hkv  = h >> 2;
    const int m0   = warp * 16;
    const int ntile = (q0 >> 6) + 1;

    auto issue_kv = [&](int jt) {
        __half* Kd = smh + SM_P_H + (jt & 1) * 2 * SM_KV_H;
        __half* Vd = Kd + SM_KV_H;
        // K tile: 64 tok x 64 halves = 512 chunks of 16B
#pragma unroll
        for (int i = 0; i < 4; i++) {
            const int ch = tid + i * 128;        // < 512
            const int tok = ch >> 3, c8 = (ch & 7) * 8;
            cp16(Kd + tok * KVS_H + c8,
                 g_Kh + (size_t)(b * TT + jt * 64 + tok) * KVD + hkv * HD + c8);
        }
        // V^T tile: 64 d-rows x 64 token-halves = 512 chunks
#pragma unroll
        for (int i = 0; i < 4; i++) {
            const int ch = tid + i * 128;        // < 512
            const int d = ch >> 3, c8 = (ch & 7) * 8;
            cp16(Vd + d * KVS_H + c8,
                 g_Vt + (size_t)(hkv * HD + d) * MM + b * TT + jt * 64 + c8);
        }
    };

    issue_kv(0);
    CP_COMMIT();

    // Q fragments (hi & lo) via direct global loads, k-permuted layout
    uint2 qfh[4][2], qfl[4][2];
#pragma unroll
    for (int kg = 0; kg < 4; kg++) {
        const size_t base0 = (size_t)(b * TT + q0 + m0 + grp) * CC + h * HD + kg * 16 + 4 * qid;
        const size_t base1 = base0 + (size_t)8 * CC;
        qfh[kg][0] = *(const uint2*)(g_Qh + base0);
        qfh[kg][1] = *(const uint2*)(g_Qh + base1);
        qfl[kg][0] = *(const uint2*)(g_Ql + base0);
        qfl[kg][1] = *(const uint2*)(g_Ql + base1);
    }

    float m_0 = -1e30f, m_1 = -1e30f, l_0 = 0.f, l_1 = 0.f;
    float o[8][4];
#pragma unroll
    for (int nt = 0; nt < 8; nt++)
#pragma unroll
        for (int e = 0; e < 4; e++) o[nt][e] = 0.f;

    for (int jt = 0; jt < ntile; jt++) {
        if (jt + 1 < ntile) issue_kv(jt + 1);
        CP_COMMIT();
        CP_WAIT1();
        __syncthreads();

        const __half* Ks = smh + SM_P_H + (jt & 1) * 2 * SM_KV_H;
        const __half* Vs = Ks + SM_KV_H;

        // ---- S = Q K^T (hi + lo mma per kg) ----
        float s[8][4];
#pragma unroll
        for (int nt = 0; nt < 8; nt++)
#pragma unroll
            for (int e = 0; e < 4; e++) s[nt][e] = 0.f;

#pragma unroll
        for (int kg = 0; kg < 4; kg++) {
#pragma unroll
            for (int nt = 0; nt < 8; nt++) {
                const int n = nt * 8 + grp;
                uint32_t b0 = *(const uint32_t*)(Ks + n * KVS_H + kg * 16 + 2 * qid);
                uint32_t b1 = *(const uint32_t*)(Ks + n * KVS_H + kg * 16 + 8 + 2 * qid);
                mma_f16(s[nt], qfh[kg][0].x, qfh[kg][1].x, qfh[kg][0].y, qfh[kg][1].y, b0, b1);
                mma_f16(s[nt], qfl[kg][0].x, qfl[kg][1].x, qfl[kg][0].y, qfl[kg][1].y, b0, b1);
            }
        }

        // ---- scale (log2 domain) + causal mask on diagonal tile ----
#pragma unroll
        for (int nt = 0; nt < 8; nt++)
#pragma unroll
            for (int e = 0; e < 4; e++) s[nt][e] *= SCALE;
        if (jt == ntile - 1) {
            const int k0 = jt * 64;
#pragma unroll
            for (int nt = 0; nt < 8; nt++)
#pragma unroll
                for (int e = 0; e < 4; e++) {
                    const int row = m0 + grp + ((e >> 1) * 8);
                    const int col = nt * 8 + qid * 2 + (e & 1);
                    if (k0 + col > q0 + row) s[nt][e] = -1e30f;
                }
        }

        // ---- register online softmax ----
        float mx0 = -1e30f, mx1 = -1e30f;
#pragma unroll
        for (int nt = 0; nt < 8; nt++) {
            mx0 = fmaxf(mx0, fmaxf(s[nt][0], s[nt][1]));
            mx1 = fmaxf(mx1, fmaxf(s[nt][2], s[nt][3]));
        }
        mx0 = fmaxf(mx0, __shfl_xor_sync(0xffffffffu, mx0, 1));
        mx0 = fmaxf(mx0, __shfl_xor_sync(0xffffffffu, mx0, 2));
        mx1 = fmaxf(mx1, __shfl_xor_sync(0xffffffffu, mx1, 1));
        mx1 = fmaxf(mx1, __shfl_xor_sync(0xffffffffu, mx1, 2));

        const float mn0 = fmaxf(m_0, mx0);
        const float mn1 = fmaxf(m_1, mx1);
        const float a0  = fast_exp2(m_0 - mn0);
        const float a1  = fast_exp2(m_1 - mn1);
        m_0 = mn0; m_1 = mn1;

        float ps0 = 0.f, ps1 = 0.f;
#pragma unroll
        for (int ntp = 0; ntp < 4; ntp++) {
            const int ntA = 2 * ntp, ntB = 2 * ntp + 1;
            float pA0 = fast_exp2(s[ntA][0] - mn0);
            float pA1 = fast_exp2(s[ntA][1] - mn0);
            float pB0 = fast_exp2(s[ntB][0] - mn0);
            float pB1 = fast_exp2(s[ntB][1] - mn0);
            ps0 += pA0 + pA1 + pB0 + pB1;
            *(uint2*)(Pp + ntp * 1024 + (m0 + grp) * 16 + 4 * qid) =
                make_uint2(pack2(pA0, pA1), pack2(pB0, pB1));
            float qA0 = fast_exp2(s[ntA][2] - mn1);
            float qA1 = fast_exp2(s[ntA][3] - mn1);
            float qB0 = fast_exp2(s[ntB][2] - mn1);
            float qB1 = fast_exp2(s[ntB][3] - mn1);
            ps1 += qA0 + qA1 + qB0 + qB1;
            *(uint2*)(Pp + ntp * 1024 + (m0 + grp + 8) * 16 + 4 * qid) =
                make_uint2(pack2(qA0, qA1), pack2(qB0, qB1));
        }
        ps0 += __shfl_xor_sync(0xffffffffu, ps0, 1);
        ps0 += __shfl_xor_sync(0xffffffffu, ps0, 2);
        ps1 += __shfl_xor_sync(0xffffffffu, ps1, 1);
        ps1 += __shfl_xor_sync(0xffffffffu, ps1, 2);
        l_0 = l_0 * a0 + ps0;
        l_1 = l_1 * a1 + ps1;
        __syncwarp();   // own-warp P stores -> own-warp fragment loads

        // ---- rescale O, then O += P V ----
#pragma unroll
        for (int nt = 0; nt < 8; nt++) {
            o[nt][0] *= a0; o[nt][1] *= a0;
            o[nt][2] *= a1; o[nt][3] *= a1;
        }
#pragma unroll
        for (int kg = 0; kg < 4; kg++) {
            uint2 pf0 = *(const uint2*)(Pp + kg * 1024 + (m0 + grp) * 16 + 4 * qid);
            uint2 pf1 = *(const uint2*)(Pp + kg * 1024 + (m0 + grp + 8) * 16 + 4 * qid);
#pragma unroll
            for (int nt = 0; nt < 8; nt++) {
                const int n = nt * 8 + grp;
                uint32_t b0 = *(const uint32_t*)(Vs + n * KVS_H + kg * 16 + 2 * qid);
                uint32_t b1 = *(const uint32_t*)(Vs + n * KVS_H + kg * 16 + 8 + 2 * qid);
                mma_f16(o[nt], pf0.x, pf1.x, pf0.y, pf1.y, b0, b1);
            }
        }
        __syncthreads();   // all warps done with this tile's K/V before overwrite
    }

    // ---- epilogue: O/l -> g_Oh fp16, k-permuted A layout ----
    const float inv0 = 1.f / l_0;
    const float inv1 = 1.f / l_1;
    const int r0 = q0 + m0 + grp;
    const int r1 = r0 + 8;
#pragma unroll
    for (int nt = 0; nt < 8; nt++) {
        const int pos = h * HD + (nt >> 1) * 16 + 4 * qid + 2 * (nt & 1);
        *(__half2*)(g_Oh + (size_t)(b * TT + r0) * CC + pos) =
            __halves2half2(__float2half_rn(o[nt][0] * inv0),
                           __float2half_rn(o[nt][1] * inv0));
        *(__half2*)(g_Oh + (size_t)(b * TT + r1) * CC + pos) =
            __halves2half2(__float2half_rn(o[nt][2] * inv1),
                           __float2half_rn(o[nt][3] * inv1));
    }
    (void)dummy;
}

// ---------------------------------------------------------------------------
extern "C" void kernel_launch(void* const* d_in, const int* in_sizes, int n_in,
                              void* d_out, int out_size)
{
    const float* x  = (const float*)d_in[0];
    // d_in[1] = mask (causal tril) — structural, not read
    const float* Wq = (const float*)d_in[2];
    const float* bq = (const float*)d_in[3];
    const float* Wk = (const float*)d_in[4];
    const float* bk = (const float*)d_in[5];
    const float* Wv = (const float*)d_in[6];
    const float* bv = (const float*)d_in[7];
    const float* Wo = (const float*)d_in[8];
    const float* bo = (const float*)d_in[9];
    float* out = (float*)d_out;

    cudaFuncSetAttribute(attn_h,
                         cudaFuncAttributeMaxDynamicSharedMemorySize, ATT_SMEM_BYTES);
    cudaFuncSetAttribute(gemm_qkv,
                         cudaFuncAttributeMaxDynamicSharedMemorySize, GEMM_SMEM_BYTES);
    cudaFuncSetAttribute(gemm_out,
                         cudaFuncAttributeMaxDynamicSharedMemorySize, GEMM_SMEM_BYTES);

    cvt_x<<<256, 256>>>(x);
    transpose_w<<<dim3(64, 64, 4), 256>>>(Wq, Wk, Wv, Wo);
    gemm_qkv<<<dim3(12, MM / 128), 256, GEMM_SMEM_BYTES>>>(bq, bk, bv);
    attn_h<<<dim3(TT / 64, HQ, BB), 128, ATT_SMEM_BYTES>>>(nullptr);
    gemm_out<<<dim3(CC / 256, MM / 128), 256, GEMM_SMEM_BYTES>>>(bo, out);
}

// round 17
// speedup vs baseline: 6.2634x; 1.1591x over previous
#include <cuda_runtime.h>
#include <cuda_fp16.h>
#include <stdint.h>

#define BB   2
#define TT   2048
#define CC   2048
#define HQ   32
#define HKV  8
#define HD   64
#define MM   (BB*TT)        // 4096
#define KVD  (HKV*HD)       // 512

// Scratch (no allocations allowed anywhere). fp16 operands, producer-written.
__device__ __half g_Qh[MM*CC];    // Q hi, k-permuted A layout
__device__ __half g_Ql[MM*CC];    // Q lo (residual), k-permuted
__device__ __half g_Kh[MM*KVD];   // K plain [tok][kvdim]
__device__ __half g_Vt[KVD*MM];   // V transposed [kvdim][tok]
__device__ __half g_Oh[MM*CC];    // attn out, k-permuted A layout
__device__ __half g_Xh[MM*CC];    // x, k-permuted A layout
__device__ __half g_Wqt[CC*CC];   // weights transposed [n][k]
__device__ __half g_Wkt[KVD*CC];
__device__ __half g_Wvt[KVD*CC];
__device__ __half g_Wot[CC*CC];

// ---------------------------------------------------------------------------
// helpers
// ---------------------------------------------------------------------------
__device__ __forceinline__ float fast_exp2(float x) {
    float r;
    asm("ex2.approx.ftz.f32 %0, %1;" : "=f"(r) : "f"(x));
    return r;
}
__device__ __forceinline__ uint32_t pack2(float a, float b) {
    __half2 t = __halves2half2(__float2half_rn(a), __float2half_rn(b));
    return *(uint32_t*)&t;
}
// f16 mma: D(16x8,f32) += A(16x16,f16) * B(16x8,f16)
__device__ __forceinline__ void mma_f16(float* d,
    uint32_t a0, uint32_t a1, uint32_t a2, uint32_t a3,
    uint32_t b0, uint32_t b1)
{
    asm volatile(
        "mma.sync.aligned.m16n8k16.row.col.f32.f16.f16.f32 "
        "{%0,%1,%2,%3}, {%4,%5,%6,%7}, {%8,%9}, {%0,%1,%2,%3};"
        : "+f"(d[0]), "+f"(d[1]), "+f"(d[2]), "+f"(d[3])
        : "r"(a0), "r"(a1), "r"(a2), "r"(a3), "r"(b0), "r"(b1));
}
__device__ __forceinline__ void cp16(void* dst, const void* src) {
    unsigned d = (unsigned)__cvta_generic_to_shared(dst);
    asm volatile("cp.async.cg.shared.global [%0], [%1], 16;" :: "r"(d), "l"(src));
}
#define CP_COMMIT()  asm volatile("cp.async.commit_group;" ::: "memory")
#define CP_WAIT1()   asm volatile("cp.async.wait_group 1;"  ::: "memory")

// ---------------------------------------------------------------------------
// cvt_x: x fp32 -> g_Xh fp16, k-permuted per 16-group:
// cluster q holds [2q, 2q+1, 2q+8, 2q+9]
// ---------------------------------------------------------------------------
__global__ __launch_bounds__(256) void cvt_x(const float* __restrict__ x)
{
    const int ngrp = MM * CC / 16;
    for (int g = blockIdx.x * blockDim.x + threadIdx.x; g < ngrp;
         g += gridDim.x * blockDim.x) {
        const float4* p = (const float4*)(x + (size_t)g * 16);
        float4 a = p[0], bq = p[1], c = p[2], d = p[3];
        uint32_t h[8];
        h[0] = pack2(a.x, a.y);  h[1] = pack2(c.x, c.y);
        h[2] = pack2(a.z, a.w);  h[3] = pack2(c.z, c.w);
        h[4] = pack2(bq.x, bq.y); h[5] = pack2(d.x, d.y);
        h[6] = pack2(bq.z, bq.w); h[7] = pack2(d.z, d.w);
        uint4* o = (uint4*)(g_Xh + (size_t)g * 16);
        o[0] = make_uint4(h[0], h[1], h[2], h[3]);
        o[1] = make_uint4(h[4], h[5], h[6], h[7]);
    }
}

// ---------------------------------------------------------------------------
// transpose_w: W[K][N] fp32 -> Wt[N][K] fp16 (K-major). 32x32 smem tiles.
// ---------------------------------------------------------------------------
__global__ __launch_bounds__(256) void transpose_w(
    const float* __restrict__ wq, const float* __restrict__ wk,
    const float* __restrict__ wv, const float* __restrict__ wo)
{
    __shared__ float t[32][33];
    const float* src; __half* dst; int Nd;
    switch (blockIdx.z) {
        case 0:  src = wq; dst = g_Wqt; Nd = CC;  break;
        case 1:  src = wk; dst = g_Wkt; Nd = KVD; break;
        case 2:  src = wv; dst = g_Wvt; Nd = KVD; break;
        default: src = wo; dst = g_Wot; Nd = CC;  break;
    }
    const int n0 = blockIdx.x * 32;
    if (n0 >= Nd) return;
    const int k0 = blockIdx.y * 32;
    const int tx = threadIdx.x & 31, ty = threadIdx.x >> 5;
#pragma unroll
    for (int i = 0; i < 32; i += 8)
        t[ty + i][tx] = src[(size_t)(k0 + ty + i) * Nd + n0 + tx];
    __syncthreads();
#pragma unroll
    for (int i = 0; i < 32; i += 8)
        dst[(size_t)(n0 + ty + i) * CC + k0 + tx] = __float2half_rn(t[tx][ty + i]);
}

// ---------------------------------------------------------------------------
// fp16 GEMM body v2: C[row0:+128, col0:+128] = A @ Bt^T + bias
// 2 CTAs/SM (60KB smem). 8 warps (2m x 4n), warp tile 64x32, k32/iter,
// 3-stage cp.async. A & B planes stride 40 halves (conflict-free frag loads).
// Output modes: 0 fp32+bias, 1 Q hi/lo fp16 permuted, 2 K fp16 plain,
//               3 V fp16 transposed.
// ---------------------------------------------------------------------------
#define GPS   40                              // plane row stride, halves
#define GSTG_B (2 * 128 * GPS * 2)            // A+B planes per stage = 20,480 B
#define GEMM_SMEM_BYTES (3 * GSTG_B)          // 61,440

__device__ __forceinline__ void gemm_h_body(
    const __half* __restrict__ A, const __half* __restrict__ Bt,
    const float* __restrict__ bias, int mode,
    float* Cf, __half* Ch, __half* Ch2,
    int Nd, int row0, int col0, char* smem)
{
    const int tid  = threadIdx.x;
    const int lane = tid & 31;
    const int warp = tid >> 5;
    const int wm   = (warp & 1) * 64;
    const int wn   = (warp >> 1) * 32;
    const int grp  = lane >> 2;
    const int qid  = lane & 3;

    float acc[4][4][4];
#pragma unroll
    for (int i = 0; i < 4; i++)
#pragma unroll
        for (int j = 0; j < 4; j++)
#pragma unroll
            for (int r = 0; r < 4; r++) acc[i][j][r] = 0.f;

    // stage fill: A 512 chunks + B 512 chunks of 16B; 4 cp.async/thread
    auto fill = [&](int t, int s) {
        __half* As = (__half*)(smem + s * GSTG_B);
        __half* Bs = As + 128 * GPS;
#pragma unroll
        for (int i = 0; i < 2; i++) {
            const int ch = tid + i * 256;          // < 512
            const int row = ch >> 2, c8 = (ch & 3) * 8;
            cp16(As + row * GPS + c8,
                 A + (size_t)(row0 + row) * CC + t * 32 + c8);
        }
#pragma unroll
        for (int i = 0; i < 2; i++) {
            const int ch = tid + i * 256;          // < 512
            const int row = ch >> 2, c8 = (ch & 3) * 8;
            cp16(Bs + row * GPS + c8,
                 Bt + (size_t)(col0 + row) * CC + t * 32 + c8);
        }
    };

    fill(0, 0); CP_COMMIT();
    fill(1, 1); CP_COMMIT();

    const int niter = CC / 32;   // 64
    int cs = 0;
    for (int t = 0; t < niter; t++) {
        CP_WAIT1();
        __syncthreads();
        const __half* As = (const __half*)(smem + cs * GSTG_B);
        const __half* Bs = As + 128 * GPS;

#pragma unroll
        for (int kg = 0; kg < 2; kg++) {
            uint2 aLo[4], aHi[4];
#pragma unroll
            for (int mt = 0; mt < 4; mt++) {
                const int r = wm + mt * 16 + grp;
                aLo[mt] = *(const uint2*)(As + r * GPS + kg * 16 + 4 * qid);
                aHi[mt] = *(const uint2*)(As + (r + 8) * GPS + kg * 16 + 4 * qid);
            }
#pragma unroll
            for (int nt = 0; nt < 4; nt++) {
                const int n = wn + nt * 8 + grp;
                uint32_t b0 = *(const uint32_t*)(Bs + n * GPS + kg * 16 + 2 * qid);
                uint32_t b1 = *(const uint32_t*)(Bs + n * GPS + kg * 16 + 8 + 2 * qid);
#pragma unroll
                for (int mt = 0; mt < 4; mt++)
                    mma_f16(acc[mt][nt], aLo[mt].x, aHi[mt].x,
                            aLo[mt].y, aHi[mt].y, b0, b1);
            }
        }

        if (t + 2 < niter) fill(t + 2, (t + 2) % 3);
        CP_COMMIT();
        cs = (cs + 1 == 3) ? 0 : cs + 1;
    }

    // epilogue
#pragma unroll
    for (int mt = 0; mt < 4; mt++) {
#pragma unroll
        for (int nt = 0; nt < 4; nt++) {
            const int r = row0 + wm + mt * 16 + grp;
            const int c = col0 + wn + nt * 8 + qid * 2;
            float v00 = acc[mt][nt][0] + bias[c];
            float v01 = acc[mt][nt][1] + bias[c + 1];
            float v10 = acc[mt][nt][2] + bias[c];
            float v11 = acc[mt][nt][3] + bias[c + 1];
            if (mode == 0) {
                *(float2*)(Cf + (size_t)r * Nd + c)       = make_float2(v00, v01);
                *(float2*)(Cf + (size_t)(r + 8) * Nd + c) = make_float2(v10, v11);
            } else if (mode == 1) {
                const int pos = (c & ~15) + 4 * qid + ((c & 8) ? 2 : 0);
                __half h00 = __float2half_rn(v00), h01 = __float2half_rn(v01);
                __half h10 = __float2half_rn(v10), h11 = __float2half_rn(v11);
                *(__half2*)(Ch + (size_t)r * CC + pos)       = __halves2half2(h00, h01);
                *(__half2*)(Ch + (size_t)(r + 8) * CC + pos) = __halves2half2(h10, h11);
                *(__half2*)(Ch2 + (size_t)r * CC + pos) =
                    __halves2half2(__float2half_rn(v00 - __half2float(h00)),
                                   __float2half_rn(v01 - __half2float(h01)));
                *(__half2*)(Ch2 + (size_t)(r + 8) * CC + pos) =
                    __halves2half2(__float2half_rn(v10 - __half2float(h10)),
                                   __float2half_rn(v11 - __half2float(h11)));
            } else if (mode == 2) {
                *(__half2*)(Ch + (size_t)r * Nd + c) =
                    __halves2half2(__float2half_rn(v00), __float2half_rn(v01));
                *(__half2*)(Ch + (size_t)(r + 8) * Nd + c) =
                    __halves2half2(__float2half_rn(v10), __float2half_rn(v11));
            } else {  // V transposed
                Ch[(size_t)c * MM + r]           = __float2half_rn(v00);
                Ch[(size_t)(c + 1) * MM + r]     = __float2half_rn(v01);
                Ch[(size_t)c * MM + r + 8]       = __float2half_rn(v10);
                Ch[(size_t)(c + 1) * MM + r + 8] = __float2half_rn(v11);
            }
        }
    }
}

// Fused Q+K+V projection. grid.x = 24: [0,16) Q, [16,20) K, [20,24) V.
__global__ __launch_bounds__(256, 2) void gemm_qkv(
    const float* __restrict__ bq, const float* __restrict__ bk,
    const float* __restrict__ bv)
{
    extern __shared__ char smem[];
    const int bx = blockIdx.x;
    if (bx < 16)
        gemm_h_body(g_Xh, g_Wqt, bq, 1, nullptr, g_Qh, g_Ql, CC,
                    blockIdx.y * 128, bx * 128, smem);
    else if (bx < 20)
        gemm_h_body(g_Xh, g_Wkt, bk, 2, nullptr, g_Kh, nullptr, KVD,
                    blockIdx.y * 128, (bx - 16) * 128, smem);
    else
        gemm_h_body(g_Xh, g_Wvt, bv, 3, nullptr, g_Vt, nullptr, KVD,
                    blockIdx.y * 128, (bx - 20) * 128, smem);
}

__global__ __launch_bounds__(256, 2) void gemm_out(
    const float* __restrict__ bo, float* __restrict__ out)
{
    extern __shared__ char smem[];
    gemm_h_body(g_Oh, g_Wot, bo, 0, out, nullptr, nullptr, CC,
                blockIdx.y * 128, blockIdx.x * 128, smem);
}

// ---------------------------------------------------------------------------
// fp16 flash attention: 128-thr CTAs (64 q-rows), causal, GQA. (unchanged)
// ---------------------------------------------------------------------------
#define KVS_H  72
#define SM_P_H   4096                      // 4 planes * 64 * 16 halves
#define SM_KV_H  (64*KVS_H)                // 4608 halves per K or V tile
#define ATT_SMEM_BYTES ((SM_P_H + 4*SM_KV_H) * 2)   // 45,056
#define SCALE 0.18033688011112042f         // log2(e)/sqrt(64)

__global__ __launch_bounds__(128, 3) void attn_h(
    float* __restrict__ dummy)
{
    extern __shared__ __half smh[];
    __half* Pp = smh;                      // planes: kg*1024 halves

    const int tid  = threadIdx.x;
    const int lane = tid & 31;
    const int warp = tid >> 5;
    const int grp  = lane >> 2;
    const int qid  = lane & 3;
    const int q0   = (gridDim.x - 1 - blockIdx.x) * 64;   // long CTAs first
    const int h    = blockIdx.y;
    const int b    = blockIdx.z;
    const int hkv  = h >> 2;
    const int m0   = warp * 16;
    const int ntile = (q0 >> 6) + 1;

    auto issue_kv = [&](int jt) {
        __half* Kd = smh + SM_P_H + (jt & 1) * 2 * SM_KV_H;
        __half* Vd = Kd + SM_KV_H;
#pragma unroll
        for (int i = 0; i < 4; i++) {
            const int ch = tid + i * 128;        // < 512
            const int tok = ch >> 3, c8 = (ch & 7) * 8;
            cp16(Kd + tok * KVS_H + c8,
                 g_Kh + (size_t)(b * TT + jt * 64 + tok) * KVD + hkv * HD + c8);
        }
#pragma unroll
        for (int i = 0; i < 4; i++) {
            const int ch = tid + i * 128;        // < 512
            const int d = ch >> 3, c8 = (ch & 7) * 8;
            cp16(Vd + d * KVS_H + c8,
                 g_Vt + (size_t)(hkv * HD + d) * MM + b * TT + jt * 64 + c8);
        }
    };

    issue_kv(0);
    CP_COMMIT();

    uint2 qfh[4][2], qfl[4][2];
#pragma unroll
    for (int kg = 0; kg < 4; kg++) {
        const size_t base0 = (size_t)(b * TT + q0 + m0 + grp) * CC + h * HD + kg * 16 + 4 * qid;
        const size_t base1 = base0 + (size_t)8 * CC;
        qfh[kg][0] = *(const uint2*)(g_Qh + base0);
        qfh[kg][1] = *(const uint2*)(g_Qh + base1);
        qfl[kg][0] = *(const uint2*)(g_Ql + base0);
        qfl[kg][1] = *(const uint2*)(g_Ql + base1);
    }

    float m_0 = -1e30f, m_1 = -1e30f, l_0 = 0.f, l_1 = 0.f;
    float o[8][4];
#pragma unroll
    for (int nt = 0; nt < 8; nt++)
#pragma unroll
        for (int e = 0; e < 4; e++) o[nt][e] = 0.f;

    for (int jt = 0; jt < ntile; jt++) {
        if (jt + 1 < ntile) issue_kv(jt + 1);
        CP_COMMIT();
        CP_WAIT1();
        __syncthreads();

        const __half* Ks = smh + SM_P_H + (jt & 1) * 2 * SM_KV_H;
        const __half* Vs = Ks + SM_KV_H;

        float s[8][4];
#pragma unroll
        for (int nt = 0; nt < 8; nt++)
#pragma unroll
            for (int e = 0; e < 4; e++) s[nt][e] = 0.f;

#pragma unroll
        for (int kg = 0; kg < 4; kg++) {
#pragma unroll
            for (int nt = 0; nt < 8; nt++) {
                const int n = nt * 8 + grp;
                uint32_t b0 = *(const uint32_t*)(Ks + n * KVS_H + kg * 16 + 2 * qid);
                uint32_t b1 = *(const uint32_t*)(Ks + n * KVS_H + kg * 16 + 8 + 2 * qid);
                mma_f16(s[nt], qfh[kg][0].x, qfh[kg][1].x, qfh[kg][0].y, qfh[kg][1].y, b0, b1);
                mma_f16(s[nt], qfl[kg][0].x, qfl[kg][1].x, qfl[kg][0].y, qfl[kg][1].y, b0, b1);
            }
        }

#pragma unroll
        for (int nt = 0; nt < 8; nt++)
#pragma unroll
            for (int e = 0; e < 4; e++) s[nt][e] *= SCALE;
        if (jt == ntile - 1) {
            const int k0 = jt * 64;
#pragma unroll
            for (int nt = 0; nt < 8; nt++)
#pragma unroll
                for (int e = 0; e < 4; e++) {
                    const int row = m0 + grp + ((e >> 1) * 8);
                    const int col = nt * 8 + qid * 2 + (e & 1);
                    if (k0 + col > q0 + row) s[nt][e] = -1e30f;
                }
        }

        float mx0 = -1e30f, mx1 = -1e30f;
#pragma unroll
        for (int nt = 0; nt < 8; nt++) {
            mx0 = fmaxf(mx0, fmaxf(s[nt][0], s[nt][1]));
            mx1 = fmaxf(mx1, fmaxf(s[nt][2], s[nt][3]));
        }
        mx0 = fmaxf(mx0, __shfl_xor_sync(0xffffffffu, mx0, 1));
        mx0 = fmaxf(mx0, __shfl_xor_sync(0xffffffffu, mx0, 2));
        mx1 = fmaxf(mx1, __shfl_xor_sync(0xffffffffu, mx1, 1));
        mx1 = fmaxf(mx1, __shfl_xor_sync(0xffffffffu, mx1, 2));

        const float mn0 = fmaxf(m_0, mx0);
        const float mn1 = fmaxf(m_1, mx1);
        const float a0  = fast_exp2(m_0 - mn0);
        const float a1  = fast_exp2(m_1 - mn1);
        m_0 = mn0; m_1 = mn1;

        float ps0 = 0.f, ps1 = 0.f;
#pragma unroll
        for (int ntp = 0; ntp < 4; ntp++) {
            const int ntA = 2 * ntp, ntB = 2 * ntp + 1;
            float pA0 = fast_exp2(s[ntA][0] - mn0);
            float pA1 = fast_exp2(s[ntA][1] - mn0);
            float pB0 = fast_exp2(s[ntB][0] - mn0);
            float pB1 = fast_exp2(s[ntB][1] - mn0);
            ps0 += pA0 + pA1 + pB0 + pB1;
            *(uint2*)(Pp + ntp * 1024 + (m0 + grp) * 16 + 4 * qid) =
                make_uint2(pack2(pA0, pA1), pack2(pB0, pB1));
            float qA0 = fast_exp2(s[ntA][2] - mn1);
            float qA1 = fast_exp2(s[ntA][3] - mn1);
            float qB0 = fast_exp2(s[ntB][2] - mn1);
            float qB1 = fast_exp2(s[ntB][3] - mn1);
            ps1 += qA0 + qA1 + qB0 + qB1;
            *(uint2*)(Pp + ntp * 1024 + (m0 + grp + 8) * 16 + 4 * qid) =
                make_uint2(pack2(qA0, qA1), pack2(qB0, qB1));
        }
        ps0 += __shfl_xor_sync(0xffffffffu, ps0, 1);
        ps0 += __shfl_xor_sync(0xffffffffu, ps0, 2);
        ps1 += __shfl_xor_sync(0xffffffffu, ps1, 1);
        ps1 += __shfl_xor_sync(0xffffffffu, ps1, 2);
        l_0 = l_0 * a0 + ps0;
        l_1 = l_1 * a1 + ps1;
        __syncwarp();

#pragma unroll
        for (int nt = 0; nt < 8; nt++) {
            o[nt][0] *= a0; o[nt][1] *= a0;
            o[nt][2] *= a1; o[nt][3] *= a1;
        }
#pragma unroll
        for (int kg = 0; kg < 4; kg++) {
            uint2 pf0 = *(const uint2*)(Pp + kg * 1024 + (m0 + grp) * 16 + 4 * qid);
            uint2 pf1 = *(const uint2*)(Pp + kg * 1024 + (m0 + grp + 8) * 16 + 4 * qid);
#pragma unroll
            for (int nt = 0; nt < 8; nt++) {
                const int n = nt * 8 + grp;
                uint32_t b0 = *(const uint32_t*)(Vs + n * KVS_H + kg * 16 + 2 * qid);
                uint32_t b1 = *(const uint32_t*)(Vs + n * KVS_H + kg * 16 + 8 + 2 * qid);
                mma_f16(o[nt], pf0.x, pf1.x, pf0.y, pf1.y, b0, b1);
            }
        }
        __syncthreads();
    }

    const float inv0 = 1.f / l_0;
    const float inv1 = 1.f / l_1;
    const int r0 = q0 + m0 + grp;
    const int r1 = r0 + 8;
#pragma unroll
    for (int nt = 0; nt < 8; nt++) {
        const int pos = h * HD + (nt >> 1) * 16 + 4 * qid + 2 * (nt & 1);
        *(__half2*)(g_Oh + (size_t)(b * TT + r0) * CC + pos) =
            __halves2half2(__float2half_rn(o[nt][0] * inv0),
                           __float2half_rn(o[nt][1] * inv0));
        *(__half2*)(g_Oh + (size_t)(b * TT + r1) * CC + pos) =
            __halves2half2(__float2half_rn(o[nt][2] * inv1),
                           __float2half_rn(o[nt][3] * inv1));
    }
    (void)dummy;
}

// ---------------------------------------------------------------------------
extern "C" void kernel_launch(void* const* d_in, const int* in_sizes, int n_in,
                              void* d_out, int out_size)
{
    const float* x  = (const float*)d_in[0];
    // d_in[1] = mask (causal tril) — structural, not read
    const float* Wq = (const float*)d_in[2];
    const float* bq = (const float*)d_in[3];
    const float* Wk = (const float*)d_in[4];
    const float* bk = (const float*)d_in[5];
    const float* Wv = (const float*)d_in[6];
    const float* bv = (const float*)d_in[7];
    const float* Wo = (const float*)d_in[8];
    const float* bo = (const float*)d_in[9];
    float* out = (float*)d_out;

    cudaFuncSetAttribute(attn_h,
                         cudaFuncAttributeMaxDynamicSharedMemorySize, ATT_SMEM_BYTES);
    cudaFuncSetAttribute(gemm_qkv,
                         cudaFuncAttributeMaxDynamicSharedMemorySize, GEMM_SMEM_BYTES);
    cudaFuncSetAttribute(gemm_out,
                         cudaFuncAttributeMaxDynamicSharedMemorySize, GEMM_SMEM_BYTES);

    cvt_x<<<256, 256>>>(x);
    transpose_w<<<dim3(64, 64, 4), 256>>>(Wq, Wk, Wv, Wo);
    gemm_qkv<<<dim3(24, MM / 128), 256, GEMM_SMEM_BYTES>>>(bq, bk, bv);
    attn_h<<<dim3(TT / 64, HQ, BB), 128, ATT_SMEM_BYTES>>>(nullptr);
    gemm_out<<<dim3(CC / 128, MM / 128), 256, GEMM_SMEM_BYTES>>>(bo, out);
}